// round 3
// baseline (speedup 1.0000x reference)
#include <cuda_runtime.h>
#include <cuda_bf16.h>
#include <math.h>

// ---------------------------------------------------------------------------
// Problem constants
// ---------------------------------------------------------------------------
#define BB   256      // batch
#define TT   256      // time
#define LEN  256      // fused feature dim (audio 64 | vision 64 | text 128)
#define RANK 24

// input order: text(0) audio(1) vision(2) Wih_t(3) Whh_t(4) b_t(5)
//              Wih_a(6) Whh_a(7) b_a(8) Wih_v(9) Whh_v(10) b_v(11)
//              W1(12) b1(13) W2(14) b2(15) fw(16)

// ---------------------------------------------------------------------------
// Scratch (static device globals; no allocation allowed)
// ---------------------------------------------------------------------------
__device__ float g_Gt[(size_t)BB * TT * 512];   // text  gate preacts (128 MiB)
__device__ float g_Ga[(size_t)BB * TT * 256];   // audio gate preacts (64 MiB)
__device__ float g_Gv[(size_t)BB * TT * 256];   // vision gate preacts (64 MiB)
__device__ float g_z [(size_t)BB * TT * 256];   // fused hidden states (64 MiB)
__device__ float g_WTt[128 * 512];              // Whh_t transposed [k][n]
__device__ float g_WTa[64 * 256];
__device__ float g_WTv[64 * 256];
__device__ float g_S [BB * RANK];               // per-batch fusion partial sums
__device__ float g_ss[BB];                      // per-batch sum-of-squares

__device__ __forceinline__ float sigf(float x) { return 1.0f / (1.0f + expf(-x)); }

// ---------------------------------------------------------------------------
// Phase 1: C[M,N] = A[M,K] * W[N,K]^T + bias[N]   (input gate projections)
// 128x128 CTA tile, 8x8 microtile, 256 threads
// ---------------------------------------------------------------------------
__global__ __launch_bounds__(256, 2)
void gemm_bias_kernel(const float* __restrict__ A, const float* __restrict__ W,
                      const float* __restrict__ bias, float* __restrict__ C,
                      int M, int N, int K)
{
    __shared__ float As[16][132];
    __shared__ float Bs[16][132];

    const int tid = threadIdx.x;
    const int ty  = tid >> 4;       // 0..15 (row group)
    const int tx  = tid & 15;       // 0..15 (col group)
    const size_t m0 = (size_t)blockIdx.x * 128;
    const size_t n0 = (size_t)blockIdx.y * 128;

    float acc[8][8];
#pragma unroll
    for (int i = 0; i < 8; i++)
#pragma unroll
        for (int j = 0; j < 8; j++) acc[i][j] = 0.0f;

    for (int k0 = 0; k0 < K; k0 += 16) {
#pragma unroll
        for (int i = 0; i < 8; i++) {
            int f  = tid + i * 256;            // 0..2047
            int m  = f >> 4;
            int kk = f & 15;
            int kg = k0 + kk;
            float av = (kg < K) ? A[(m0 + m) * K + kg] : 0.0f;
            float wv = (kg < K) ? W[(n0 + m) * K + kg] : 0.0f;
            As[kk][m] = av;
            Bs[kk][m] = wv;
        }
        __syncthreads();

#pragma unroll
        for (int kk = 0; kk < 16; kk++) {
            float4 a0 = *(const float4*)&As[kk][ty * 8];
            float4 a1 = *(const float4*)&As[kk][ty * 8 + 4];
            float4 b0 = *(const float4*)&Bs[kk][tx * 8];
            float4 b1 = *(const float4*)&Bs[kk][tx * 8 + 4];
            float av[8] = {a0.x, a0.y, a0.z, a0.w, a1.x, a1.y, a1.z, a1.w};
            float bv[8] = {b0.x, b0.y, b0.z, b0.w, b1.x, b1.y, b1.z, b1.w};
#pragma unroll
            for (int i = 0; i < 8; i++)
#pragma unroll
                for (int j = 0; j < 8; j++) acc[i][j] += av[i] * bv[j];
        }
        __syncthreads();
    }

    // epilogue: add bias, vectorized stores
#pragma unroll
    for (int i = 0; i < 8; i++) {
        size_t row = m0 + ty * 8 + i;
        size_t col = n0 + tx * 8;
        float4 o0, o1;
        o0.x = acc[i][0] + bias[col + 0]; o0.y = acc[i][1] + bias[col + 1];
        o0.z = acc[i][2] + bias[col + 2]; o0.w = acc[i][3] + bias[col + 3];
        o1.x = acc[i][4] + bias[col + 4]; o1.y = acc[i][5] + bias[col + 5];
        o1.z = acc[i][6] + bias[col + 6]; o1.w = acc[i][7] + bias[col + 7];
        *(float4*)&C[row * N + col]     = o0;
        *(float4*)&C[row * N + col + 4] = o1;
    }
}

// ---------------------------------------------------------------------------
// Prep: transpose Whh matrices into [k][n] layout
// ---------------------------------------------------------------------------
__global__ void prep_kernel(const float* __restrict__ Wt,
                            const float* __restrict__ Wa,
                            const float* __restrict__ Wv)
{
    int i = blockIdx.x * 256 + threadIdx.x;   // 0..65535
    if (i < 512 * 128) { int n = i / 128, k = i % 128; g_WTt[k * 512 + n] = Wt[i]; }
    if (i < 256 * 64)  { int n = i / 64,  k = i % 64;  g_WTa[k * 256 + n] = Wa[i];
                                                       g_WTv[k * 256 + n] = Wv[i]; }
}

// ---------------------------------------------------------------------------
// Phase 2: LSTM recurrence. One launch, 384 CTAs:
//   bx [0,128):   text   (H=128, 4H=512), 2 batch rows per CTA
//   bx [128,256): audio  (H=64,  4H=256), 2 batch rows per CTA
//   bx [256,384): vision (H=64,  4H=256), 2 batch rows per CTA
// Recurrence is independent per batch row -> no inter-CTA sync needed.
// ---------------------------------------------------------------------------
#define KC 96   // k-panels of Whh_t cached in SMEM (96*512*4 = 192KB); 32 streamed from L2
#define LSTM_SMEM ((KC * 512 + 256 + 512) * 4)   // 199680 B

__global__ __launch_bounds__(256, 1)
void lstm_kernel()
{
    extern __shared__ float sm[];
    const int bx = blockIdx.x;
    const int j  = threadIdx.x;   // 0..255

    if (bx < 128) {
        // ----------------------- text -----------------------
        float*  Wc   = sm;                                   // KC*512
        float2* hbuf = (float2*)(sm + KC * 512);             // 128 x {h[b0],h[b1]}
        float*  exf0 = sm + KC * 512 + 256;                  // sig(f) b0
        float*  exf1 = exf0 + 128;                           // sig(f) b1
        float*  exo0 = exf1 + 128;                           // raw o  b0
        float*  exo1 = exo0 + 128;                           // raw o  b1

        const int b0 = bx * 2, b1 = b0 + 1;

        for (int i = j; i < KC * 512; i += 256) Wc[i] = g_WTt[i];
        if (j < 128) hbuf[j] = make_float2(0.0f, 0.0f);
        __syncthreads();

        float c0 = 0.0f, c1 = 0.0f;
        const float* Wg = g_WTt + KC * 512;   // streamed tail (k = KC..127)

        for (int t = 0; t < TT; t++) {
            const float* Gb0 = g_Gt + ((size_t)(b0 * TT + t)) * 512;
            const float* Gb1 = g_Gt + ((size_t)(b1 * TT + t)) * 512;
            float a00 = Gb0[j], a01 = Gb0[j + 256];
            float a10 = Gb1[j], a11 = Gb1[j + 256];

#pragma unroll 8
            for (int k = 0; k < KC; k++) {
                float2 h2 = hbuf[k];
                float w0 = Wc[k * 512 + j];
                float w1 = Wc[k * 512 + j + 256];
                a00 += w0 * h2.x; a10 += w0 * h2.y;
                a01 += w1 * h2.x; a11 += w1 * h2.y;
            }
#pragma unroll 8
            for (int k = 0; k < 128 - KC; k++) {
                float2 h2 = hbuf[KC + k];
                float w0 = __ldg(&Wg[k * 512 + j]);
                float w1 = __ldg(&Wg[k * 512 + j + 256]);
                a00 += w0 * h2.x; a10 += w0 * h2.y;
                a01 += w1 * h2.x; a11 += w1 * h2.y;
            }

            // gate layout in 4H: [i | f | g | o], each 128.
            // thread j<128 owns i_j (a00/a10) and g_j (a01/a11);
            // thread j>=128 owns f_{j-128} and o_{j-128}.
            if (j >= 128) {
                int jj = j - 128;
                exf0[jj] = sigf(a00); exf1[jj] = sigf(a10);
                exo0[jj] = a01;       exo1[jj] = a11;
            }
            __syncthreads();
            if (j < 128) {
                c0 = exf0[j] * c0 + sigf(a00) * tanhf(a01);
                c1 = exf1[j] * c1 + sigf(a10) * tanhf(a11);
                float h0 = sigf(exo0[j]) * tanhf(c0);
                float h1 = sigf(exo1[j]) * tanhf(c1);
                hbuf[j] = make_float2(h0, h1);
                g_z[((size_t)(b0 * TT + t)) * 256 + 128 + j] = h0;
                g_z[((size_t)(b1 * TT + t)) * 256 + 128 + j] = h1;
            }
            __syncthreads();
        }
    } else {
        // ------------------- audio / vision -------------------
        const bool  is_audio = (bx < 256);
        const int   blk  = is_audio ? (bx - 128) : (bx - 256);
        const float* Gsrc = is_audio ? g_Ga  : g_Gv;
        const float* WTs  = is_audio ? g_WTa : g_WTv;
        const int   zoff = is_audio ? 0 : 64;

        float*  Wc   = sm;                          // 64*256 = 16384 floats
        float2* hbuf = (float2*)(sm + 16384);       // 64
        float*  gb0  = sm + 16384 + 128;            // 256 raw gates b0
        float*  gb1  = gb0 + 256;                   // 256 raw gates b1

        const int b0 = blk * 2, b1 = b0 + 1;

        for (int i = j; i < 64 * 256; i += 256) Wc[i] = WTs[i];
        if (j < 64) hbuf[j] = make_float2(0.0f, 0.0f);
        __syncthreads();

        float c0 = 0.0f, c1 = 0.0f;

        for (int t = 0; t < TT; t++) {
            const float* Gp0 = Gsrc + ((size_t)(b0 * TT + t)) * 256;
            const float* Gp1 = Gsrc + ((size_t)(b1 * TT + t)) * 256;
            float a0 = Gp0[j], a1 = Gp1[j];

#pragma unroll 8
            for (int k = 0; k < 64; k++) {
                float2 h2 = hbuf[k];
                float w = Wc[k * 256 + j];
                a0 += w * h2.x; a1 += w * h2.y;
            }
            gb0[j] = a0; gb1[j] = a1;
            __syncthreads();
            if (j < 64) {
                float i0 = sigf(gb0[j]),      f0 = sigf(gb0[64 + j]);
                float gg0 = tanhf(gb0[128 + j]), o0 = sigf(gb0[192 + j]);
                c0 = f0 * c0 + i0 * gg0;
                float h0 = o0 * tanhf(c0);
                float i1 = sigf(gb1[j]),      f1 = sigf(gb1[64 + j]);
                float gg1 = tanhf(gb1[128 + j]), o1 = sigf(gb1[192 + j]);
                c1 = f1 * c1 + i1 * gg1;
                float h1 = o1 * tanhf(c1);
                hbuf[j] = make_float2(h0, h1);
                g_z[((size_t)(b0 * TT + t)) * 256 + zoff + j] = h0;
                g_z[((size_t)(b1 * TT + t)) * 256 + zoff + j] = h1;
            }
            __syncthreads();
        }
    }
}

// ---------------------------------------------------------------------------
// Phase 3: fusion.  One CTA per batch row b.
//   a_r  = W1[r,:]  . z[b,t]              + b1[r]
//   bb_r = W2[r,0] + W2[r,1:257].z[b,t] + W2[r,257:513].z[b,(t+1)%T] + b2[r]
//   S[b,r] = sum_t a_r * bb_r ;  plus per-b sum of squares of z (for norm)
// warp w owns contiguous t range [w*32, w*32+32), processed in pairs.
// ---------------------------------------------------------------------------
#define FUSION_SMEM ((6144 + 12312 + 24 + 24 + 192 + 8) * 4)   // 74816 B

__global__ __launch_bounds__(256, 1)
void fusion_kernel(const float* __restrict__ W1, const float* __restrict__ b1,
                   const float* __restrict__ W2, const float* __restrict__ b2)
{
    extern __shared__ float sm[];
    float* W1s   = sm;                 // 24*256
    float* W2s   = sm + 6144;          // 24*513
    float* b1s   = W2s + 12312;        // 24
    float* bcs   = b1s + 24;           // 24  (b2[r] + W2[r,0])
    float* Sred  = bcs + 24;           // 8*24
    float* ssred = Sred + 192;         // 8

    const int tid = threadIdx.x;
    const int b   = blockIdx.x;

    for (int i = tid; i < 6144;  i += 256) W1s[i] = W1[i];
    for (int i = tid; i < 12312; i += 256) W2s[i] = W2[i];
    if (tid < 24) b1s[tid] = b1[tid];
    __syncthreads();
    if (tid < 24) bcs[tid] = b2[tid] + W2s[tid * 513];
    __syncthreads();

    const int w = tid >> 5, l = tid & 31;
    float S[RANK];
#pragma unroll
    for (int r = 0; r < RANK; r++) S[r] = 0.0f;
    float ss = 0.0f;

    const float* zb = g_z + (size_t)b * TT * 256;

    for (int t0 = w * 32; t0 < w * 32 + 32; t0 += 2) {
        const int t1 = t0 + 1;
        const int t2 = (t0 + 2) & 255;
        float zc0[8], zc1[8], zc2[8];
#pragma unroll
        for (int q = 0; q < 8; q++) {
            zc0[q] = zb[t0 * 256 + l + 32 * q];
            zc1[q] = zb[t1 * 256 + l + 32 * q];
            zc2[q] = zb[t2 * 256 + l + 32 * q];
            ss += zc0[q] * zc0[q] + zc1[q] * zc1[q];
        }
#pragma unroll
        for (int r = 0; r < RANK; r++) {
            float a0 = 0.0f, bb0 = 0.0f, a1 = 0.0f, bb1 = 0.0f;
#pragma unroll
            for (int q = 0; q < 8; q++) {
                float w1v = W1s[r * 256 + l + 32 * q];
                float w2a = W2s[r * 513 + 1   + l + 32 * q];
                float w2b = W2s[r * 513 + 257 + l + 32 * q];
                a0  += w1v * zc0[q];
                bb0 += w2a * zc0[q] + w2b * zc1[q];
                a1  += w1v * zc1[q];
                bb1 += w2a * zc1[q] + w2b * zc2[q];
            }
#pragma unroll
            for (int o = 16; o; o >>= 1) {
                a0  += __shfl_xor_sync(0xffffffffu, a0,  o);
                bb0 += __shfl_xor_sync(0xffffffffu, bb0, o);
                a1  += __shfl_xor_sync(0xffffffffu, a1,  o);
                bb1 += __shfl_xor_sync(0xffffffffu, bb1, o);
            }
            S[r] += (a0 + b1s[r]) * (bb0 + bcs[r])
                  + (a1 + b1s[r]) * (bb1 + bcs[r]);
        }
    }

#pragma unroll
    for (int o = 16; o; o >>= 1) ss += __shfl_xor_sync(0xffffffffu, ss, o);
    if (l == 0) {
#pragma unroll
        for (int r = 0; r < RANK; r++) Sred[w * RANK + r] = S[r];
        ssred[w] = ss;
    }
    __syncthreads();
    if (tid < RANK) {
        float tot = 0.0f;
        for (int ww = 0; ww < 8; ww++) tot += Sred[ww * RANK + tid];
        g_S[b * RANK + tid] = tot;
    }
    if (tid == 32) {
        float tot = 0.0f;
        for (int ww = 0; ww < 8; ww++) tot += ssred[ww];
        g_ss[b] = tot;
    }
}

// ---------------------------------------------------------------------------
// Phase 4: final reduction.  out[0:256] = output, out[256] = norm.
// ---------------------------------------------------------------------------
__global__ void final_kernel(const float* __restrict__ fw, float* __restrict__ out)
{
    const int tid = threadIdx.x;   // 256 threads
    float s = 0.0f;
#pragma unroll
    for (int r = 0; r < RANK; r++) s += fw[r] * g_S[tid * RANK + r];
    out[tid] = s * (1.0f / (float)TT);   // mean over T

    __shared__ float red[256];
    red[tid] = sqrtf(g_ss[tid]);
    __syncthreads();
    for (int o = 128; o; o >>= 1) {
        if (tid < o) red[tid] += red[tid + o];
        __syncthreads();
    }
    if (tid == 0) out[256] = red[0] / (float)BB;
}

// ---------------------------------------------------------------------------
// Launch
// ---------------------------------------------------------------------------
extern "C" void kernel_launch(void* const* d_in, const int* in_sizes, int n_in,
                              void* d_out, int out_size)
{
    const float* text  = (const float*)d_in[0];
    const float* audio = (const float*)d_in[1];
    const float* vision= (const float*)d_in[2];
    const float* Wih_t = (const float*)d_in[3];
    const float* Whh_t = (const float*)d_in[4];
    const float* b_t   = (const float*)d_in[5];
    const float* Wih_a = (const float*)d_in[6];
    const float* Whh_a = (const float*)d_in[7];
    const float* b_a   = (const float*)d_in[8];
    const float* Wih_v = (const float*)d_in[9];
    const float* Whh_v = (const float*)d_in[10];
    const float* b_v   = (const float*)d_in[11];
    const float* W1    = (const float*)d_in[12];
    const float* b1    = (const float*)d_in[13];
    const float* W2    = (const float*)d_in[14];
    const float* b2    = (const float*)d_in[15];
    const float* fw    = (const float*)d_in[16];

    float *Gt, *Ga, *Gv;
    cudaGetSymbolAddress((void**)&Gt, g_Gt);
    cudaGetSymbolAddress((void**)&Ga, g_Ga);
    cudaGetSymbolAddress((void**)&Gv, g_Gv);

    cudaFuncSetAttribute(lstm_kernel,   cudaFuncAttributeMaxDynamicSharedMemorySize, LSTM_SMEM);
    cudaFuncSetAttribute(fusion_kernel, cudaFuncAttributeMaxDynamicSharedMemorySize, FUSION_SMEM);

    const int M = BB * TT;   // 65536

    // Phase 1: input gate projections
    gemm_bias_kernel<<<dim3(M / 128, 4), 256>>>(text,   Wih_t, b_t, Gt, M, 512, 768);
    gemm_bias_kernel<<<dim3(M / 128, 2), 256>>>(audio,  Wih_a, b_a, Ga, M, 256, 74);
    gemm_bias_kernel<<<dim3(M / 128, 2), 256>>>(vision, Wih_v, b_v, Gv, M, 256, 35);

    // Prep: transpose recurrent weights
    prep_kernel<<<256, 256>>>(Whh_t, Whh_a, Whh_v);

    // Phase 2: recurrence (text CTAs first — they are the long pole)
    lstm_kernel<<<384, 256, LSTM_SMEM>>>();

    // Phase 3: fusion + norm partials
    fusion_kernel<<<BB, 256, FUSION_SMEM>>>(W1, b1, W2, b2);

    // Phase 4: final outputs
    final_kernel<<<1, 256>>>(fw, (float*)d_out);
}

// round 4
// speedup vs baseline: 1.0021x; 1.0021x over previous
#include <cuda_runtime.h>
#include <cuda_bf16.h>
#include <math.h>

// ---------------------------------------------------------------------------
// Problem constants
// ---------------------------------------------------------------------------
#define BB   256      // batch
#define TT   256      // time
#define LEN  256      // fused feature dim (audio 64 | vision 64 | text 128)
#define RANK 24

// input order: text(0) audio(1) vision(2) Wih_t(3) Whh_t(4) b_t(5)
//              Wih_a(6) Whh_a(7) b_a(8) Wih_v(9) Whh_v(10) b_v(11)
//              W1(12) b1(13) W2(14) b2(15) fw(16)

// ---------------------------------------------------------------------------
// Scratch (static device globals; no allocation allowed)
// ---------------------------------------------------------------------------
__device__ float g_Gt[(size_t)BB * TT * 512];   // text  gate preacts (128 MiB)
__device__ float g_Ga[(size_t)BB * TT * 256];   // audio gate preacts (64 MiB)
__device__ float g_Gv[(size_t)BB * TT * 256];   // vision gate preacts (64 MiB)
__device__ float g_z [(size_t)BB * TT * 256];   // fused hidden states (64 MiB)
__device__ float g_WTt[128 * 512];              // Whh_t transposed [k][n]
__device__ float g_WTa[64 * 256];
__device__ float g_WTv[64 * 256];
__device__ float g_S [BB * RANK];               // per-batch fusion partial sums
__device__ float g_ss[BB];                      // per-batch sum-of-squares

__device__ __forceinline__ float sigf(float x) { return 1.0f / (1.0f + expf(-x)); }

// ---------------------------------------------------------------------------
// Phase 1: C[M,N] = A[M,K] * W[N,K]^T + bias[N]   (input gate projections)
// 128x128 CTA tile, 8x8 microtile, 256 threads
// ---------------------------------------------------------------------------
__global__ __launch_bounds__(256, 2)
void gemm_bias_kernel(const float* __restrict__ A, const float* __restrict__ W,
                      const float* __restrict__ bias, float* __restrict__ C,
                      int M, int N, int K)
{
    __shared__ float As[16][132];
    __shared__ float Bs[16][132];

    const int tid = threadIdx.x;
    const int ty  = tid >> 4;       // 0..15 (row group)
    const int tx  = tid & 15;       // 0..15 (col group)
    const size_t m0 = (size_t)blockIdx.x * 128;
    const size_t n0 = (size_t)blockIdx.y * 128;

    float acc[8][8];
#pragma unroll
    for (int i = 0; i < 8; i++)
#pragma unroll
        for (int j = 0; j < 8; j++) acc[i][j] = 0.0f;

    for (int k0 = 0; k0 < K; k0 += 16) {
#pragma unroll
        for (int i = 0; i < 8; i++) {
            int f  = tid + i * 256;            // 0..2047
            int m  = f >> 4;
            int kk = f & 15;
            int kg = k0 + kk;
            float av = (kg < K) ? A[(m0 + m) * K + kg] : 0.0f;
            float wv = (kg < K) ? W[(n0 + m) * K + kg] : 0.0f;
            As[kk][m] = av;
            Bs[kk][m] = wv;
        }
        __syncthreads();

#pragma unroll
        for (int kk = 0; kk < 16; kk++) {
            float4 a0 = *(const float4*)&As[kk][ty * 8];
            float4 a1 = *(const float4*)&As[kk][ty * 8 + 4];
            float4 b0 = *(const float4*)&Bs[kk][tx * 8];
            float4 b1 = *(const float4*)&Bs[kk][tx * 8 + 4];
            float av[8] = {a0.x, a0.y, a0.z, a0.w, a1.x, a1.y, a1.z, a1.w};
            float bv[8] = {b0.x, b0.y, b0.z, b0.w, b1.x, b1.y, b1.z, b1.w};
#pragma unroll
            for (int i = 0; i < 8; i++)
#pragma unroll
                for (int j = 0; j < 8; j++) acc[i][j] += av[i] * bv[j];
        }
        __syncthreads();
    }

    // epilogue: add bias, vectorized stores
#pragma unroll
    for (int i = 0; i < 8; i++) {
        size_t row = m0 + ty * 8 + i;
        size_t col = n0 + tx * 8;
        float4 o0, o1;
        o0.x = acc[i][0] + bias[col + 0]; o0.y = acc[i][1] + bias[col + 1];
        o0.z = acc[i][2] + bias[col + 2]; o0.w = acc[i][3] + bias[col + 3];
        o1.x = acc[i][4] + bias[col + 4]; o1.y = acc[i][5] + bias[col + 5];
        o1.z = acc[i][6] + bias[col + 6]; o1.w = acc[i][7] + bias[col + 7];
        *(float4*)&C[row * N + col]     = o0;
        *(float4*)&C[row * N + col + 4] = o1;
    }
}

// ---------------------------------------------------------------------------
// Prep: transpose Whh matrices into [k][n] layout
// ---------------------------------------------------------------------------
__global__ void prep_kernel(const float* __restrict__ Wt,
                            const float* __restrict__ Wa,
                            const float* __restrict__ Wv)
{
    int i = blockIdx.x * 256 + threadIdx.x;   // 0..65535
    if (i < 512 * 128) { int n = i / 128, k = i % 128; g_WTt[k * 512 + n] = Wt[i]; }
    if (i < 256 * 64)  { int n = i / 64,  k = i % 64;  g_WTa[k * 256 + n] = Wa[i];
                                                       g_WTv[k * 256 + n] = Wv[i]; }
}

// ---------------------------------------------------------------------------
// Phase 2: LSTM recurrence. One launch, 384 CTAs:
//   bx [0,128):   text   (H=128, 4H=512), 2 batch rows per CTA
//   bx [128,256): audio  (H=64,  4H=256), 2 batch rows per CTA
//   bx [256,384): vision (H=64,  4H=256), 2 batch rows per CTA
// Recurrence is independent per batch row -> no inter-CTA sync needed.
// ---------------------------------------------------------------------------
#define KC 96   // k-panels of Whh_t cached in SMEM (96*512*4 = 192KB); 32 streamed from L2
#define LSTM_SMEM ((KC * 512 + 256 + 512) * 4)   // 199680 B

__global__ __launch_bounds__(256, 1)
void lstm_kernel()
{
    extern __shared__ float sm[];
    const int bx = blockIdx.x;
    const int j  = threadIdx.x;   // 0..255

    if (bx < 128) {
        // ----------------------- text -----------------------
        float*  Wc   = sm;                                   // KC*512
        float2* hbuf = (float2*)(sm + KC * 512);             // 128 x {h[b0],h[b1]}
        float*  exf0 = sm + KC * 512 + 256;                  // sig(f) b0
        float*  exf1 = exf0 + 128;                           // sig(f) b1
        float*  exo0 = exf1 + 128;                           // raw o  b0
        float*  exo1 = exo0 + 128;                           // raw o  b1

        const int b0 = bx * 2, b1 = b0 + 1;

        for (int i = j; i < KC * 512; i += 256) Wc[i] = g_WTt[i];
        if (j < 128) hbuf[j] = make_float2(0.0f, 0.0f);
        __syncthreads();

        float c0 = 0.0f, c1 = 0.0f;
        const float* Wg = g_WTt + KC * 512;   // streamed tail (k = KC..127)

        for (int t = 0; t < TT; t++) {
            const float* Gb0 = g_Gt + ((size_t)(b0 * TT + t)) * 512;
            const float* Gb1 = g_Gt + ((size_t)(b1 * TT + t)) * 512;
            float a00 = Gb0[j], a01 = Gb0[j + 256];
            float a10 = Gb1[j], a11 = Gb1[j + 256];

#pragma unroll 8
            for (int k = 0; k < KC; k++) {
                float2 h2 = hbuf[k];
                float w0 = Wc[k * 512 + j];
                float w1 = Wc[k * 512 + j + 256];
                a00 += w0 * h2.x; a10 += w0 * h2.y;
                a01 += w1 * h2.x; a11 += w1 * h2.y;
            }
#pragma unroll 8
            for (int k = 0; k < 128 - KC; k++) {
                float2 h2 = hbuf[KC + k];
                float w0 = __ldg(&Wg[k * 512 + j]);
                float w1 = __ldg(&Wg[k * 512 + j + 256]);
                a00 += w0 * h2.x; a10 += w0 * h2.y;
                a01 += w1 * h2.x; a11 += w1 * h2.y;
            }

            // gate layout in 4H: [i | f | g | o], each 128.
            // thread j<128 owns i_j (a00/a10) and g_j (a01/a11);
            // thread j>=128 owns f_{j-128} and o_{j-128}.
            if (j >= 128) {
                int jj = j - 128;
                exf0[jj] = sigf(a00); exf1[jj] = sigf(a10);
                exo0[jj] = a01;       exo1[jj] = a11;
            }
            __syncthreads();
            if (j < 128) {
                c0 = exf0[j] * c0 + sigf(a00) * tanhf(a01);
                c1 = exf1[j] * c1 + sigf(a10) * tanhf(a11);
                float h0 = sigf(exo0[j]) * tanhf(c0);
                float h1 = sigf(exo1[j]) * tanhf(c1);
                hbuf[j] = make_float2(h0, h1);
                g_z[((size_t)(b0 * TT + t)) * 256 + 128 + j] = h0;
                g_z[((size_t)(b1 * TT + t)) * 256 + 128 + j] = h1;
            }
            __syncthreads();
        }
    } else {
        // ------------------- audio / vision -------------------
        const bool  is_audio = (bx < 256);
        const int   blk  = is_audio ? (bx - 128) : (bx - 256);
        const float* Gsrc = is_audio ? g_Ga  : g_Gv;
        const float* WTs  = is_audio ? g_WTa : g_WTv;
        const int   zoff = is_audio ? 0 : 64;

        float*  Wc   = sm;                          // 64*256 = 16384 floats
        float2* hbuf = (float2*)(sm + 16384);       // 64
        float*  gb0  = sm + 16384 + 128;            // 256 raw gates b0
        float*  gb1  = gb0 + 256;                   // 256 raw gates b1

        const int b0 = blk * 2, b1 = b0 + 1;

        for (int i = j; i < 64 * 256; i += 256) Wc[i] = WTs[i];
        if (j < 64) hbuf[j] = make_float2(0.0f, 0.0f);
        __syncthreads();

        float c0 = 0.0f, c1 = 0.0f;

        for (int t = 0; t < TT; t++) {
            const float* Gp0 = Gsrc + ((size_t)(b0 * TT + t)) * 256;
            const float* Gp1 = Gsrc + ((size_t)(b1 * TT + t)) * 256;
            float a0 = Gp0[j], a1 = Gp1[j];

#pragma unroll 8
            for (int k = 0; k < 64; k++) {
                float2 h2 = hbuf[k];
                float w = Wc[k * 256 + j];
                a0 += w * h2.x; a1 += w * h2.y;
            }
            gb0[j] = a0; gb1[j] = a1;
            __syncthreads();
            if (j < 64) {
                float i0 = sigf(gb0[j]),      f0 = sigf(gb0[64 + j]);
                float gg0 = tanhf(gb0[128 + j]), o0 = sigf(gb0[192 + j]);
                c0 = f0 * c0 + i0 * gg0;
                float h0 = o0 * tanhf(c0);
                float i1 = sigf(gb1[j]),      f1 = sigf(gb1[64 + j]);
                float gg1 = tanhf(gb1[128 + j]), o1 = sigf(gb1[192 + j]);
                c1 = f1 * c1 + i1 * gg1;
                float h1 = o1 * tanhf(c1);
                hbuf[j] = make_float2(h0, h1);
                g_z[((size_t)(b0 * TT + t)) * 256 + zoff + j] = h0;
                g_z[((size_t)(b1 * TT + t)) * 256 + zoff + j] = h1;
            }
            __syncthreads();
        }
    }
}

// ---------------------------------------------------------------------------
// Phase 3: fusion.  One CTA per batch row b.
//   a_r  = W1[r,:]  . z[b,t]              + b1[r]
//   bb_r = W2[r,0] + W2[r,1:257].z[b,t] + W2[r,257:513].z[b,(t+1)%T] + b2[r]
//   S[b,r] = sum_t a_r * bb_r ;  plus per-b sum of squares of z (for norm)
// warp w owns contiguous t range [w*32, w*32+32), processed in pairs.
// ---------------------------------------------------------------------------
#define FUSION_SMEM ((6144 + 12312 + 24 + 24 + 192 + 8) * 4)   // 74816 B

__global__ __launch_bounds__(256, 1)
void fusion_kernel(const float* __restrict__ W1, const float* __restrict__ b1,
                   const float* __restrict__ W2, const float* __restrict__ b2)
{
    extern __shared__ float sm[];
    float* W1s   = sm;                 // 24*256
    float* W2s   = sm + 6144;          // 24*513
    float* b1s   = W2s + 12312;        // 24
    float* bcs   = b1s + 24;           // 24  (b2[r] + W2[r,0])
    float* Sred  = bcs + 24;           // 8*24
    float* ssred = Sred + 192;         // 8

    const int tid = threadIdx.x;
    const int b   = blockIdx.x;

    for (int i = tid; i < 6144;  i += 256) W1s[i] = W1[i];
    for (int i = tid; i < 12312; i += 256) W2s[i] = W2[i];
    if (tid < 24) b1s[tid] = b1[tid];
    __syncthreads();
    if (tid < 24) bcs[tid] = b2[tid] + W2s[tid * 513];
    __syncthreads();

    const int w = tid >> 5, l = tid & 31;
    float S[RANK];
#pragma unroll
    for (int r = 0; r < RANK; r++) S[r] = 0.0f;
    float ss = 0.0f;

    const float* zb = g_z + (size_t)b * TT * 256;

    for (int t0 = w * 32; t0 < w * 32 + 32; t0 += 2) {
        const int t1 = t0 + 1;
        const int t2 = (t0 + 2) & 255;
        float zc0[8], zc1[8], zc2[8];
#pragma unroll
        for (int q = 0; q < 8; q++) {
            zc0[q] = zb[t0 * 256 + l + 32 * q];
            zc1[q] = zb[t1 * 256 + l + 32 * q];
            zc2[q] = zb[t2 * 256 + l + 32 * q];
            ss += zc0[q] * zc0[q] + zc1[q] * zc1[q];
        }
#pragma unroll
        for (int r = 0; r < RANK; r++) {
            float a0 = 0.0f, bb0 = 0.0f, a1 = 0.0f, bb1 = 0.0f;
#pragma unroll
            for (int q = 0; q < 8; q++) {
                float w1v = W1s[r * 256 + l + 32 * q];
                float w2a = W2s[r * 513 + 1   + l + 32 * q];
                float w2b = W2s[r * 513 + 257 + l + 32 * q];
                a0  += w1v * zc0[q];
                bb0 += w2a * zc0[q] + w2b * zc1[q];
                a1  += w1v * zc1[q];
                bb1 += w2a * zc1[q] + w2b * zc2[q];
            }
#pragma unroll
            for (int o = 16; o; o >>= 1) {
                a0  += __shfl_xor_sync(0xffffffffu, a0,  o);
                bb0 += __shfl_xor_sync(0xffffffffu, bb0, o);
                a1  += __shfl_xor_sync(0xffffffffu, a1,  o);
                bb1 += __shfl_xor_sync(0xffffffffu, bb1, o);
            }
            S[r] += (a0 + b1s[r]) * (bb0 + bcs[r])
                  + (a1 + b1s[r]) * (bb1 + bcs[r]);
        }
    }

#pragma unroll
    for (int o = 16; o; o >>= 1) ss += __shfl_xor_sync(0xffffffffu, ss, o);
    if (l == 0) {
#pragma unroll
        for (int r = 0; r < RANK; r++) Sred[w * RANK + r] = S[r];
        ssred[w] = ss;
    }
    __syncthreads();
    if (tid < RANK) {
        float tot = 0.0f;
        for (int ww = 0; ww < 8; ww++) tot += Sred[ww * RANK + tid];
        g_S[b * RANK + tid] = tot;
    }
    if (tid == 32) {
        float tot = 0.0f;
        for (int ww = 0; ww < 8; ww++) tot += ssred[ww];
        g_ss[b] = tot;
    }
}

// ---------------------------------------------------------------------------
// Phase 4: final reduction.  out[0:256] = output, out[256] = norm.
// ---------------------------------------------------------------------------
__global__ void final_kernel(const float* __restrict__ fw, float* __restrict__ out)
{
    const int tid = threadIdx.x;   // 256 threads
    float s = 0.0f;
#pragma unroll
    for (int r = 0; r < RANK; r++) s += fw[r] * g_S[tid * RANK + r];
    out[tid] = s * (1.0f / (float)TT);   // mean over T

    __shared__ float red[256];
    red[tid] = sqrtf(g_ss[tid]);
    __syncthreads();
    for (int o = 128; o; o >>= 1) {
        if (tid < o) red[tid] += red[tid + o];
        __syncthreads();
    }
    if (tid == 0) out[256] = red[0] / (float)BB;
}

// ---------------------------------------------------------------------------
// Launch
// ---------------------------------------------------------------------------
extern "C" void kernel_launch(void* const* d_in, const int* in_sizes, int n_in,
                              void* d_out, int out_size)
{
    const float* text  = (const float*)d_in[0];
    const float* audio = (const float*)d_in[1];
    const float* vision= (const float*)d_in[2];
    const float* Wih_t = (const float*)d_in[3];
    const float* Whh_t = (const float*)d_in[4];
    const float* b_t   = (const float*)d_in[5];
    const float* Wih_a = (const float*)d_in[6];
    const float* Whh_a = (const float*)d_in[7];
    const float* b_a   = (const float*)d_in[8];
    const float* Wih_v = (const float*)d_in[9];
    const float* Whh_v = (const float*)d_in[10];
    const float* b_v   = (const float*)d_in[11];
    const float* W1    = (const float*)d_in[12];
    const float* b1    = (const float*)d_in[13];
    const float* W2    = (const float*)d_in[14];
    const float* b2    = (const float*)d_in[15];
    const float* fw    = (const float*)d_in[16];

    float *Gt, *Ga, *Gv;
    cudaGetSymbolAddress((void**)&Gt, g_Gt);
    cudaGetSymbolAddress((void**)&Ga, g_Ga);
    cudaGetSymbolAddress((void**)&Gv, g_Gv);

    cudaFuncSetAttribute(lstm_kernel,   cudaFuncAttributeMaxDynamicSharedMemorySize, LSTM_SMEM);
    cudaFuncSetAttribute(fusion_kernel, cudaFuncAttributeMaxDynamicSharedMemorySize, FUSION_SMEM);

    const int M = BB * TT;   // 65536

    // Phase 1: input gate projections
    gemm_bias_kernel<<<dim3(M / 128, 4), 256>>>(text,   Wih_t, b_t, Gt, M, 512, 768);
    gemm_bias_kernel<<<dim3(M / 128, 2), 256>>>(audio,  Wih_a, b_a, Ga, M, 256, 74);
    gemm_bias_kernel<<<dim3(M / 128, 2), 256>>>(vision, Wih_v, b_v, Gv, M, 256, 35);

    // Prep: transpose recurrent weights
    prep_kernel<<<256, 256>>>(Whh_t, Whh_a, Whh_v);

    // Phase 2: recurrence (text CTAs first — they are the long pole)
    lstm_kernel<<<384, 256, LSTM_SMEM>>>();

    // Phase 3: fusion + norm partials
    fusion_kernel<<<BB, 256, FUSION_SMEM>>>(W1, b1, W2, b2);

    // Phase 4: final outputs
    final_kernel<<<1, 256>>>(fw, (float*)d_out);
}

// round 6
// speedup vs baseline: 1.5444x; 1.5411x over previous
#include <cuda_runtime.h>
#include <cuda_bf16.h>
#include <math.h>
#include <stdint.h>

#define BB   256
#define TT   256
#define RANK 24
#define MM   (BB * TT)

#define KP_T 768
#define KP_A 80
#define KP_V 48

// ---------------- scratch globals ----------------
__device__ float g_Gt[(size_t)MM * 512];
__device__ float g_Ga[(size_t)MM * 256];
__device__ float g_Gv[(size_t)MM * 256];
__device__ float g_z [(size_t)MM * 256];

__device__ __nv_bfloat16 g_Athi[(size_t)MM * KP_T];
__device__ __nv_bfloat16 g_Atlo[(size_t)MM * KP_T];
__device__ __nv_bfloat16 g_Aahi[(size_t)MM * KP_A];
__device__ __nv_bfloat16 g_Aalo[(size_t)MM * KP_A];
__device__ __nv_bfloat16 g_Avhi[(size_t)MM * KP_V];
__device__ __nv_bfloat16 g_Avlo[(size_t)MM * KP_V];
__device__ __nv_bfloat16 g_Wthi[512 * KP_T];
__device__ __nv_bfloat16 g_Wtlo[512 * KP_T];
__device__ __nv_bfloat16 g_Wahi[256 * KP_A];
__device__ __nv_bfloat16 g_Walo[256 * KP_A];
__device__ __nv_bfloat16 g_Wvhi[256 * KP_V];
__device__ __nv_bfloat16 g_Wvlo[256 * KP_V];

__device__ float g_WIt[128 * 512];   // Whh_t interleaved [k][2j+s]
__device__ float g_WTa[64 * 256];
__device__ float g_WTv[64 * 256];
__device__ float g_S [BB * RANK];
__device__ float g_ss[BB];

__device__ __forceinline__ float sigf(float x)  { return 1.0f / (1.0f + __expf(-x)); }
__device__ __forceinline__ float tanhfa(float x){ return 1.0f - 2.0f / (__expf(2.0f * x) + 1.0f); }

// ---------------- fp32 -> (hi,lo) bf16 split ----------------
__global__ void conv_split4(const float4* __restrict__ src,
                            __nv_bfloat162* __restrict__ hi,
                            __nv_bfloat162* __restrict__ lo, long n4)
{
    for (long i = (long)blockIdx.x * blockDim.x + threadIdx.x; i < n4;
         i += (long)gridDim.x * blockDim.x) {
        float4 v = src[i];
        __nv_bfloat16 h0 = __float2bfloat16(v.x), h1 = __float2bfloat16(v.y);
        __nv_bfloat16 h2 = __float2bfloat16(v.z), h3 = __float2bfloat16(v.w);
        hi[2*i]   = __halves2bfloat162(h0, h1);
        hi[2*i+1] = __halves2bfloat162(h2, h3);
        lo[2*i]   = __halves2bfloat162(__float2bfloat16(v.x - __bfloat162float(h0)),
                                       __float2bfloat16(v.y - __bfloat162float(h1)));
        lo[2*i+1] = __halves2bfloat162(__float2bfloat16(v.z - __bfloat162float(h2)),
                                       __float2bfloat16(v.w - __bfloat162float(h3)));
    }
}

__global__ void conv_pad(const float* __restrict__ src,
                         __nv_bfloat16* __restrict__ hi,
                         __nv_bfloat16* __restrict__ lo,
                         int rows, int K, int Kp)
{
    long total = (long)rows * Kp;
    for (long i = (long)blockIdx.x * blockDim.x + threadIdx.x; i < total;
         i += (long)gridDim.x * blockDim.x) {
        int m = (int)(i / Kp), k = (int)(i % Kp);
        float v = (k < K) ? src[(size_t)m * K + k] : 0.0f;
        __nv_bfloat16 h = __float2bfloat16(v);
        hi[i] = h;
        lo[i] = __float2bfloat16(v - __bfloat162float(h));
    }
}

// ---------------- tensor-core GEMM: C = A * W^T + bias ----------------
// split bf16, 3 passes. CTA tile 128x128, 8 warps (4x2), warp tile 32x64.
// smem per array: 128 rows * 48B (32B data + 16B pad -> conflict-free).
#define GARR 6144
#define GSTG 24576

__device__ __forceinline__ void cp16(unsigned int dst, const void* src) {
    asm volatile("cp.async.cg.shared.global [%0], [%1], 16;\n" :: "r"(dst), "l"(src));
}
__device__ __forceinline__ unsigned int ld4(const char* base, int r, int e) {
    return *(const unsigned int*)(base + r * 48 + e * 2);
}
__device__ __forceinline__ void mma16816(float* d, const unsigned int* a, const unsigned int* b) {
    asm volatile(
        "mma.sync.aligned.m16n8k16.row.col.f32.bf16.bf16.f32 "
        "{%0,%1,%2,%3}, {%4,%5,%6,%7}, {%8,%9}, {%0,%1,%2,%3};"
        : "+f"(d[0]), "+f"(d[1]), "+f"(d[2]), "+f"(d[3])
        : "r"(a[0]), "r"(a[1]), "r"(a[2]), "r"(a[3]), "r"(b[0]), "r"(b[1]));
}

__global__ __launch_bounds__(256, 1)
void gemm_bf16s(const __nv_bfloat16* __restrict__ Ahi, const __nv_bfloat16* __restrict__ Alo,
                const __nv_bfloat16* __restrict__ Bhi, const __nv_bfloat16* __restrict__ Blo,
                const float* __restrict__ bias, float* __restrict__ C, int N, int Kp)
{
    extern __shared__ char gsm[];
    const int tid = threadIdx.x;
    const size_t m0 = (size_t)blockIdx.x * 128;
    const size_t n0 = (size_t)blockIdx.y * 128;
    const int rr = tid >> 1, cc = tid & 1;
    const unsigned int us = (unsigned int)__cvta_generic_to_shared(gsm);
    const int NK = Kp >> 4;

    const __nv_bfloat16* gp[4] = {Ahi + (m0 + rr) * Kp + cc * 8,
                                  Alo + (m0 + rr) * Kp + cc * 8,
                                  Bhi + (n0 + rr) * Kp + cc * 8,
                                  Blo + (n0 + rr) * Kp + cc * 8};
    const unsigned int dbase = us + rr * 48 + cc * 16;

    const int warp = tid >> 5, wm = warp >> 1, wn = warp & 1;
    const int lane = tid & 31, grp = lane >> 2, q = lane & 3;

    float acc[2][8][4];
#pragma unroll
    for (int mt = 0; mt < 2; mt++)
#pragma unroll
        for (int nt = 0; nt < 8; nt++)
#pragma unroll
            for (int i = 0; i < 4; i++) acc[mt][nt][i] = 0.0f;

#pragma unroll
    for (int arr = 0; arr < 4; arr++) cp16(dbase + arr * GARR, gp[arr]);
    asm volatile("cp.async.commit_group;\n" ::: "memory");

    for (int kc = 0; kc < NK; kc++) {
        if (kc + 1 < NK) {
#pragma unroll
            for (int arr = 0; arr < 4; arr++)
                cp16(dbase + ((kc + 1) & 1) * GSTG + arr * GARR, gp[arr] + (kc + 1) * 16);
        }
        asm volatile("cp.async.commit_group;\n" ::: "memory");
        asm volatile("cp.async.wait_group 1;\n" ::: "memory");
        __syncthreads();

        const char* st  = gsm + (kc & 1) * GSTG;
        const char* sAh = st;
        const char* sAl = st + GARR;
        const char* sBh = st + 2 * GARR;
        const char* sBl = st + 3 * GARR;

        unsigned int bh[8][2], af[2][4], al[2][4];
#pragma unroll
        for (int nt = 0; nt < 8; nt++) {
            int nr = wn * 64 + nt * 8 + grp;
            bh[nt][0] = ld4(sBh, nr, 2 * q);
            bh[nt][1] = ld4(sBh, nr, 2 * q + 8);
        }
#pragma unroll
        for (int mt = 0; mt < 2; mt++) {
            int r = wm * 32 + mt * 16 + grp;
            af[mt][0] = ld4(sAh, r,     2 * q);
            af[mt][1] = ld4(sAh, r + 8, 2 * q);
            af[mt][2] = ld4(sAh, r,     2 * q + 8);
            af[mt][3] = ld4(sAh, r + 8, 2 * q + 8);
            al[mt][0] = ld4(sAl, r,     2 * q);
            al[mt][1] = ld4(sAl, r + 8, 2 * q);
            al[mt][2] = ld4(sAl, r,     2 * q + 8);
            al[mt][3] = ld4(sAl, r + 8, 2 * q + 8);
        }
#pragma unroll
        for (int mt = 0; mt < 2; mt++)
#pragma unroll
            for (int nt = 0; nt < 8; nt++) {
                mma16816(acc[mt][nt], af[mt], bh[nt]);
                mma16816(acc[mt][nt], al[mt], bh[nt]);
            }
#pragma unroll
        for (int nt = 0; nt < 8; nt++) {
            int nr = wn * 64 + nt * 8 + grp;
            bh[nt][0] = ld4(sBl, nr, 2 * q);
            bh[nt][1] = ld4(sBl, nr, 2 * q + 8);
        }
#pragma unroll
        for (int mt = 0; mt < 2; mt++)
#pragma unroll
            for (int nt = 0; nt < 8; nt++)
                mma16816(acc[mt][nt], af[mt], bh[nt]);
        __syncthreads();
    }

#pragma unroll
    for (int mt = 0; mt < 2; mt++) {
        size_t r = m0 + wm * 32 + mt * 16 + grp;
#pragma unroll
        for (int nt = 0; nt < 8; nt++) {
            size_t cb = n0 + wn * 64 + nt * 8 + 2 * q;
            float b0v = bias[cb], b1v = bias[cb + 1];
            *(float2*)&C[r * N + cb]       = make_float2(acc[mt][nt][0] + b0v, acc[mt][nt][1] + b1v);
            *(float2*)&C[(r + 8) * N + cb] = make_float2(acc[mt][nt][2] + b0v, acc[mt][nt][3] + b1v);
        }
    }
}

// ---------------- prep recurrent weights ----------------
__global__ void prep_kernel(const float* __restrict__ Wt,
                            const float* __restrict__ Wa,
                            const float* __restrict__ Wv)
{
    int i = blockIdx.x * 256 + threadIdx.x;
    if (i < 512 * 128) {
        int n = i / 128, k = i % 128;
        int j = (n < 256) ? n : (n - 256);
        int s = (n < 256) ? 0 : 1;
        g_WIt[k * 512 + 2 * j + s] = Wt[i];
    }
    if (i < 256 * 64) {
        int n = i / 64, k = i % 64;
        g_WTa[k * 256 + n] = Wa[i];
        g_WTv[k * 256 + n] = Wv[i];
    }
}

// ---------------- LSTM text: 128 CTAs, 2 batch rows each ----------------
#define KCT 96
#define TEXT_SMEM ((KCT * 512 + 256 + 512) * 4)

__global__ __launch_bounds__(256, 1)
void lstm_text_kernel()
{
    extern __shared__ float sm[];
    float2* Wc2  = (float2*)sm;                  // KCT*256 float2
    float2* hbuf = (float2*)(sm + KCT * 512);    // 128
    float*  exf0 = sm + KCT * 512 + 256;
    float*  exf1 = exf0 + 128;
    float*  exo0 = exf1 + 128;
    float*  exo1 = exo0 + 128;

    const int bx = blockIdx.x, j = threadIdx.x;
    const int b0 = bx * 2, b1 = b0 + 1;
    const float2* WI2 = (const float2*)g_WIt;

    for (int i = j; i < KCT * 256; i += 256) Wc2[i] = WI2[i];
    float2 wt[32];
#pragma unroll
    for (int kk = 0; kk < 32; kk++) wt[kk] = WI2[(KCT + kk) * 256 + j];
    if (j < 128) hbuf[j] = make_float2(0.0f, 0.0f);
    __syncthreads();

    float c0 = 0.0f, c1 = 0.0f;

    for (int t = 0; t < TT; t++) {
        const float* Gb0 = g_Gt + ((size_t)(b0 * TT + t)) * 512;
        const float* Gb1 = g_Gt + ((size_t)(b1 * TT + t)) * 512;
        float a00 = Gb0[j], a01 = Gb0[j + 256];
        float a10 = Gb1[j], a11 = Gb1[j + 256];

#pragma unroll 8
        for (int k = 0; k < KCT; k++) {
            float2 w2 = Wc2[k * 256 + j];
            float2 h2 = hbuf[k];
            a00 += w2.x * h2.x; a10 += w2.x * h2.y;
            a01 += w2.y * h2.x; a11 += w2.y * h2.y;
        }
#pragma unroll
        for (int kk = 0; kk < 32; kk++) {
            float2 h2 = hbuf[KCT + kk];
            a00 += wt[kk].x * h2.x; a10 += wt[kk].x * h2.y;
            a01 += wt[kk].y * h2.x; a11 += wt[kk].y * h2.y;
        }

        if (j >= 128) {
            int jj = j - 128;
            exf0[jj] = sigf(a00); exf1[jj] = sigf(a10);
            exo0[jj] = a01;       exo1[jj] = a11;
        }
        __syncthreads();
        if (j < 128) {
            c0 = exf0[j] * c0 + sigf(a00) * tanhfa(a01);
            c1 = exf1[j] * c1 + sigf(a10) * tanhfa(a11);
            float h0 = sigf(exo0[j]) * tanhfa(c0);
            float h1 = sigf(exo1[j]) * tanhfa(c1);
            hbuf[j] = make_float2(h0, h1);
            g_z[((size_t)(b0 * TT + t)) * 256 + 128 + j] = h0;
            g_z[((size_t)(b1 * TT + t)) * 256 + 128 + j] = h1;
        }
        __syncthreads();
    }
}

// ---------------- LSTM audio+vision: 128 CTAs, 4 batch rows each ----------------
#define AV_SMEM ((64 * 256 + 256 + 1024) * 4)

__global__ __launch_bounds__(256, 1)
void lstm_av_kernel()
{
    extern __shared__ float sm[];
    float*  Wc    = sm;                        // 64*256
    float4* hbuf4 = (float4*)(sm + 16384);     // 64
    float*  hbufF = sm + 16384;
    float*  gb    = sm + 16384 + 256;          // 4*256

    const int bx = blockIdx.x, j = threadIdx.x;
    const bool is_audio = (bx < 64);
    const int blk = is_audio ? bx : (bx - 64);
    const float* Gsrc = is_audio ? g_Ga : g_Gv;
    const float* WTs  = is_audio ? g_WTa : g_WTv;
    const int zoff = is_audio ? 0 : 64;
    const int b0 = blk * 4;

    for (int i = j; i < 64 * 256; i += 256) Wc[i] = WTs[i];
    if (j < 64) hbuf4[j] = make_float4(0.0f, 0.0f, 0.0f, 0.0f);
    __syncthreads();

    const int row = j >> 6, hj = j & 63;
    float c = 0.0f;

    for (int t = 0; t < TT; t++) {
        float a0 = Gsrc[((size_t)((b0 + 0) * TT + t)) * 256 + j];
        float a1 = Gsrc[((size_t)((b0 + 1) * TT + t)) * 256 + j];
        float a2 = Gsrc[((size_t)((b0 + 2) * TT + t)) * 256 + j];
        float a3 = Gsrc[((size_t)((b0 + 3) * TT + t)) * 256 + j];

#pragma unroll 8
        for (int k = 0; k < 64; k++) {
            float w = Wc[k * 256 + j];
            float4 h4 = hbuf4[k];
            a0 += w * h4.x; a1 += w * h4.y; a2 += w * h4.z; a3 += w * h4.w;
        }
        gb[0 * 256 + j] = a0; gb[1 * 256 + j] = a1;
        gb[2 * 256 + j] = a2; gb[3 * 256 + j] = a3;
        __syncthreads();

        const float* g = gb + row * 256;
        float gi = sigf(g[hj]),         gf = sigf(g[64 + hj]);
        float gg = tanhfa(g[128 + hj]), go = sigf(g[192 + hj]);
        c = gf * c + gi * gg;
        float h = go * tanhfa(c);
        hbufF[hj * 4 + row] = h;
        g_z[((size_t)((b0 + row) * TT + t)) * 256 + zoff + hj] = h;
        __syncthreads();
    }
}

// ---------------- fusion ----------------
#define FUSION_SMEM ((6144 + 12312 + 24 + 24 + 192 + 8) * 4)

__global__ __launch_bounds__(256, 1)
void fusion_kernel(const float* __restrict__ W1, const float* __restrict__ b1,
                   const float* __restrict__ W2, const float* __restrict__ b2)
{
    extern __shared__ float sm[];
    float* W1s   = sm;
    float* W2s   = sm + 6144;
    float* b1s   = W2s + 12312;
    float* bcs   = b1s + 24;
    float* Sred  = bcs + 24;
    float* ssred = Sred + 192;

    const int tid = threadIdx.x;
    const int b   = blockIdx.x;

    for (int i = tid; i < 6144;  i += 256) W1s[i] = W1[i];
    for (int i = tid; i < 12312; i += 256) W2s[i] = W2[i];
    if (tid < 24) b1s[tid] = b1[tid];
    __syncthreads();
    if (tid < 24) bcs[tid] = b2[tid] + W2s[tid * 513];
    __syncthreads();

    const int w = tid >> 5, l = tid & 31;
    float S[RANK];
#pragma unroll
    for (int r = 0; r < RANK; r++) S[r] = 0.0f;
    float ss = 0.0f;

    const float* zb = g_z + (size_t)b * TT * 256;

    for (int t0 = w * 32; t0 < w * 32 + 32; t0 += 2) {
        const int t1 = t0 + 1;
        const int t2 = (t0 + 2) & 255;
        float zc0[8], zc1[8], zc2[8];
#pragma unroll
        for (int q = 0; q < 8; q++) {
            zc0[q] = zb[t0 * 256 + l + 32 * q];
            zc1[q] = zb[t1 * 256 + l + 32 * q];
            zc2[q] = zb[t2 * 256 + l + 32 * q];
            ss += zc0[q] * zc0[q] + zc1[q] * zc1[q];
        }
#pragma unroll
        for (int r = 0; r < RANK; r++) {
            float a0 = 0.0f, bb0 = 0.0f, a1 = 0.0f, bb1 = 0.0f;
#pragma unroll
            for (int q = 0; q < 8; q++) {
                float w1v = W1s[r * 256 + l + 32 * q];
                float w2a = W2s[r * 513 + 1   + l + 32 * q];
                float w2b = W2s[r * 513 + 257 + l + 32 * q];
                a0  += w1v * zc0[q];
                bb0 += w2a * zc0[q] + w2b * zc1[q];
                a1  += w1v * zc1[q];
                bb1 += w2a * zc1[q] + w2b * zc2[q];
            }
#pragma unroll
            for (int o = 16; o; o >>= 1) {
                a0  += __shfl_xor_sync(0xffffffffu, a0,  o);
                bb0 += __shfl_xor_sync(0xffffffffu, bb0, o);
                a1  += __shfl_xor_sync(0xffffffffu, a1,  o);
                bb1 += __shfl_xor_sync(0xffffffffu, bb1, o);
            }
            S[r] += (a0 + b1s[r]) * (bb0 + bcs[r])
                  + (a1 + b1s[r]) * (bb1 + bcs[r]);
        }
    }

#pragma unroll
    for (int o = 16; o; o >>= 1) ss += __shfl_xor_sync(0xffffffffu, ss, o);
    if (l == 0) {
#pragma unroll
        for (int r = 0; r < RANK; r++) Sred[w * RANK + r] = S[r];
        ssred[w] = ss;
    }
    __syncthreads();
    if (tid < RANK) {
        float tot = 0.0f;
        for (int ww = 0; ww < 8; ww++) tot += Sred[ww * RANK + tid];
        g_S[b * RANK + tid] = tot;
    }
    if (tid == 32) {
        float tot = 0.0f;
        for (int ww = 0; ww < 8; ww++) tot += ssred[ww];
        g_ss[b] = tot;
    }
}

// ---------------- final ----------------
__global__ void final_kernel(const float* __restrict__ fw, float* __restrict__ out)
{
    const int tid = threadIdx.x;
    float s = 0.0f;
#pragma unroll
    for (int r = 0; r < RANK; r++) s += fw[r] * g_S[tid * RANK + r];
    out[tid] = s * (1.0f / (float)TT);

    __shared__ float red[256];
    red[tid] = sqrtf(g_ss[tid]);
    __syncthreads();
    for (int o = 128; o; o >>= 1) {
        if (tid < o) red[tid] += red[tid + o];
        __syncthreads();
    }
    if (tid == 0) out[256] = red[0] / (float)BB;
}

// ---------------- launch ----------------
extern "C" void kernel_launch(void* const* d_in, const int* in_sizes, int n_in,
                              void* d_out, int out_size)
{
    const float* text  = (const float*)d_in[0];
    const float* audio = (const float*)d_in[1];
    const float* vision= (const float*)d_in[2];
    const float* Wih_t = (const float*)d_in[3];
    const float* Whh_t = (const float*)d_in[4];
    const float* b_t   = (const float*)d_in[5];
    const float* Wih_a = (const float*)d_in[6];
    const float* Whh_a = (const float*)d_in[7];
    const float* b_a   = (const float*)d_in[8];
    const float* Wih_v = (const float*)d_in[9];
    const float* Whh_v = (const float*)d_in[10];
    const float* b_v   = (const float*)d_in[11];
    const float* W1    = (const float*)d_in[12];
    const float* b1    = (const float*)d_in[13];
    const float* W2    = (const float*)d_in[14];
    const float* b2    = (const float*)d_in[15];
    const float* fw    = (const float*)d_in[16];

    float *Gt, *Ga, *Gv;
    cudaGetSymbolAddress((void**)&Gt, g_Gt);
    cudaGetSymbolAddress((void**)&Ga, g_Ga);
    cudaGetSymbolAddress((void**)&Gv, g_Gv);
    __nv_bfloat16 *Athi, *Atlo, *Aahi, *Aalo, *Avhi, *Avlo;
    __nv_bfloat16 *Wthi, *Wtlo, *Wahi, *Walo, *Wvhi, *Wvlo;
    cudaGetSymbolAddress((void**)&Athi, g_Athi);
    cudaGetSymbolAddress((void**)&Atlo, g_Atlo);
    cudaGetSymbolAddress((void**)&Aahi, g_Aahi);
    cudaGetSymbolAddress((void**)&Aalo, g_Aalo);
    cudaGetSymbolAddress((void**)&Avhi, g_Avhi);
    cudaGetSymbolAddress((void**)&Avlo, g_Avlo);
    cudaGetSymbolAddress((void**)&Wthi, g_Wthi);
    cudaGetSymbolAddress((void**)&Wtlo, g_Wtlo);
    cudaGetSymbolAddress((void**)&Wahi, g_Wahi);
    cudaGetSymbolAddress((void**)&Walo, g_Walo);
    cudaGetSymbolAddress((void**)&Wvhi, g_Wvhi);
    cudaGetSymbolAddress((void**)&Wvlo, g_Wvlo);

    cudaFuncSetAttribute(gemm_bf16s,      cudaFuncAttributeMaxDynamicSharedMemorySize, 2 * GSTG);
    cudaFuncSetAttribute(lstm_text_kernel,cudaFuncAttributeMaxDynamicSharedMemorySize, TEXT_SMEM);
    cudaFuncSetAttribute(lstm_av_kernel,  cudaFuncAttributeMaxDynamicSharedMemorySize, AV_SMEM);
    cudaFuncSetAttribute(fusion_kernel,   cudaFuncAttributeMaxDynamicSharedMemorySize, FUSION_SMEM);

    // conversions
    conv_split4<<<8192, 256>>>((const float4*)text,
                               (__nv_bfloat162*)Athi, (__nv_bfloat162*)Atlo,
                               (long)MM * KP_T / 4);
    conv_split4<<<384, 256>>>((const float4*)Wih_t,
                              (__nv_bfloat162*)Wthi, (__nv_bfloat162*)Wtlo,
                              (long)512 * KP_T / 4);
    conv_pad<<<4096, 256>>>(audio,  Aahi, Aalo, MM,  74, KP_A);
    conv_pad<<<80,   256>>>(Wih_a,  Wahi, Walo, 256, 74, KP_A);
    conv_pad<<<4096, 256>>>(vision, Avhi, Avlo, MM,  35, KP_V);
    conv_pad<<<48,   256>>>(Wih_v,  Wvhi, Wvlo, 256, 35, KP_V);

    // input projections (tensor cores)
    gemm_bf16s<<<dim3(MM / 128, 4), 256, 2 * GSTG>>>(Athi, Atlo, Wthi, Wtlo, b_t, Gt, 512, KP_T);
    gemm_bf16s<<<dim3(MM / 128, 2), 256, 2 * GSTG>>>(Aahi, Aalo, Wahi, Walo, b_a, Ga, 256, KP_A);
    gemm_bf16s<<<dim3(MM / 128, 2), 256, 2 * GSTG>>>(Avhi, Avlo, Wvhi, Wvlo, b_v, Gv, 256, KP_V);

    // recurrent weight prep
    prep_kernel<<<256, 256>>>(Whh_t, Whh_a, Whh_v);

    // recurrences
    lstm_text_kernel<<<128, 256, TEXT_SMEM>>>();
    lstm_av_kernel<<<128, 256, AV_SMEM>>>();

    // fusion + final
    fusion_kernel<<<BB, 256, FUSION_SMEM>>>(W1, b1, W2, b2);
    final_kernel<<<1, 256>>>(fw, (float*)d_out);
}

// round 7
// speedup vs baseline: 1.6533x; 1.0705x over previous
#include <cuda_runtime.h>
#include <cuda_bf16.h>
#include <math.h>
#include <stdint.h>

#define BB   256
#define TT   256
#define RANK 24
#define MM   (BB * TT)

#define KP_T 768
#define KP_A 80
#define KP_V 48

typedef unsigned long long ull;

// ---------------- scratch globals ----------------
__device__ float g_Gt[(size_t)MM * 512];
__device__ float g_Ga[(size_t)MM * 256];
__device__ float g_Gv[(size_t)MM * 256];
__device__ float g_z [(size_t)MM * 256];

__device__ __nv_bfloat16 g_Athi[(size_t)MM * KP_T];
__device__ __nv_bfloat16 g_Atlo[(size_t)MM * KP_T];
__device__ __nv_bfloat16 g_Aahi[(size_t)MM * KP_A];
__device__ __nv_bfloat16 g_Aalo[(size_t)MM * KP_A];
__device__ __nv_bfloat16 g_Avhi[(size_t)MM * KP_V];
__device__ __nv_bfloat16 g_Avlo[(size_t)MM * KP_V];
__device__ __nv_bfloat16 g_Wthi[512 * KP_T];
__device__ __nv_bfloat16 g_Wtlo[512 * KP_T];
__device__ __nv_bfloat16 g_Wahi[256 * KP_A];
__device__ __nv_bfloat16 g_Walo[256 * KP_A];
__device__ __nv_bfloat16 g_Wvhi[256 * KP_V];
__device__ __nv_bfloat16 g_Wvlo[256 * KP_V];

__device__ float g_WIt[128 * 512];   // Whh_t interleaved [k][2j+s]
__device__ float g_WTa[64 * 256];
__device__ float g_WTv[64 * 256];
__device__ float g_S [BB * RANK];
__device__ float g_ss[BB];

__device__ __forceinline__ float sigf(float x)  { return 1.0f / (1.0f + __expf(-x)); }
__device__ __forceinline__ float tanhfa(float x){ return 1.0f - 2.0f / (__expf(2.0f * x) + 1.0f); }

// packed fp32x2 helpers (Blackwell fma.rn.f32x2 — exact fp32, 2 lanes/instr)
__device__ __forceinline__ void fma2(ull& d, ull a, ull b) {
    asm("fma.rn.f32x2 %0, %1, %2, %0;" : "+l"(d) : "l"(a), "l"(b));
}
__device__ __forceinline__ ull pack2(float x, float y) {
    ull r; asm("mov.b64 %0, {%1,%2};" : "=l"(r) : "f"(x), "f"(y)); return r;
}
__device__ __forceinline__ float2 unpack2(ull v) {
    float2 r; asm("mov.b64 {%0,%1}, %2;" : "=f"(r.x), "=f"(r.y) : "l"(v)); return r;
}

// ---------------- fp32 -> (hi,lo) bf16 split ----------------
__global__ void conv_split4(const float4* __restrict__ src,
                            __nv_bfloat162* __restrict__ hi,
                            __nv_bfloat162* __restrict__ lo, long n4)
{
    for (long i = (long)blockIdx.x * blockDim.x + threadIdx.x; i < n4;
         i += (long)gridDim.x * blockDim.x) {
        float4 v = src[i];
        __nv_bfloat16 h0 = __float2bfloat16(v.x), h1 = __float2bfloat16(v.y);
        __nv_bfloat16 h2 = __float2bfloat16(v.z), h3 = __float2bfloat16(v.w);
        hi[2*i]   = __halves2bfloat162(h0, h1);
        hi[2*i+1] = __halves2bfloat162(h2, h3);
        lo[2*i]   = __halves2bfloat162(__float2bfloat16(v.x - __bfloat162float(h0)),
                                       __float2bfloat16(v.y - __bfloat162float(h1)));
        lo[2*i+1] = __halves2bfloat162(__float2bfloat16(v.z - __bfloat162float(h2)),
                                       __float2bfloat16(v.w - __bfloat162float(h3)));
    }
}

__device__ __forceinline__ void conv_one(const float* __restrict__ src,
                                         __nv_bfloat16* __restrict__ hi,
                                         __nv_bfloat16* __restrict__ lo,
                                         long i, int K, int Kp)
{
    int m = (int)(i / Kp), k = (int)(i % Kp);
    float v = (k < K) ? src[(size_t)m * K + k] : 0.0f;
    __nv_bfloat16 h = __float2bfloat16(v);
    hi[i] = h;
    lo[i] = __float2bfloat16(v - __bfloat162float(h));
}

#define R0 ((long)MM * KP_A)
#define R1 ((long)256 * KP_A)
#define R2 ((long)MM * KP_V)
#define R3 ((long)256 * KP_V)

__global__ void conv_pad_all(const float* __restrict__ audio, const float* __restrict__ Wa,
                             const float* __restrict__ vision, const float* __restrict__ Wv)
{
    long total = R0 + R1 + R2 + R3;
    for (long i = (long)blockIdx.x * blockDim.x + threadIdx.x; i < total;
         i += (long)gridDim.x * blockDim.x) {
        if (i < R0)               conv_one(audio,  g_Aahi, g_Aalo, i,             74, KP_A);
        else if (i < R0+R1)       conv_one(Wa,     g_Wahi, g_Walo, i-R0,          74, KP_A);
        else if (i < R0+R1+R2)    conv_one(vision, g_Avhi, g_Avlo, i-R0-R1,       35, KP_V);
        else                      conv_one(Wv,     g_Wvhi, g_Wvlo, i-R0-R1-R2,    35, KP_V);
    }
}

// ---------------- tensor-core GEMM: C = A * W^T + bias ----------------
#define GARR 6144
#define GSTG 24576

__device__ __forceinline__ void cp16(unsigned int dst, const void* src) {
    asm volatile("cp.async.cg.shared.global [%0], [%1], 16;\n" :: "r"(dst), "l"(src));
}
__device__ __forceinline__ unsigned int ld4(const char* base, int r, int e) {
    return *(const unsigned int*)(base + r * 48 + e * 2);
}
__device__ __forceinline__ void mma16816(float* d, const unsigned int* a, const unsigned int* b) {
    asm volatile(
        "mma.sync.aligned.m16n8k16.row.col.f32.bf16.bf16.f32 "
        "{%0,%1,%2,%3}, {%4,%5,%6,%7}, {%8,%9}, {%0,%1,%2,%3};"
        : "+f"(d[0]), "+f"(d[1]), "+f"(d[2]), "+f"(d[3])
        : "r"(a[0]), "r"(a[1]), "r"(a[2]), "r"(a[3]), "r"(b[0]), "r"(b[1]));
}

__global__ __launch_bounds__(256, 2)
void gemm_bf16s(const __nv_bfloat16* __restrict__ Ahi, const __nv_bfloat16* __restrict__ Alo,
                const __nv_bfloat16* __restrict__ Bhi, const __nv_bfloat16* __restrict__ Blo,
                const float* __restrict__ bias, float* __restrict__ C, int N, int Kp)
{
    extern __shared__ char gsm[];
    const int tid = threadIdx.x;
    const size_t m0 = (size_t)blockIdx.x * 128;
    const size_t n0 = (size_t)blockIdx.y * 128;
    const int rr = tid >> 1, cc = tid & 1;
    const unsigned int us = (unsigned int)__cvta_generic_to_shared(gsm);
    const int NK = Kp >> 4;

    const __nv_bfloat16* gp[4] = {Ahi + (m0 + rr) * Kp + cc * 8,
                                  Alo + (m0 + rr) * Kp + cc * 8,
                                  Bhi + (n0 + rr) * Kp + cc * 8,
                                  Blo + (n0 + rr) * Kp + cc * 8};
    const unsigned int dbase = us + rr * 48 + cc * 16;

    const int warp = tid >> 5, wm = warp >> 1, wn = warp & 1;
    const int lane = tid & 31, grp = lane >> 2, q = lane & 3;

    float acc[2][8][4];
#pragma unroll
    for (int mt = 0; mt < 2; mt++)
#pragma unroll
        for (int nt = 0; nt < 8; nt++)
#pragma unroll
            for (int i = 0; i < 4; i++) acc[mt][nt][i] = 0.0f;

#pragma unroll
    for (int arr = 0; arr < 4; arr++) cp16(dbase + arr * GARR, gp[arr]);
    asm volatile("cp.async.commit_group;\n" ::: "memory");

    for (int kc = 0; kc < NK; kc++) {
        if (kc + 1 < NK) {
#pragma unroll
            for (int arr = 0; arr < 4; arr++)
                cp16(dbase + ((kc + 1) & 1) * GSTG + arr * GARR, gp[arr] + (kc + 1) * 16);
        }
        asm volatile("cp.async.commit_group;\n" ::: "memory");
        asm volatile("cp.async.wait_group 1;\n" ::: "memory");
        __syncthreads();

        const char* st  = gsm + (kc & 1) * GSTG;
        const char* sAh = st;
        const char* sAl = st + GARR;
        const char* sBh = st + 2 * GARR;
        const char* sBl = st + 3 * GARR;

        unsigned int bh[8][2], af[2][4], al[2][4];
#pragma unroll
        for (int nt = 0; nt < 8; nt++) {
            int nr = wn * 64 + nt * 8 + grp;
            bh[nt][0] = ld4(sBh, nr, 2 * q);
            bh[nt][1] = ld4(sBh, nr, 2 * q + 8);
        }
#pragma unroll
        for (int mt = 0; mt < 2; mt++) {
            int r = wm * 32 + mt * 16 + grp;
            af[mt][0] = ld4(sAh, r,     2 * q);
            af[mt][1] = ld4(sAh, r + 8, 2 * q);
            af[mt][2] = ld4(sAh, r,     2 * q + 8);
            af[mt][3] = ld4(sAh, r + 8, 2 * q + 8);
            al[mt][0] = ld4(sAl, r,     2 * q);
            al[mt][1] = ld4(sAl, r + 8, 2 * q);
            al[mt][2] = ld4(sAl, r,     2 * q + 8);
            al[mt][3] = ld4(sAl, r + 8, 2 * q + 8);
        }
#pragma unroll
        for (int mt = 0; mt < 2; mt++)
#pragma unroll
            for (int nt = 0; nt < 8; nt++) {
                mma16816(acc[mt][nt], af[mt], bh[nt]);
                mma16816(acc[mt][nt], al[mt], bh[nt]);
            }
#pragma unroll
        for (int nt = 0; nt < 8; nt++) {
            int nr = wn * 64 + nt * 8 + grp;
            bh[nt][0] = ld4(sBl, nr, 2 * q);
            bh[nt][1] = ld4(sBl, nr, 2 * q + 8);
        }
#pragma unroll
        for (int mt = 0; mt < 2; mt++)
#pragma unroll
            for (int nt = 0; nt < 8; nt++)
                mma16816(acc[mt][nt], af[mt], bh[nt]);
        __syncthreads();
    }

#pragma unroll
    for (int mt = 0; mt < 2; mt++) {
        size_t r = m0 + wm * 32 + mt * 16 + grp;
#pragma unroll
        for (int nt = 0; nt < 8; nt++) {
            size_t cb = n0 + wn * 64 + nt * 8 + 2 * q;
            float b0v = bias[cb], b1v = bias[cb + 1];
            *(float2*)&C[r * N + cb]       = make_float2(acc[mt][nt][0] + b0v, acc[mt][nt][1] + b1v);
            *(float2*)&C[(r + 8) * N + cb] = make_float2(acc[mt][nt][2] + b0v, acc[mt][nt][3] + b1v);
        }
    }
}

// ---------------- prep recurrent weights ----------------
__global__ void prep_kernel(const float* __restrict__ Wt,
                            const float* __restrict__ Wa,
                            const float* __restrict__ Wv)
{
    int i = blockIdx.x * 256 + threadIdx.x;
    if (i < 512 * 128) {
        int n = i / 128, k = i % 128;
        int j = (n < 256) ? n : (n - 256);
        int s = (n < 256) ? 0 : 1;
        g_WIt[k * 512 + 2 * j + s] = Wt[i];
    }
    if (i < 256 * 64) {
        int n = i / 64, k = i % 64;
        g_WTa[k * 256 + n] = Wa[i];
        g_WTv[k * 256 + n] = Wv[i];
    }
}

// ---------------- LSTM text: 128 CTAs, 2 batch rows each ----------------
// Whh panels 0..KCS-1 in SMEM (packed pairs), panels KCS..127 in registers.
// Inner loop: packed fma.rn.f32x2 on (w_colj, w_colj+256) x (h,h).
#define KCS 64
#define TEXT_SMEM ((KCS * 512 + 512 + 512) * 4)   // 135168 B

__global__ __launch_bounds__(256, 1)
void lstm_text_kernel()
{
    extern __shared__ float sm[];
    ull*        Wc8  = (ull*)sm;                         // KCS*256 packed (w0,w1)
    ulonglong2* hdup = (ulonglong2*)(sm + KCS * 512);    // 128: ((h0,h0),(h1,h1))
    float*      exf0 = sm + KCS * 512 + 512;
    float*      exf1 = exf0 + 128;
    float*      exo0 = exf1 + 128;
    float*      exo1 = exo0 + 128;

    const int bx = blockIdx.x, j = threadIdx.x;
    const int b0 = bx * 2, b1 = b0 + 1;
    const ull* WI8 = (const ull*)g_WIt;

    for (int i = j; i < KCS * 256; i += 256) Wc8[i] = WI8[i];
    ull wreg[128 - KCS];
#pragma unroll
    for (int kk = 0; kk < 128 - KCS; kk++) wreg[kk] = WI8[(KCS + kk) * 256 + j];
    if (j < 128) { hdup[j].x = pack2(0.f, 0.f); hdup[j].y = pack2(0.f, 0.f); }
    __syncthreads();

    float c0 = 0.0f, c1 = 0.0f;

    for (int t = 0; t < TT; t++) {
        const float* Gb0 = g_Gt + ((size_t)(b0 * TT + t)) * 512;
        const float* Gb1 = g_Gt + ((size_t)(b1 * TT + t)) * 512;
        ull p0 = pack2(Gb0[j], Gb0[j + 256]);   // sample0: (col j, col j+256)
        ull p1 = pack2(Gb1[j], Gb1[j + 256]);   // sample1

#pragma unroll 8
        for (int k = 0; k < KCS; k++) {
            ull w = Wc8[k * 256 + j];
            ulonglong2 h = hdup[k];
            fma2(p0, w, h.x);
            fma2(p1, w, h.y);
        }
#pragma unroll
        for (int kk = 0; kk < 128 - KCS; kk++) {
            ulonglong2 h = hdup[KCS + kk];
            fma2(p0, wreg[kk], h.x);
            fma2(p1, wreg[kk], h.y);
        }
        float2 A0 = unpack2(p0);   // (a00 = gate col j, a01 = gate col j+256)
        float2 A1 = unpack2(p1);

        if (j >= 128) {            // j: f-gate col, j+256: o-gate col
            int jj = j - 128;
            exf0[jj] = sigf(A0.x); exf1[jj] = sigf(A1.x);
            exo0[jj] = A0.y;       exo1[jj] = A1.y;
        }
        __syncthreads();
        if (j < 128) {             // j: i-gate col, j+256: g-gate col
            c0 = exf0[j] * c0 + sigf(A0.x) * tanhfa(A0.y);
            c1 = exf1[j] * c1 + sigf(A1.x) * tanhfa(A1.y);
            float h0 = sigf(exo0[j]) * tanhfa(c0);
            float h1 = sigf(exo1[j]) * tanhfa(c1);
            hdup[j].x = pack2(h0, h0);
            hdup[j].y = pack2(h1, h1);
            g_z[((size_t)(b0 * TT + t)) * 256 + 128 + j] = h0;
            g_z[((size_t)(b1 * TT + t)) * 256 + 128 + j] = h1;
        }
        __syncthreads();
    }
}

// ---------------- LSTM audio+vision: 128 CTAs, 4 batch rows each ----------------
#define AV_SMEM ((64 * 256 + 256 + 1024) * 4)

__global__ __launch_bounds__(256, 1)
void lstm_av_kernel()
{
    extern __shared__ float sm[];
    float*      Wc   = sm;                         // 64*256
    ulonglong2* hb2  = (ulonglong2*)(sm + 16384);  // 64: ((h0,h1),(h2,h3))
    float*      hbufF = sm + 16384;
    float*      gb   = sm + 16384 + 256;           // 4*256

    const int bx = blockIdx.x, j = threadIdx.x;
    const bool is_audio = (bx < 64);
    const int blk = is_audio ? bx : (bx - 64);
    const float* Gsrc = is_audio ? g_Ga : g_Gv;
    const float* WTs  = is_audio ? g_WTa : g_WTv;
    const int zoff = is_audio ? 0 : 64;
    const int b0 = blk * 4;

    for (int i = j; i < 64 * 256; i += 256) Wc[i] = WTs[i];
    if (j < 64) { hb2[j].x = pack2(0.f, 0.f); hb2[j].y = pack2(0.f, 0.f); }
    __syncthreads();

    const int row = j >> 6, hj = j & 63;
    float c = 0.0f;

    for (int t = 0; t < TT; t++) {
        ull q0 = pack2(Gsrc[((size_t)((b0 + 0) * TT + t)) * 256 + j],
                       Gsrc[((size_t)((b0 + 1) * TT + t)) * 256 + j]);
        ull q1 = pack2(Gsrc[((size_t)((b0 + 2) * TT + t)) * 256 + j],
                       Gsrc[((size_t)((b0 + 3) * TT + t)) * 256 + j]);

#pragma unroll 8
        for (int k = 0; k < 64; k++) {
            float w = Wc[k * 256 + j];
            ull ww = pack2(w, w);
            ulonglong2 h = hb2[k];
            fma2(q0, ww, h.x);
            fma2(q1, ww, h.y);
        }
        float2 Q0 = unpack2(q0), Q1 = unpack2(q1);
        gb[0 * 256 + j] = Q0.x; gb[1 * 256 + j] = Q0.y;
        gb[2 * 256 + j] = Q1.x; gb[3 * 256 + j] = Q1.y;
        __syncthreads();

        const float* g = gb + row * 256;
        float gi = sigf(g[hj]),         gf = sigf(g[64 + hj]);
        float gg = tanhfa(g[128 + hj]), go = sigf(g[192 + hj]);
        c = gf * c + gi * gg;
        float h = go * tanhfa(c);
        hbufF[hj * 4 + row] = h;
        g_z[((size_t)((b0 + row) * TT + t)) * 256 + zoff + hj] = h;
        __syncthreads();
    }
}

// ---------------- fusion ----------------
#define FUSION_SMEM ((6144 + 12312 + 24 + 24 + 192 + 8) * 4)

__global__ __launch_bounds__(256, 1)
void fusion_kernel(const float* __restrict__ W1, const float* __restrict__ b1,
                   const float* __restrict__ W2, const float* __restrict__ b2)
{
    extern __shared__ float sm[];
    float* W1s   = sm;
    float* W2s   = sm + 6144;
    float* b1s   = W2s + 12312;
    float* bcs   = b1s + 24;
    float* Sred  = bcs + 24;
    float* ssred = Sred + 192;

    const int tid = threadIdx.x;
    const int b   = blockIdx.x;

    for (int i = tid; i < 6144;  i += 256) W1s[i] = W1[i];
    for (int i = tid; i < 12312; i += 256) W2s[i] = W2[i];
    if (tid < 24) b1s[tid] = b1[tid];
    __syncthreads();
    if (tid < 24) bcs[tid] = b2[tid] + W2s[tid * 513];
    __syncthreads();

    const int w = tid >> 5, l = tid & 31;
    float S[RANK];
#pragma unroll
    for (int r = 0; r < RANK; r++) S[r] = 0.0f;
    float ss = 0.0f;

    const float* zb = g_z + (size_t)b * TT * 256;

    for (int t0 = w * 32; t0 < w * 32 + 32; t0 += 2) {
        const int t1 = t0 + 1;
        const int t2 = (t0 + 2) & 255;
        float zc0[8], zc1[8], zc2[8];
#pragma unroll
        for (int q = 0; q < 8; q++) {
            zc0[q] = zb[t0 * 256 + l + 32 * q];
            zc1[q] = zb[t1 * 256 + l + 32 * q];
            zc2[q] = zb[t2 * 256 + l + 32 * q];
            ss += zc0[q] * zc0[q] + zc1[q] * zc1[q];
        }
#pragma unroll
        for (int r = 0; r < RANK; r++) {
            float a0 = 0.0f, bb0 = 0.0f, a1 = 0.0f, bb1 = 0.0f;
#pragma unroll
            for (int q = 0; q < 8; q++) {
                float w1v = W1s[r * 256 + l + 32 * q];
                float w2a = W2s[r * 513 + 1   + l + 32 * q];
                float w2b = W2s[r * 513 + 257 + l + 32 * q];
                a0  += w1v * zc0[q];
                bb0 += w2a * zc0[q] + w2b * zc1[q];
                a1  += w1v * zc1[q];
                bb1 += w2a * zc1[q] + w2b * zc2[q];
            }
#pragma unroll
            for (int o = 16; o; o >>= 1) {
                a0  += __shfl_xor_sync(0xffffffffu, a0,  o);
                bb0 += __shfl_xor_sync(0xffffffffu, bb0, o);
                a1  += __shfl_xor_sync(0xffffffffu, a1,  o);
                bb1 += __shfl_xor_sync(0xffffffffu, bb1, o);
            }
            S[r] += (a0 + b1s[r]) * (bb0 + bcs[r])
                  + (a1 + b1s[r]) * (bb1 + bcs[r]);
        }
    }

#pragma unroll
    for (int o = 16; o; o >>= 1) ss += __shfl_xor_sync(0xffffffffu, ss, o);
    if (l == 0) {
#pragma unroll
        for (int r = 0; r < RANK; r++) Sred[w * RANK + r] = S[r];
        ssred[w] = ss;
    }
    __syncthreads();
    if (tid < RANK) {
        float tot = 0.0f;
        for (int ww = 0; ww < 8; ww++) tot += Sred[ww * RANK + tid];
        g_S[b * RANK + tid] = tot;
    }
    if (tid == 32) {
        float tot = 0.0f;
        for (int ww = 0; ww < 8; ww++) tot += ssred[ww];
        g_ss[b] = tot;
    }
}

// ---------------- final ----------------
__global__ void final_kernel(const float* __restrict__ fw, float* __restrict__ out)
{
    const int tid = threadIdx.x;
    float s = 0.0f;
#pragma unroll
    for (int r = 0; r < RANK; r++) s += fw[r] * g_S[tid * RANK + r];
    out[tid] = s * (1.0f / (float)TT);

    __shared__ float red[256];
    red[tid] = sqrtf(g_ss[tid]);
    __syncthreads();
    for (int o = 128; o; o >>= 1) {
        if (tid < o) red[tid] += red[tid + o];
        __syncthreads();
    }
    if (tid == 0) out[256] = red[0] / (float)BB;
}

// ---------------- launch ----------------
extern "C" void kernel_launch(void* const* d_in, const int* in_sizes, int n_in,
                              void* d_out, int out_size)
{
    const float* text  = (const float*)d_in[0];
    const float* audio = (const float*)d_in[1];
    const float* vision= (const float*)d_in[2];
    const float* Wih_t = (const float*)d_in[3];
    const float* Whh_t = (const float*)d_in[4];
    const float* b_t   = (const float*)d_in[5];
    const float* Wih_a = (const float*)d_in[6];
    const float* Whh_a = (const float*)d_in[7];
    const float* b_a   = (const float*)d_in[8];
    const float* Wih_v = (const float*)d_in[9];
    const float* Whh_v = (const float*)d_in[10];
    const float* b_v   = (const float*)d_in[11];
    const float* W1    = (const float*)d_in[12];
    const float* b1    = (const float*)d_in[13];
    const float* W2    = (const float*)d_in[14];
    const float* b2    = (const float*)d_in[15];
    const float* fw    = (const float*)d_in[16];

    float *Gt, *Ga, *Gv;
    cudaGetSymbolAddress((void**)&Gt, g_Gt);
    cudaGetSymbolAddress((void**)&Ga, g_Ga);
    cudaGetSymbolAddress((void**)&Gv, g_Gv);
    __nv_bfloat16 *Athi, *Atlo, *Aahi, *Aalo, *Avhi, *Avlo;
    __nv_bfloat16 *Wthi, *Wtlo, *Wahi, *Walo, *Wvhi, *Wvlo;
    cudaGetSymbolAddress((void**)&Athi, g_Athi);
    cudaGetSymbolAddress((void**)&Atlo, g_Atlo);
    cudaGetSymbolAddress((void**)&Aahi, g_Aahi);
    cudaGetSymbolAddress((void**)&Aalo, g_Aalo);
    cudaGetSymbolAddress((void**)&Avhi, g_Avhi);
    cudaGetSymbolAddress((void**)&Avlo, g_Avlo);
    cudaGetSymbolAddress((void**)&Wthi, g_Wthi);
    cudaGetSymbolAddress((void**)&Wtlo, g_Wtlo);
    cudaGetSymbolAddress((void**)&Wahi, g_Wahi);
    cudaGetSymbolAddress((void**)&Walo, g_Walo);
    cudaGetSymbolAddress((void**)&Wvhi, g_Wvhi);
    cudaGetSymbolAddress((void**)&Wvlo, g_Wvlo);

    cudaFuncSetAttribute(gemm_bf16s,      cudaFuncAttributeMaxDynamicSharedMemorySize, 2 * GSTG);
    cudaFuncSetAttribute(lstm_text_kernel,cudaFuncAttributeMaxDynamicSharedMemorySize, TEXT_SMEM);
    cudaFuncSetAttribute(lstm_av_kernel,  cudaFuncAttributeMaxDynamicSharedMemorySize, AV_SMEM);
    cudaFuncSetAttribute(fusion_kernel,   cudaFuncAttributeMaxDynamicSharedMemorySize, FUSION_SMEM);

    // conversions (3 launches)
    conv_split4<<<8192, 256>>>((const float4*)text,
                               (__nv_bfloat162*)Athi, (__nv_bfloat162*)Atlo,
                               (long)MM * KP_T / 4);
    conv_split4<<<384, 256>>>((const float4*)Wih_t,
                              (__nv_bfloat162*)Wthi, (__nv_bfloat162*)Wtlo,
                              (long)512 * KP_T / 4);
    conv_pad_all<<<4096, 256>>>(audio, Wih_a, vision, Wih_v);

    // input projections — text LAST so it is launch #6 (ncu -s 5 -c 1 target)
    gemm_bf16s<<<dim3(MM / 128, 2), 256, 2 * GSTG>>>(Aahi, Aalo, Wahi, Walo, b_a, Ga, 256, KP_A);
    gemm_bf16s<<<dim3(MM / 128, 2), 256, 2 * GSTG>>>(Avhi, Avlo, Wvhi, Wvlo, b_v, Gv, 256, KP_V);
    gemm_bf16s<<<dim3(MM / 128, 4), 256, 2 * GSTG>>>(Athi, Atlo, Wthi, Wtlo, b_t, Gt, 512, KP_T);

    // recurrent weight prep
    prep_kernel<<<256, 256>>>(Whh_t, Whh_a, Whh_v);

    // recurrences
    lstm_text_kernel<<<128, 256, TEXT_SMEM>>>();
    lstm_av_kernel<<<128, 256, AV_SMEM>>>();

    // fusion + final
    fusion_kernel<<<BB, 256, FUSION_SMEM>>>(W1, b1, W2, b2);
    final_kernel<<<1, 256>>>(fw, (float*)d_out);
}

// round 10
// speedup vs baseline: 1.7277x; 1.0450x over previous
#include <cuda_runtime.h>
#include <cuda_bf16.h>
#include <math.h>
#include <stdint.h>

#define BB   256
#define TT   256
#define RANK 24
#define MM   (BB * TT)

#define KP_T 768
#define KP_A 96
#define KP_V 64

typedef unsigned long long ull;

// ---------------- scratch globals ----------------
__device__ float g_Gt[(size_t)MM * 512];
__device__ float g_Ga[(size_t)MM * 256];
__device__ float g_Gv[(size_t)MM * 256];
__device__ float g_z [(size_t)MM * 256];

__device__ __nv_bfloat16 g_Athi[(size_t)MM * KP_T];
__device__ __nv_bfloat16 g_Atlo[(size_t)MM * KP_T];
__device__ __nv_bfloat16 g_Aahi[(size_t)MM * KP_A];
__device__ __nv_bfloat16 g_Aalo[(size_t)MM * KP_A];
__device__ __nv_bfloat16 g_Avhi[(size_t)MM * KP_V];
__device__ __nv_bfloat16 g_Avlo[(size_t)MM * KP_V];
__device__ __nv_bfloat16 g_Wthi[512 * KP_T];
__device__ __nv_bfloat16 g_Wtlo[512 * KP_T];
__device__ __nv_bfloat16 g_Wahi[256 * KP_A];
__device__ __nv_bfloat16 g_Walo[256 * KP_A];
__device__ __nv_bfloat16 g_Wvhi[256 * KP_V];
__device__ __nv_bfloat16 g_Wvlo[256 * KP_V];

__device__ float g_WIt[128 * 512];   // Whh_t interleaved [k][2j+s]
__device__ float g_WTa[64 * 256];
__device__ float g_WTv[64 * 256];
__device__ float g_S [BB * RANK];
__device__ float g_ss[BB];

__device__ __forceinline__ float sigf(float x)  { return 1.0f / (1.0f + __expf(-x)); }
__device__ __forceinline__ float tanhfa(float x){ return 1.0f - 2.0f / (__expf(2.0f * x) + 1.0f); }

// packed fp32x2 helpers (exact fp32, 2 lanes/instr)
__device__ __forceinline__ void fma2(ull& d, ull a, ull b) {
    asm("fma.rn.f32x2 %0, %1, %2, %0;" : "+l"(d) : "l"(a), "l"(b));
}
__device__ __forceinline__ ull pack2(float x, float y) {
    ull r; asm("mov.b64 %0, {%1,%2};" : "=l"(r) : "f"(x), "f"(y)); return r;
}
__device__ __forceinline__ float2 unpack2(ull v) {
    float2 r; asm("mov.b64 {%0,%1}, %2;" : "=f"(r.x), "=f"(r.y) : "l"(v)); return r;
}

// ---------------- fp32 -> (hi,lo) bf16 split ----------------
__global__ void conv_split4(const float4* __restrict__ src,
                            __nv_bfloat162* __restrict__ hi,
                            __nv_bfloat162* __restrict__ lo, long n4)
{
    for (long i = (long)blockIdx.x * blockDim.x + threadIdx.x; i < n4;
         i += (long)gridDim.x * blockDim.x) {
        float4 v = src[i];
        __nv_bfloat16 h0 = __float2bfloat16(v.x), h1 = __float2bfloat16(v.y);
        __nv_bfloat16 h2 = __float2bfloat16(v.z), h3 = __float2bfloat16(v.w);
        hi[2*i]   = __halves2bfloat162(h0, h1);
        hi[2*i+1] = __halves2bfloat162(h2, h3);
        lo[2*i]   = __halves2bfloat162(__float2bfloat16(v.x - __bfloat162float(h0)),
                                       __float2bfloat16(v.y - __bfloat162float(h1)));
        lo[2*i+1] = __halves2bfloat162(__float2bfloat16(v.z - __bfloat162float(h2)),
                                       __float2bfloat16(v.w - __bfloat162float(h3)));
    }
}

__device__ __forceinline__ void conv_one(const float* __restrict__ src,
                                         __nv_bfloat16* __restrict__ hi,
                                         __nv_bfloat16* __restrict__ lo,
                                         long i, int K, int Kp)
{
    int m = (int)(i / Kp), k = (int)(i % Kp);
    float v = (k < K) ? src[(size_t)m * K + k] : 0.0f;
    __nv_bfloat16 h = __float2bfloat16(v);
    hi[i] = h;
    lo[i] = __float2bfloat16(v - __bfloat162float(h));
}

#define R0 ((long)MM * KP_A)
#define R1 ((long)256 * KP_A)
#define R2 ((long)MM * KP_V)
#define R3 ((long)256 * KP_V)

__global__ void conv_pad_all(const float* __restrict__ audio, const float* __restrict__ Wa,
                             const float* __restrict__ vision, const float* __restrict__ Wv)
{
    long total = R0 + R1 + R2 + R3;
    for (long i = (long)blockIdx.x * blockDim.x + threadIdx.x; i < total;
         i += (long)gridDim.x * blockDim.x) {
        if (i < R0)               conv_one(audio,  g_Aahi, g_Aalo, i,             74, KP_A);
        else if (i < R0+R1)       conv_one(Wa,     g_Wahi, g_Walo, i-R0,          74, KP_A);
        else if (i < R0+R1+R2)    conv_one(vision, g_Avhi, g_Avlo, i-R0-R1,       35, KP_V);
        else                      conv_one(Wv,     g_Wvhi, g_Wvlo, i-R0-R1-R2,    35, KP_V);
    }
}

// ---------------- tensor-core GEMM (mma.sync): C = A * W^T + bias ----------------
// split bf16, 3 passes. CTA tile 128x128, warp tile 32x64. K-chunk 32.
// smem row: 64B data + 16B pad = 80B -> bank (20*grp+q)%32, conflict-free.
// Grid: x = n-tile (fastest) so concurrent CTAs share the A m-tile via L2.
#define GARR 10240
#define GSTG 40960

__device__ __forceinline__ void cp16(unsigned dst, const void* src) {
    asm volatile("cp.async.cg.shared.global [%0], [%1], 16;\n" :: "r"(dst), "l"(src));
}
__device__ __forceinline__ unsigned ld4(const char* base, int r, int e) {
    return *(const unsigned*)(base + r * 80 + e * 2);
}
__device__ __forceinline__ void mma16816(float* d, const unsigned* a, const unsigned* b) {
    asm volatile(
        "mma.sync.aligned.m16n8k16.row.col.f32.bf16.bf16.f32 "
        "{%0,%1,%2,%3}, {%4,%5,%6,%7}, {%8,%9}, {%0,%1,%2,%3};"
        : "+f"(d[0]), "+f"(d[1]), "+f"(d[2]), "+f"(d[3])
        : "r"(a[0]), "r"(a[1]), "r"(a[2]), "r"(a[3]), "r"(b[0]), "r"(b[1]));
}

__global__ __launch_bounds__(256, 2)
void gemm_bf16s(const __nv_bfloat16* __restrict__ Ahi, const __nv_bfloat16* __restrict__ Alo,
                const __nv_bfloat16* __restrict__ Bhi, const __nv_bfloat16* __restrict__ Blo,
                const float* __restrict__ bias, float* __restrict__ C, int N, int Kp)
{
    extern __shared__ char gsm[];
    const int tid = threadIdx.x;
    const size_t n0 = (size_t)blockIdx.x * 128;   // n fastest -> A shared in L2
    const size_t m0 = (size_t)blockIdx.y * 128;
    const unsigned us = (unsigned)__cvta_generic_to_shared(gsm);
    const int NK = Kp >> 5;

    const __nv_bfloat16* gsrc[4] = {Ahi + m0 * Kp, Alo + m0 * Kp,
                                    Bhi + n0 * Kp, Blo + n0 * Kp};

    auto load_chunk = [&](int kc, int stg) {
        unsigned base = us + stg * GSTG;
#pragma unroll
        for (int arr = 0; arr < 4; arr++) {
#pragma unroll
            for (int i = 0; i < 2; i++) {
                int u = tid + 256 * i;          // 0..511
                int row = u >> 2, seg = u & 3;  // 4x16B segs per 64B row
                unsigned dst = base + arr * GARR + row * 80 + seg * 16;
                cp16(dst, gsrc[arr] + (size_t)row * Kp + kc * 32 + seg * 8);
            }
        }
        asm volatile("cp.async.commit_group;" ::: "memory");
    };

    const int warp = tid >> 5, wm = warp >> 1, wn = warp & 1;
    const int lane = tid & 31, grp = lane >> 2, q = lane & 3;

    float acc[2][8][4];
#pragma unroll
    for (int mt = 0; mt < 2; mt++)
#pragma unroll
        for (int nt = 0; nt < 8; nt++)
#pragma unroll
            for (int i = 0; i < 4; i++) acc[mt][nt][i] = 0.0f;

    load_chunk(0, 0);

    for (int kc = 0; kc < NK; kc++) {
        if (kc + 1 < NK) load_chunk(kc + 1, (kc + 1) & 1);
        else             asm volatile("cp.async.commit_group;" ::: "memory");
        asm volatile("cp.async.wait_group 1;" ::: "memory");
        __syncthreads();

        const char* st  = gsm + (kc & 1) * GSTG;
        const char* sAh = st;
        const char* sAl = st + GARR;
        const char* sBh = st + 2 * GARR;
        const char* sBl = st + 3 * GARR;

#pragma unroll
        for (int kk = 0; kk < 32; kk += 16) {
            unsigned bh[8][2], af[2][4], al[2][4];
#pragma unroll
            for (int nt = 0; nt < 8; nt++) {
                int nr = wn * 64 + nt * 8 + grp;
                bh[nt][0] = ld4(sBh, nr, kk + 2 * q);
                bh[nt][1] = ld4(sBh, nr, kk + 2 * q + 8);
            }
#pragma unroll
            for (int mt = 0; mt < 2; mt++) {
                int r = wm * 32 + mt * 16 + grp;
                af[mt][0] = ld4(sAh, r,     kk + 2 * q);
                af[mt][1] = ld4(sAh, r + 8, kk + 2 * q);
                af[mt][2] = ld4(sAh, r,     kk + 2 * q + 8);
                af[mt][3] = ld4(sAh, r + 8, kk + 2 * q + 8);
                al[mt][0] = ld4(sAl, r,     kk + 2 * q);
                al[mt][1] = ld4(sAl, r + 8, kk + 2 * q);
                al[mt][2] = ld4(sAl, r,     kk + 2 * q + 8);
                al[mt][3] = ld4(sAl, r + 8, kk + 2 * q + 8);
            }
#pragma unroll
            for (int mt = 0; mt < 2; mt++)
#pragma unroll
                for (int nt = 0; nt < 8; nt++) {
                    mma16816(acc[mt][nt], af[mt], bh[nt]);
                    mma16816(acc[mt][nt], al[mt], bh[nt]);
                }
#pragma unroll
            for (int nt = 0; nt < 8; nt++) {
                int nr = wn * 64 + nt * 8 + grp;
                bh[nt][0] = ld4(sBl, nr, kk + 2 * q);
                bh[nt][1] = ld4(sBl, nr, kk + 2 * q + 8);
            }
#pragma unroll
            for (int mt = 0; mt < 2; mt++)
#pragma unroll
                for (int nt = 0; nt < 8; nt++)
                    mma16816(acc[mt][nt], af[mt], bh[nt]);
        }
        __syncthreads();
    }

#pragma unroll
    for (int mt = 0; mt < 2; mt++) {
        size_t r = m0 + wm * 32 + mt * 16 + grp;
#pragma unroll
        for (int nt = 0; nt < 8; nt++) {
            size_t cb = n0 + wn * 64 + nt * 8 + 2 * q;
            float b0v = bias[cb], b1v = bias[cb + 1];
            *(float2*)&C[r * N + cb]       = make_float2(acc[mt][nt][0] + b0v, acc[mt][nt][1] + b1v);
            *(float2*)&C[(r + 8) * N + cb] = make_float2(acc[mt][nt][2] + b0v, acc[mt][nt][3] + b1v);
        }
    }
}

// ---------------- prep recurrent weights ----------------
__global__ void prep_kernel(const float* __restrict__ Wt,
                            const float* __restrict__ Wa,
                            const float* __restrict__ Wv)
{
    int i = blockIdx.x * 256 + threadIdx.x;
    if (i < 512 * 128) {
        int n = i / 128, k = i % 128;
        int j = (n < 256) ? n : (n - 256);
        int s = (n < 256) ? 0 : 1;
        g_WIt[k * 512 + 2 * j + s] = Wt[i];
    }
    if (i < 256 * 64) {
        int n = i / 64, k = i % 64;
        g_WTa[k * 256 + n] = Wa[i];
        g_WTv[k * 256 + n] = Wv[i];
    }
}

// ---------------- LSTM text: 128 CTAs, 2 batch rows each ----------------
#define KCS 64
#define TEXT_SMEM ((KCS * 512 + 512 + 512) * 4)

__global__ __launch_bounds__(256, 1)
void lstm_text_kernel()
{
    extern __shared__ float sm[];
    ull*        Wc8  = (ull*)sm;
    ulonglong2* hdup = (ulonglong2*)(sm + KCS * 512);
    float*      exf0 = sm + KCS * 512 + 512;
    float*      exf1 = exf0 + 128;
    float*      exo0 = exf1 + 128;
    float*      exo1 = exo0 + 128;

    const int bx = blockIdx.x, j = threadIdx.x;
    const int b0 = bx * 2, b1 = b0 + 1;
    const ull* WI8 = (const ull*)g_WIt;

    for (int i = j; i < KCS * 256; i += 256) Wc8[i] = WI8[i];
    ull wreg[128 - KCS];
#pragma unroll
    for (int kk = 0; kk < 128 - KCS; kk++) wreg[kk] = WI8[(KCS + kk) * 256 + j];
    if (j < 128) { hdup[j].x = pack2(0.f, 0.f); hdup[j].y = pack2(0.f, 0.f); }
    __syncthreads();

    float c0 = 0.0f, c1 = 0.0f;

    for (int t = 0; t < TT; t++) {
        const float* Gb0 = g_Gt + ((size_t)(b0 * TT + t)) * 512;
        const float* Gb1 = g_Gt + ((size_t)(b1 * TT + t)) * 512;
        ull p0 = pack2(Gb0[j], Gb0[j + 256]);
        ull p1 = pack2(Gb1[j], Gb1[j + 256]);

#pragma unroll 8
        for (int k = 0; k < KCS; k++) {
            ull w = Wc8[k * 256 + j];
            ulonglong2 h = hdup[k];
            fma2(p0, w, h.x);
            fma2(p1, w, h.y);
        }
#pragma unroll
        for (int kk = 0; kk < 128 - KCS; kk++) {
            ulonglong2 h = hdup[KCS + kk];
            fma2(p0, wreg[kk], h.x);
            fma2(p1, wreg[kk], h.y);
        }
        float2 A0 = unpack2(p0);
        float2 A1 = unpack2(p1);

        if (j >= 128) {
            int jj = j - 128;
            exf0[jj] = sigf(A0.x); exf1[jj] = sigf(A1.x);
            exo0[jj] = A0.y;       exo1[jj] = A1.y;
        }
        __syncthreads();
        if (j < 128) {
            c0 = exf0[j] * c0 + sigf(A0.x) * tanhfa(A0.y);
            c1 = exf1[j] * c1 + sigf(A1.x) * tanhfa(A1.y);
            float h0 = sigf(exo0[j]) * tanhfa(c0);
            float h1 = sigf(exo1[j]) * tanhfa(c1);
            hdup[j].x = pack2(h0, h0);
            hdup[j].y = pack2(h1, h1);
            g_z[((size_t)(b0 * TT + t)) * 256 + 128 + j] = h0;
            g_z[((size_t)(b1 * TT + t)) * 256 + 128 + j] = h1;
        }
        __syncthreads();
    }
}

// ---------------- LSTM audio+vision: 128 CTAs, 4 batch rows each ----------------
#define AV_SMEM ((64 * 256 + 256 + 1024) * 4)

__global__ __launch_bounds__(256, 1)
void lstm_av_kernel()
{
    extern __shared__ float sm[];
    float*      Wc   = sm;
    ulonglong2* hb2  = (ulonglong2*)(sm + 16384);
    float*      hbufF = sm + 16384;
    float*      gb   = sm + 16384 + 256;

    const int bx = blockIdx.x, j = threadIdx.x;
    const bool is_audio = (bx < 64);
    const int blk = is_audio ? bx : (bx - 64);
    const float* Gsrc = is_audio ? g_Ga : g_Gv;
    const float* WTs  = is_audio ? g_WTa : g_WTv;
    const int zoff = is_audio ? 0 : 64;
    const int b0 = blk * 4;

    for (int i = j; i < 64 * 256; i += 256) Wc[i] = WTs[i];
    if (j < 64) { hb2[j].x = pack2(0.f, 0.f); hb2[j].y = pack2(0.f, 0.f); }
    __syncthreads();

    const int row = j >> 6, hj = j & 63;
    float c = 0.0f;

    for (int t = 0; t < TT; t++) {
        ull q0 = pack2(Gsrc[((size_t)((b0 + 0) * TT + t)) * 256 + j],
                       Gsrc[((size_t)((b0 + 1) * TT + t)) * 256 + j]);
        ull q1 = pack2(Gsrc[((size_t)((b0 + 2) * TT + t)) * 256 + j],
                       Gsrc[((size_t)((b0 + 3) * TT + t)) * 256 + j]);

#pragma unroll 8
        for (int k = 0; k < 64; k++) {
            float w = Wc[k * 256 + j];
            ull ww = pack2(w, w);
            ulonglong2 h = hb2[k];
            fma2(q0, ww, h.x);
            fma2(q1, ww, h.y);
        }
        float2 Q0 = unpack2(q0), Q1 = unpack2(q1);
        gb[0 * 256 + j] = Q0.x; gb[1 * 256 + j] = Q0.y;
        gb[2 * 256 + j] = Q1.x; gb[3 * 256 + j] = Q1.y;
        __syncthreads();

        const float* g = gb + row * 256;
        float gi = sigf(g[hj]),         gf = sigf(g[64 + hj]);
        float gg = tanhfa(g[128 + hj]), go = sigf(g[192 + hj]);
        c = gf * c + gi * gg;
        float h = go * tanhfa(c);
        hbufF[hj * 4 + row] = h;
        g_z[((size_t)((b0 + row) * TT + t)) * 256 + zoff + hj] = h;
        __syncthreads();
    }
}

// ---------------- fusion ----------------
#define FUSION_SMEM ((6144 + 12312 + 24 + 24 + 192 + 8) * 4)

__global__ __launch_bounds__(256, 1)
void fusion_kernel(const float* __restrict__ W1, const float* __restrict__ b1,
                   const float* __restrict__ W2, const float* __restrict__ b2)
{
    extern __shared__ float sm[];
    float* W1s   = sm;
    float* W2s   = sm + 6144;
    float* b1s   = W2s + 12312;
    float* bcs   = b1s + 24;
    float* Sred  = bcs + 24;
    float* ssred = Sred + 192;

    const int tid = threadIdx.x;
    const int b   = blockIdx.x;

    for (int i = tid; i < 6144;  i += 256) W1s[i] = W1[i];
    for (int i = tid; i < 12312; i += 256) W2s[i] = W2[i];
    if (tid < 24) b1s[tid] = b1[tid];
    __syncthreads();
    if (tid < 24) bcs[tid] = b2[tid] + W2s[tid * 513];
    __syncthreads();

    const int w = tid >> 5, l = tid & 31;
    float S[RANK];
#pragma unroll
    for (int r = 0; r < RANK; r++) S[r] = 0.0f;
    float ss = 0.0f;

    const float* zb = g_z + (size_t)b * TT * 256;

    for (int t0 = w * 32; t0 < w * 32 + 32; t0 += 2) {
        const int t1 = t0 + 1;
        const int t2 = (t0 + 2) & 255;
        float zc0[8], zc1[8], zc2[8];
#pragma unroll
        for (int q = 0; q < 8; q++) {
            zc0[q] = zb[t0 * 256 + l + 32 * q];
            zc1[q] = zb[t1 * 256 + l + 32 * q];
            zc2[q] = zb[t2 * 256 + l + 32 * q];
            ss += zc0[q] * zc0[q] + zc1[q] * zc1[q];
        }
#pragma unroll
        for (int r = 0; r < RANK; r++) {
            float a0 = 0.0f, bb0 = 0.0f, a1 = 0.0f, bb1 = 0.0f;
#pragma unroll
            for (int q = 0; q < 8; q++) {
                float w1v = W1s[r * 256 + l + 32 * q];
                float w2a = W2s[r * 513 + 1   + l + 32 * q];
                float w2b = W2s[r * 513 + 257 + l + 32 * q];
                a0  += w1v * zc0[q];
                bb0 += w2a * zc0[q] + w2b * zc1[q];
                a1  += w1v * zc1[q];
                bb1 += w2a * zc1[q] + w2b * zc2[q];
            }
#pragma unroll
            for (int o = 16; o; o >>= 1) {
                a0  += __shfl_xor_sync(0xffffffffu, a0,  o);
                bb0 += __shfl_xor_sync(0xffffffffu, bb0, o);
                a1  += __shfl_xor_sync(0xffffffffu, a1,  o);
                bb1 += __shfl_xor_sync(0xffffffffu, bb1, o);
            }
            S[r] += (a0 + b1s[r]) * (bb0 + bcs[r])
                  + (a1 + b1s[r]) * (bb1 + bcs[r]);
        }
    }

#pragma unroll
    for (int o = 16; o; o >>= 1) ss += __shfl_xor_sync(0xffffffffu, ss, o);
    if (l == 0) {
#pragma unroll
        for (int r = 0; r < RANK; r++) Sred[w * RANK + r] = S[r];
        ssred[w] = ss;
    }
    __syncthreads();
    if (tid < RANK) {
        float tot = 0.0f;
        for (int ww = 0; ww < 8; ww++) tot += Sred[ww * RANK + tid];
        g_S[b * RANK + tid] = tot;
    }
    if (tid == 32) {
        float tot = 0.0f;
        for (int ww = 0; ww < 8; ww++) tot += ssred[ww];
        g_ss[b] = tot;
    }
}

// ---------------- final ----------------
__global__ void final_kernel(const float* __restrict__ fw, float* __restrict__ out)
{
    const int tid = threadIdx.x;
    float s = 0.0f;
#pragma unroll
    for (int r = 0; r < RANK; r++) s += fw[r] * g_S[tid * RANK + r];
    out[tid] = s * (1.0f / (float)TT);

    __shared__ float red[256];
    red[tid] = sqrtf(g_ss[tid]);
    __syncthreads();
    for (int o = 128; o; o >>= 1) {
        if (tid < o) red[tid] += red[tid + o];
        __syncthreads();
    }
    if (tid == 0) out[256] = red[0] / (float)BB;
}

// ---------------- launch ----------------
extern "C" void kernel_launch(void* const* d_in, const int* in_sizes, int n_in,
                              void* d_out, int out_size)
{
    const float* text  = (const float*)d_in[0];
    const float* audio = (const float*)d_in[1];
    const float* vision= (const float*)d_in[2];
    const float* Wih_t = (const float*)d_in[3];
    const float* Whh_t = (const float*)d_in[4];
    const float* b_t   = (const float*)d_in[5];
    const float* Wih_a = (const float*)d_in[6];
    const float* Whh_a = (const float*)d_in[7];
    const float* b_a   = (const float*)d_in[8];
    const float* Wih_v = (const float*)d_in[9];
    const float* Whh_v = (const float*)d_in[10];
    const float* b_v   = (const float*)d_in[11];
    const float* W1    = (const float*)d_in[12];
    const float* b1    = (const float*)d_in[13];
    const float* W2    = (const float*)d_in[14];
    const float* b2    = (const float*)d_in[15];
    const float* fw    = (const float*)d_in[16];

    float *Gt, *Ga, *Gv;
    cudaGetSymbolAddress((void**)&Gt, g_Gt);
    cudaGetSymbolAddress((void**)&Ga, g_Ga);
    cudaGetSymbolAddress((void**)&Gv, g_Gv);
    __nv_bfloat16 *Athi, *Atlo, *Aahi, *Aalo, *Avhi, *Avlo;
    __nv_bfloat16 *Wthi, *Wtlo, *Wahi, *Walo, *Wvhi, *Wvlo;
    cudaGetSymbolAddress((void**)&Athi, g_Athi);
    cudaGetSymbolAddress((void**)&Atlo, g_Atlo);
    cudaGetSymbolAddress((void**)&Aahi, g_Aahi);
    cudaGetSymbolAddress((void**)&Aalo, g_Aalo);
    cudaGetSymbolAddress((void**)&Avhi, g_Avhi);
    cudaGetSymbolAddress((void**)&Avlo, g_Avlo);
    cudaGetSymbolAddress((void**)&Wthi, g_Wthi);
    cudaGetSymbolAddress((void**)&Wtlo, g_Wtlo);
    cudaGetSymbolAddress((void**)&Wahi, g_Wahi);
    cudaGetSymbolAddress((void**)&Walo, g_Walo);
    cudaGetSymbolAddress((void**)&Wvhi, g_Wvhi);
    cudaGetSymbolAddress((void**)&Wvlo, g_Wvlo);

    cudaFuncSetAttribute(gemm_bf16s,      cudaFuncAttributeMaxDynamicSharedMemorySize, 2 * GSTG);
    cudaFuncSetAttribute(lstm_text_kernel,cudaFuncAttributeMaxDynamicSharedMemorySize, TEXT_SMEM);
    cudaFuncSetAttribute(lstm_av_kernel,  cudaFuncAttributeMaxDynamicSharedMemorySize, AV_SMEM);
    cudaFuncSetAttribute(fusion_kernel,   cudaFuncAttributeMaxDynamicSharedMemorySize, FUSION_SMEM);

    // 1-3: conversions
    conv_split4<<<8192, 256>>>((const float4*)text,
                               (__nv_bfloat162*)Athi, (__nv_bfloat162*)Atlo,
                               (long)MM * KP_T / 4);
    conv_split4<<<384, 256>>>((const float4*)Wih_t,
                              (__nv_bfloat162*)Wthi, (__nv_bfloat162*)Wtlo,
                              (long)512 * KP_T / 4);
    conv_pad_all<<<4096, 256>>>(audio, Wih_a, vision, Wih_v);

    // 4: recurrent weight prep (before lstm_text)
    prep_kernel<<<256, 256>>>(Whh_t, Whh_a, Whh_v);

    // 5: text GEMM (grid: n fastest, m second)
    gemm_bf16s<<<dim3(4, MM / 128), 256, 2 * GSTG>>>(Athi, Atlo, Wthi, Wtlo, b_t, Gt, 512, KP_T);

    // 6: text recurrence  <-- profiled slot (ncu -s 5 -c 1)
    lstm_text_kernel<<<128, 256, TEXT_SMEM>>>();

    // 7-8: audio/vision GEMMs
    gemm_bf16s<<<dim3(2, MM / 128), 256, 2 * GSTG>>>(Aahi, Aalo, Wahi, Walo, b_a, Ga, 256, KP_A);
    gemm_bf16s<<<dim3(2, MM / 128), 256, 2 * GSTG>>>(Avhi, Avlo, Wvhi, Wvlo, b_v, Gv, 256, KP_V);

    // 9: audio/vision recurrences
    lstm_av_kernel<<<128, 256, AV_SMEM>>>();

    // 10-11: fusion + final
    fusion_kernel<<<BB, 256, FUSION_SMEM>>>(W1, b1, W2, b2);
    final_kernel<<<1, 256>>>(fw, (float*)d_out);
}

// round 11
// speedup vs baseline: 1.9571x; 1.1328x over previous
#include <cuda_runtime.h>
#include <cuda_bf16.h>
#include <math.h>
#include <stdint.h>

#define BB   256
#define TT   256
#define RANK 24
#define MM   (BB * TT)

#define KP_T 768
#define KP_A 96
#define KP_V 64

typedef unsigned long long ull;

// ---------------- scratch globals ----------------
__device__ float g_Gt[(size_t)MM * 512];
__device__ float g_Ga[(size_t)MM * 256];
__device__ float g_Gv[(size_t)MM * 256];
__device__ float g_z [(size_t)MM * 256];

__device__ __nv_bfloat16 g_Athi[(size_t)MM * KP_T];
__device__ __nv_bfloat16 g_Atlo[(size_t)MM * KP_T];
__device__ __nv_bfloat16 g_Aahi[(size_t)MM * KP_A];
__device__ __nv_bfloat16 g_Aalo[(size_t)MM * KP_A];
__device__ __nv_bfloat16 g_Avhi[(size_t)MM * KP_V];
__device__ __nv_bfloat16 g_Avlo[(size_t)MM * KP_V];
__device__ __nv_bfloat16 g_Wthi[512 * KP_T];
__device__ __nv_bfloat16 g_Wtlo[512 * KP_T];
__device__ __nv_bfloat16 g_Wahi[256 * KP_A];
__device__ __nv_bfloat16 g_Walo[256 * KP_A];
__device__ __nv_bfloat16 g_Wvhi[256 * KP_V];
__device__ __nv_bfloat16 g_Wvlo[256 * KP_V];

__device__ float g_WIt[128 * 512];   // Whh_t interleaved [k][2j+s]
__device__ float g_WTa[64 * 256];
__device__ float g_WTv[64 * 256];
__device__ float g_S [BB * RANK];
__device__ float g_ss[BB];

__device__ __forceinline__ float sigf(float x)  { return 1.0f / (1.0f + __expf(-x)); }
__device__ __forceinline__ float tanhfa(float x){ return 1.0f - 2.0f / (__expf(2.0f * x) + 1.0f); }

// packed fp32x2 helpers (exact fp32, 2 lanes/instr)
__device__ __forceinline__ void fma2(ull& d, ull a, ull b) {
    asm("fma.rn.f32x2 %0, %1, %2, %0;" : "+l"(d) : "l"(a), "l"(b));
}
__device__ __forceinline__ ull pack2(float x, float y) {
    ull r; asm("mov.b64 %0, {%1,%2};" : "=l"(r) : "f"(x), "f"(y)); return r;
}
__device__ __forceinline__ float2 unpack2(ull v) {
    float2 r; asm("mov.b64 {%0,%1}, %2;" : "=f"(r.x), "=f"(r.y) : "l"(v)); return r;
}

// ---------------- fused conversion kernel ----------------
__device__ __forceinline__ void split4(const float4* __restrict__ src,
                                       __nv_bfloat162* __restrict__ hi,
                                       __nv_bfloat162* __restrict__ lo, long i)
{
    float4 v = src[i];
    __nv_bfloat16 h0 = __float2bfloat16(v.x), h1 = __float2bfloat16(v.y);
    __nv_bfloat16 h2 = __float2bfloat16(v.z), h3 = __float2bfloat16(v.w);
    hi[2*i]   = __halves2bfloat162(h0, h1);
    hi[2*i+1] = __halves2bfloat162(h2, h3);
    lo[2*i]   = __halves2bfloat162(__float2bfloat16(v.x - __bfloat162float(h0)),
                                   __float2bfloat16(v.y - __bfloat162float(h1)));
    lo[2*i+1] = __halves2bfloat162(__float2bfloat16(v.z - __bfloat162float(h2)),
                                   __float2bfloat16(v.w - __bfloat162float(h3)));
}

__device__ __forceinline__ void conv_one(const float* __restrict__ src,
                                         __nv_bfloat16* __restrict__ hi,
                                         __nv_bfloat16* __restrict__ lo,
                                         long i, int K, int Kp)
{
    int m = (int)(i / Kp), k = (int)(i % Kp);
    float v = (k < K) ? src[(size_t)m * K + k] : 0.0f;
    __nv_bfloat16 h = __float2bfloat16(v);
    hi[i] = h;
    lo[i] = __float2bfloat16(v - __bfloat162float(h));
}

#define CT0 ((long)MM * KP_T / 4)          // text float4 units
#define CT1 ((long)512 * KP_T / 4)         // Wih_t float4 units
#define CR0 ((long)MM * KP_A)
#define CR1 ((long)256 * KP_A)
#define CR2 ((long)MM * KP_V)
#define CR3 ((long)256 * KP_V)

__global__ void conv_all(const float* __restrict__ text, const float* __restrict__ Wt,
                         const float* __restrict__ audio, const float* __restrict__ Wa,
                         const float* __restrict__ vision, const float* __restrict__ Wv)
{
    const long total = CT0 + CT1 + CR0 + CR1 + CR2 + CR3;
    for (long i = (long)blockIdx.x * blockDim.x + threadIdx.x; i < total;
         i += (long)gridDim.x * blockDim.x) {
        long x = i;
        if (x < CT0) { split4((const float4*)text, (__nv_bfloat162*)g_Athi, (__nv_bfloat162*)g_Atlo, x); continue; }
        x -= CT0;
        if (x < CT1) { split4((const float4*)Wt, (__nv_bfloat162*)g_Wthi, (__nv_bfloat162*)g_Wtlo, x); continue; }
        x -= CT1;
        if (x < CR0) { conv_one(audio,  g_Aahi, g_Aalo, x, 74, KP_A); continue; }
        x -= CR0;
        if (x < CR1) { conv_one(Wa,     g_Wahi, g_Walo, x, 74, KP_A); continue; }
        x -= CR1;
        if (x < CR2) { conv_one(vision, g_Avhi, g_Avlo, x, 35, KP_V); continue; }
        x -= CR2;
        conv_one(Wv, g_Wvhi, g_Wvlo, x, 35, KP_V);
    }
}

// ---------------- tensor-core GEMM (mma.sync): C = A * W^T + bias ----------------
#define GARR 10240
#define GSTG 40960

__device__ __forceinline__ void cp16(unsigned dst, const void* src) {
    asm volatile("cp.async.cg.shared.global [%0], [%1], 16;\n" :: "r"(dst), "l"(src));
}
__device__ __forceinline__ unsigned ld4(const char* base, int r, int e) {
    return *(const unsigned*)(base + r * 80 + e * 2);
}
__device__ __forceinline__ void mma16816(float* d, const unsigned* a, const unsigned* b) {
    asm volatile(
        "mma.sync.aligned.m16n8k16.row.col.f32.bf16.bf16.f32 "
        "{%0,%1,%2,%3}, {%4,%5,%6,%7}, {%8,%9}, {%0,%1,%2,%3};"
        : "+f"(d[0]), "+f"(d[1]), "+f"(d[2]), "+f"(d[3])
        : "r"(a[0]), "r"(a[1]), "r"(a[2]), "r"(a[3]), "r"(b[0]), "r"(b[1]));
}

__global__ __launch_bounds__(256, 2)
void gemm_bf16s(const __nv_bfloat16* __restrict__ Ahi, const __nv_bfloat16* __restrict__ Alo,
                const __nv_bfloat16* __restrict__ Bhi, const __nv_bfloat16* __restrict__ Blo,
                const float* __restrict__ bias, float* __restrict__ C, int N, int Kp)
{
    extern __shared__ char gsm[];
    const int tid = threadIdx.x;
    const size_t n0 = (size_t)blockIdx.x * 128;   // n fastest -> A shared in L2
    const size_t m0 = (size_t)blockIdx.y * 128;
    const unsigned us = (unsigned)__cvta_generic_to_shared(gsm);
    const int NK = Kp >> 5;

    const __nv_bfloat16* gsrc[4] = {Ahi + m0 * Kp, Alo + m0 * Kp,
                                    Bhi + n0 * Kp, Blo + n0 * Kp};

    auto load_chunk = [&](int kc, int stg) {
        unsigned base = us + stg * GSTG;
#pragma unroll
        for (int arr = 0; arr < 4; arr++) {
#pragma unroll
            for (int i = 0; i < 2; i++) {
                int u = tid + 256 * i;
                int row = u >> 2, seg = u & 3;
                unsigned dst = base + arr * GARR + row * 80 + seg * 16;
                cp16(dst, gsrc[arr] + (size_t)row * Kp + kc * 32 + seg * 8);
            }
        }
        asm volatile("cp.async.commit_group;" ::: "memory");
    };

    const int warp = tid >> 5, wm = warp >> 1, wn = warp & 1;
    const int lane = tid & 31, grp = lane >> 2, q = lane & 3;

    float acc[2][8][4];
#pragma unroll
    for (int mt = 0; mt < 2; mt++)
#pragma unroll
        for (int nt = 0; nt < 8; nt++)
#pragma unroll
            for (int i = 0; i < 4; i++) acc[mt][nt][i] = 0.0f;

    load_chunk(0, 0);

    for (int kc = 0; kc < NK; kc++) {
        if (kc + 1 < NK) load_chunk(kc + 1, (kc + 1) & 1);
        else             asm volatile("cp.async.commit_group;" ::: "memory");
        asm volatile("cp.async.wait_group 1;" ::: "memory");
        __syncthreads();

        const char* st  = gsm + (kc & 1) * GSTG;
        const char* sAh = st;
        const char* sAl = st + GARR;
        const char* sBh = st + 2 * GARR;
        const char* sBl = st + 3 * GARR;

#pragma unroll
        for (int kk = 0; kk < 32; kk += 16) {
            unsigned bh[8][2], af[2][4], al[2][4];
#pragma unroll
            for (int nt = 0; nt < 8; nt++) {
                int nr = wn * 64 + nt * 8 + grp;
                bh[nt][0] = ld4(sBh, nr, kk + 2 * q);
                bh[nt][1] = ld4(sBh, nr, kk + 2 * q + 8);
            }
#pragma unroll
            for (int mt = 0; mt < 2; mt++) {
                int r = wm * 32 + mt * 16 + grp;
                af[mt][0] = ld4(sAh, r,     kk + 2 * q);
                af[mt][1] = ld4(sAh, r + 8, kk + 2 * q);
                af[mt][2] = ld4(sAh, r,     kk + 2 * q + 8);
                af[mt][3] = ld4(sAh, r + 8, kk + 2 * q + 8);
                al[mt][0] = ld4(sAl, r,     kk + 2 * q);
                al[mt][1] = ld4(sAl, r + 8, kk + 2 * q);
                al[mt][2] = ld4(sAl, r,     kk + 2 * q + 8);
                al[mt][3] = ld4(sAl, r + 8, kk + 2 * q + 8);
            }
#pragma unroll
            for (int mt = 0; mt < 2; mt++)
#pragma unroll
                for (int nt = 0; nt < 8; nt++) {
                    mma16816(acc[mt][nt], af[mt], bh[nt]);
                    mma16816(acc[mt][nt], al[mt], bh[nt]);
                }
#pragma unroll
            for (int nt = 0; nt < 8; nt++) {
                int nr = wn * 64 + nt * 8 + grp;
                bh[nt][0] = ld4(sBl, nr, kk + 2 * q);
                bh[nt][1] = ld4(sBl, nr, kk + 2 * q + 8);
            }
#pragma unroll
            for (int mt = 0; mt < 2; mt++)
#pragma unroll
                for (int nt = 0; nt < 8; nt++)
                    mma16816(acc[mt][nt], af[mt], bh[nt]);
        }
        __syncthreads();
    }

#pragma unroll
    for (int mt = 0; mt < 2; mt++) {
        size_t r = m0 + wm * 32 + mt * 16 + grp;
#pragma unroll
        for (int nt = 0; nt < 8; nt++) {
            size_t cb = n0 + wn * 64 + nt * 8 + 2 * q;
            float b0v = bias[cb], b1v = bias[cb + 1];
            *(float2*)&C[r * N + cb]       = make_float2(acc[mt][nt][0] + b0v, acc[mt][nt][1] + b1v);
            *(float2*)&C[(r + 8) * N + cb] = make_float2(acc[mt][nt][2] + b0v, acc[mt][nt][3] + b1v);
        }
    }
}

// ---------------- prep recurrent weights ----------------
__global__ void prep_kernel(const float* __restrict__ Wt,
                            const float* __restrict__ Wa,
                            const float* __restrict__ Wv)
{
    int i = blockIdx.x * 256 + threadIdx.x;
    if (i < 512 * 128) {
        int n = i / 128, k = i % 128;
        int j = (n < 256) ? n : (n - 256);
        int s = (n < 256) ? 0 : 1;
        g_WIt[k * 512 + 2 * j + s] = Wt[i];
    }
    if (i < 256 * 64) {
        int n = i / 64, k = i % 64;
        g_WTa[k * 256 + n] = Wa[i];
        g_WTv[k * 256 + n] = Wv[i];
    }
}

// ---------------- LSTM text: 128 CTAs, 2 batch rows each ----------------
// W panels 0..KCS-1 in smem (packed pairs), KCS..127 in registers.
// G loads issued at iteration top, consumed AFTER the k-loop (latency hidden).
#define KCS 64
#define TEXT_SMEM ((KCS * 512 + 512 + 512) * 4)

__global__ __launch_bounds__(256, 1)
void lstm_text_kernel()
{
    extern __shared__ float sm[];
    ull*        Wc8  = (ull*)sm;
    ulonglong2* hdup = (ulonglong2*)(sm + KCS * 512);
    float*      exf0 = sm + KCS * 512 + 512;
    float*      exf1 = exf0 + 128;
    float*      exo0 = exf1 + 128;
    float*      exo1 = exo0 + 128;

    const int bx = blockIdx.x, j = threadIdx.x;
    const int b0 = bx * 2, b1 = b0 + 1;
    const ull* WI8 = (const ull*)g_WIt;

    for (int i = j; i < KCS * 256; i += 256) Wc8[i] = WI8[i];
    ull wreg[128 - KCS];
#pragma unroll
    for (int kk = 0; kk < 128 - KCS; kk++) wreg[kk] = WI8[(KCS + kk) * 256 + j];
    if (j < 128) { hdup[j].x = pack2(0.f, 0.f); hdup[j].y = pack2(0.f, 0.f); }
    __syncthreads();

    float c0 = 0.0f, c1 = 0.0f;

    for (int t = 0; t < TT; t++) {
        const float* Gb0 = g_Gt + ((size_t)(b0 * TT + t)) * 512;
        const float* Gb1 = g_Gt + ((size_t)(b1 * TT + t)) * 512;
        // issue G loads now; consumed only after the k-loop
        float ga0 = __ldg(&Gb0[j]), ga1 = __ldg(&Gb0[j + 256]);
        float gb0v = __ldg(&Gb1[j]), gb1v = __ldg(&Gb1[j + 256]);

        ull p0 = pack2(0.f, 0.f);
        ull p1 = pack2(0.f, 0.f);

#pragma unroll 8
        for (int k = 0; k < KCS; k++) {
            ull w = Wc8[k * 256 + j];
            ulonglong2 h = hdup[k];
            fma2(p0, w, h.x);
            fma2(p1, w, h.y);
        }
#pragma unroll
        for (int kk = 0; kk < 128 - KCS; kk++) {
            ulonglong2 h = hdup[KCS + kk];
            fma2(p0, wreg[kk], h.x);
            fma2(p1, wreg[kk], h.y);
        }
        float2 A0 = unpack2(p0);
        float2 A1 = unpack2(p1);
        A0.x += ga0;  A0.y += ga1;
        A1.x += gb0v; A1.y += gb1v;

        if (j >= 128) {
            int jj = j - 128;
            exf0[jj] = sigf(A0.x); exf1[jj] = sigf(A1.x);
            exo0[jj] = A0.y;       exo1[jj] = A1.y;
        }
        __syncthreads();
        if (j < 128) {
            c0 = exf0[j] * c0 + sigf(A0.x) * tanhfa(A0.y);
            c1 = exf1[j] * c1 + sigf(A1.x) * tanhfa(A1.y);
            float h0 = sigf(exo0[j]) * tanhfa(c0);
            float h1 = sigf(exo1[j]) * tanhfa(c1);
            hdup[j].x = pack2(h0, h0);
            hdup[j].y = pack2(h1, h1);
            g_z[((size_t)(b0 * TT + t)) * 256 + 128 + j] = h0;
            g_z[((size_t)(b1 * TT + t)) * 256 + 128 + j] = h1;
        }
        __syncthreads();
    }
}

// ---------------- LSTM audio+vision: 128 CTAs, 4 batch rows each ----------------
#define AV_SMEM ((64 * 256 + 256 + 1024) * 4)

__global__ __launch_bounds__(256, 1)
void lstm_av_kernel()
{
    extern __shared__ float sm[];
    float*      Wc   = sm;
    ulonglong2* hb2  = (ulonglong2*)(sm + 16384);
    float*      hbufF = sm + 16384;
    float*      gb   = sm + 16384 + 256;

    const int bx = blockIdx.x, j = threadIdx.x;
    const bool is_audio = (bx < 64);
    const int blk = is_audio ? bx : (bx - 64);
    const float* Gsrc = is_audio ? g_Ga : g_Gv;
    const float* WTs  = is_audio ? g_WTa : g_WTv;
    const int zoff = is_audio ? 0 : 64;
    const int b0 = blk * 4;

    for (int i = j; i < 64 * 256; i += 256) Wc[i] = WTs[i];
    if (j < 64) { hb2[j].x = pack2(0.f, 0.f); hb2[j].y = pack2(0.f, 0.f); }
    __syncthreads();

    const int row = j >> 6, hj = j & 63;
    float c = 0.0f;

    for (int t = 0; t < TT; t++) {
        // issue G loads now; consumed after the k-loop
        float a0 = __ldg(&Gsrc[((size_t)((b0 + 0) * TT + t)) * 256 + j]);
        float a1 = __ldg(&Gsrc[((size_t)((b0 + 1) * TT + t)) * 256 + j]);
        float a2 = __ldg(&Gsrc[((size_t)((b0 + 2) * TT + t)) * 256 + j]);
        float a3 = __ldg(&Gsrc[((size_t)((b0 + 3) * TT + t)) * 256 + j]);

        ull q0 = pack2(0.f, 0.f);
        ull q1 = pack2(0.f, 0.f);

#pragma unroll 8
        for (int k = 0; k < 64; k++) {
            float w = Wc[k * 256 + j];
            ull ww = pack2(w, w);
            ulonglong2 h = hb2[k];
            fma2(q0, ww, h.x);
            fma2(q1, ww, h.y);
        }
        float2 Q0 = unpack2(q0), Q1 = unpack2(q1);
        gb[0 * 256 + j] = Q0.x + a0; gb[1 * 256 + j] = Q0.y + a1;
        gb[2 * 256 + j] = Q1.x + a2; gb[3 * 256 + j] = Q1.y + a3;
        __syncthreads();

        const float* g = gb + row * 256;
        float gi = sigf(g[hj]),         gf = sigf(g[64 + hj]);
        float gg = tanhfa(g[128 + hj]), go = sigf(g[192 + hj]);
        c = gf * c + gi * gg;
        float h = go * tanhfa(c);
        hbufF[hj * 4 + row] = h;
        g_z[((size_t)((b0 + row) * TT + t)) * 256 + zoff + hj] = h;
        __syncthreads();
    }
}

// ---------------- fusion ----------------
#define FUSION_SMEM ((6144 + 12312 + 24 + 24 + 192 + 8) * 4)

__global__ __launch_bounds__(256, 1)
void fusion_kernel(const float* __restrict__ W1, const float* __restrict__ b1,
                   const float* __restrict__ W2, const float* __restrict__ b2)
{
    extern __shared__ float sm[];
    float* W1s   = sm;
    float* W2s   = sm + 6144;
    float* b1s   = W2s + 12312;
    float* bcs   = b1s + 24;
    float* Sred  = bcs + 24;
    float* ssred = Sred + 192;

    const int tid = threadIdx.x;
    const int b   = blockIdx.x;

    for (int i = tid; i < 6144;  i += 256) W1s[i] = W1[i];
    for (int i = tid; i < 12312; i += 256) W2s[i] = W2[i];
    if (tid < 24) b1s[tid] = b1[tid];
    __syncthreads();
    if (tid < 24) bcs[tid] = b2[tid] + W2s[tid * 513];
    __syncthreads();

    const int w = tid >> 5, l = tid & 31;
    float S[RANK];
#pragma unroll
    for (int r = 0; r < RANK; r++) S[r] = 0.0f;
    float ss = 0.0f;

    const float* zb = g_z + (size_t)b * TT * 256;

    for (int t0 = w * 32; t0 < w * 32 + 32; t0 += 2) {
        const int t1 = t0 + 1;
        const int t2 = (t0 + 2) & 255;
        float zc0[8], zc1[8], zc2[8];
#pragma unroll
        for (int q = 0; q < 8; q++) {
            zc0[q] = zb[t0 * 256 + l + 32 * q];
            zc1[q] = zb[t1 * 256 + l + 32 * q];
            zc2[q] = zb[t2 * 256 + l + 32 * q];
            ss += zc0[q] * zc0[q] + zc1[q] * zc1[q];
        }
#pragma unroll
        for (int r = 0; r < RANK; r++) {
            float a0 = 0.0f, bb0 = 0.0f, a1 = 0.0f, bb1 = 0.0f;
#pragma unroll
            for (int q = 0; q < 8; q++) {
                float w1v = W1s[r * 256 + l + 32 * q];
                float w2a = W2s[r * 513 + 1   + l + 32 * q];
                float w2b = W2s[r * 513 + 257 + l + 32 * q];
                a0  += w1v * zc0[q];
                bb0 += w2a * zc0[q] + w2b * zc1[q];
                a1  += w1v * zc1[q];
                bb1 += w2a * zc1[q] + w2b * zc2[q];
            }
#pragma unroll
            for (int o = 16; o; o >>= 1) {
                a0  += __shfl_xor_sync(0xffffffffu, a0,  o);
                bb0 += __shfl_xor_sync(0xffffffffu, bb0, o);
                a1  += __shfl_xor_sync(0xffffffffu, a1,  o);
                bb1 += __shfl_xor_sync(0xffffffffu, bb1, o);
            }
            S[r] += (a0 + b1s[r]) * (bb0 + bcs[r])
                  + (a1 + b1s[r]) * (bb1 + bcs[r]);
        }
    }

#pragma unroll
    for (int o = 16; o; o >>= 1) ss += __shfl_xor_sync(0xffffffffu, ss, o);
    if (l == 0) {
#pragma unroll
        for (int r = 0; r < RANK; r++) Sred[w * RANK + r] = S[r];
        ssred[w] = ss;
    }
    __syncthreads();
    if (tid < RANK) {
        float tot = 0.0f;
        for (int ww = 0; ww < 8; ww++) tot += Sred[ww * RANK + tid];
        g_S[b * RANK + tid] = tot;
    }
    if (tid == 32) {
        float tot = 0.0f;
        for (int ww = 0; ww < 8; ww++) tot += ssred[ww];
        g_ss[b] = tot;
    }
}

// ---------------- final ----------------
__global__ void final_kernel(const float* __restrict__ fw, float* __restrict__ out)
{
    const int tid = threadIdx.x;
    float s = 0.0f;
#pragma unroll
    for (int r = 0; r < RANK; r++) s += fw[r] * g_S[tid * RANK + r];
    out[tid] = s * (1.0f / (float)TT);

    __shared__ float red[256];
    red[tid] = sqrtf(g_ss[tid]);
    __syncthreads();
    for (int o = 128; o; o >>= 1) {
        if (tid < o) red[tid] += red[tid + o];
        __syncthreads();
    }
    if (tid == 0) out[256] = red[0] / (float)BB;
}

// ---------------- launch ----------------
extern "C" void kernel_launch(void* const* d_in, const int* in_sizes, int n_in,
                              void* d_out, int out_size)
{
    const float* text  = (const float*)d_in[0];
    const float* audio = (const float*)d_in[1];
    const float* vision= (const float*)d_in[2];
    const float* Wih_t = (const float*)d_in[3];
    const float* Whh_t = (const float*)d_in[4];
    const float* b_t   = (const float*)d_in[5];
    const float* Wih_a = (const float*)d_in[6];
    const float* Whh_a = (const float*)d_in[7];
    const float* b_a   = (const float*)d_in[8];
    const float* Wih_v = (const float*)d_in[9];
    const float* Whh_v = (const float*)d_in[10];
    const float* b_v   = (const float*)d_in[11];
    const float* W1    = (const float*)d_in[12];
    const float* b1    = (const float*)d_in[13];
    const float* W2    = (const float*)d_in[14];
    const float* b2    = (const float*)d_in[15];
    const float* fw    = (const float*)d_in[16];

    float *Gt, *Ga, *Gv;
    cudaGetSymbolAddress((void**)&Gt, g_Gt);
    cudaGetSymbolAddress((void**)&Ga, g_Ga);
    cudaGetSymbolAddress((void**)&Gv, g_Gv);
    __nv_bfloat16 *Athi, *Atlo, *Aahi, *Aalo, *Avhi, *Avlo;
    __nv_bfloat16 *Wthi, *Wtlo, *Wahi, *Walo, *Wvhi, *Wvlo;
    cudaGetSymbolAddress((void**)&Athi, g_Athi);
    cudaGetSymbolAddress((void**)&Atlo, g_Atlo);
    cudaGetSymbolAddress((void**)&Aahi, g_Aahi);
    cudaGetSymbolAddress((void**)&Aalo, g_Aalo);
    cudaGetSymbolAddress((void**)&Avhi, g_Avhi);
    cudaGetSymbolAddress((void**)&Avlo, g_Avlo);
    cudaGetSymbolAddress((void**)&Wthi, g_Wthi);
    cudaGetSymbolAddress((void**)&Wtlo, g_Wtlo);
    cudaGetSymbolAddress((void**)&Wahi, g_Wahi);
    cudaGetSymbolAddress((void**)&Walo, g_Walo);
    cudaGetSymbolAddress((void**)&Wvhi, g_Wvhi);
    cudaGetSymbolAddress((void**)&Wvlo, g_Wvlo);

    cudaFuncSetAttribute(gemm_bf16s,      cudaFuncAttributeMaxDynamicSharedMemorySize, 2 * GSTG);
    cudaFuncSetAttribute(lstm_text_kernel,cudaFuncAttributeMaxDynamicSharedMemorySize, TEXT_SMEM);
    cudaFuncSetAttribute(lstm_av_kernel,  cudaFuncAttributeMaxDynamicSharedMemorySize, AV_SMEM);
    cudaFuncSetAttribute(fusion_kernel,   cudaFuncAttributeMaxDynamicSharedMemorySize, FUSION_SMEM);

    // 1: all conversions fused
    conv_all<<<8192, 256>>>(text, Wih_t, audio, Wih_a, vision, Wih_v);

    // 2: recurrent weight prep
    prep_kernel<<<256, 256>>>(Whh_t, Whh_a, Whh_v);

    // 3: text GEMM
    gemm_bf16s<<<dim3(4, MM / 128), 256, 2 * GSTG>>>(Athi, Atlo, Wthi, Wtlo, b_t, Gt, 512, KP_T);

    // 4: text recurrence  <-- profiled slot (launch #4)
    lstm_text_kernel<<<128, 256, TEXT_SMEM>>>();

    // 5-6: audio/vision GEMMs
    gemm_bf16s<<<dim3(2, MM / 128), 256, 2 * GSTG>>>(Aahi, Aalo, Wahi, Walo, b_a, Ga, 256, KP_A);
    gemm_bf16s<<<dim3(2, MM / 128), 256, 2 * GSTG>>>(Avhi, Avlo, Wvhi, Wvlo, b_v, Gv, 256, KP_V);

    // 7: audio/vision recurrences
    lstm_av_kernel<<<128, 256, AV_SMEM>>>();

    // 8-9: fusion + final
    fusion_kernel<<<BB, 256, FUSION_SMEM>>>(W1, b1, W2, b2);
    final_kernel<<<1, 256>>>(fw, (float*)d_out);
}

// round 16
// speedup vs baseline: 1.9688x; 1.0060x over previous
#include <cuda_runtime.h>
#include <cuda_bf16.h>
#include <math.h>
#include <stdint.h>

#define BB   256
#define TT   256
#define RANK 24
#define MM   (BB * TT)

#define KP_T 768
#define KP_A 96
#define KP_V 64

typedef unsigned long long ull;

// ---------------- scratch globals ----------------
__device__ float g_Gt[(size_t)MM * 512];
__device__ float g_Ga[(size_t)MM * 256];
__device__ float g_Gv[(size_t)MM * 256];
__device__ float g_z [(size_t)MM * 256];

__device__ __nv_bfloat16 g_Athi[(size_t)MM * KP_T];
__device__ __nv_bfloat16 g_Atlo[(size_t)MM * KP_T];
__device__ __nv_bfloat16 g_Aahi[(size_t)MM * KP_A];
__device__ __nv_bfloat16 g_Aalo[(size_t)MM * KP_A];
__device__ __nv_bfloat16 g_Avhi[(size_t)MM * KP_V];
__device__ __nv_bfloat16 g_Avlo[(size_t)MM * KP_V];
__device__ __nv_bfloat16 g_Wthi[512 * KP_T];
__device__ __nv_bfloat16 g_Wtlo[512 * KP_T];
__device__ __nv_bfloat16 g_Wahi[256 * KP_A];
__device__ __nv_bfloat16 g_Walo[256 * KP_A];
__device__ __nv_bfloat16 g_Wvhi[256 * KP_V];
__device__ __nv_bfloat16 g_Wvlo[256 * KP_V];

// text Whh paired layout: float index ((k>>1)*256 + j)*4 + (k&1)*2 + s
// where j = unit col (0..255 pair id), s=0 -> col j, s=1 -> col j+256.
// One ulonglong2 = two consecutive k-panels' (w_j, w_j+256) packs.
__device__ float g_WP [128 * 512];
__device__ float g_WTa[64 * 256];
__device__ float g_WTv[64 * 256];
__device__ float g_S [BB * RANK];
__device__ float g_ss[BB];

__device__ __forceinline__ float sigf(float x)  { return 1.0f / (1.0f + __expf(-x)); }
__device__ __forceinline__ float tanhfa(float x){ return 1.0f - 2.0f / (__expf(2.0f * x) + 1.0f); }

__device__ __forceinline__ void fma2(ull& d, ull a, ull b) {
    asm("fma.rn.f32x2 %0, %1, %2, %0;" : "+l"(d) : "l"(a), "l"(b));
}
__device__ __forceinline__ ull pack2(float x, float y) {
    ull r; asm("mov.b64 %0, {%1,%2};" : "=l"(r) : "f"(x), "f"(y)); return r;
}
__device__ __forceinline__ float2 unpack2(ull v) {
    float2 r; asm("mov.b64 {%0,%1}, %2;" : "=f"(r.x), "=f"(r.y) : "l"(v)); return r;
}

// ---------------- fused conversion kernel ----------------
__device__ __forceinline__ void split4(const float4* __restrict__ src,
                                       __nv_bfloat162* __restrict__ hi,
                                       __nv_bfloat162* __restrict__ lo, long i)
{
    float4 v = src[i];
    __nv_bfloat16 h0 = __float2bfloat16(v.x), h1 = __float2bfloat16(v.y);
    __nv_bfloat16 h2 = __float2bfloat16(v.z), h3 = __float2bfloat16(v.w);
    hi[2*i]   = __halves2bfloat162(h0, h1);
    hi[2*i+1] = __halves2bfloat162(h2, h3);
    lo[2*i]   = __halves2bfloat162(__float2bfloat16(v.x - __bfloat162float(h0)),
                                   __float2bfloat16(v.y - __bfloat162float(h1)));
    lo[2*i+1] = __halves2bfloat162(__float2bfloat16(v.z - __bfloat162float(h2)),
                                   __float2bfloat16(v.w - __bfloat162float(h3)));
}

__device__ __forceinline__ void conv_one(const float* __restrict__ src,
                                         __nv_bfloat16* __restrict__ hi,
                                         __nv_bfloat16* __restrict__ lo,
                                         long i, int K, int Kp)
{
    int m = (int)(i / Kp), k = (int)(i % Kp);
    float v = (k < K) ? src[(size_t)m * K + k] : 0.0f;
    __nv_bfloat16 h = __float2bfloat16(v);
    hi[i] = h;
    lo[i] = __float2bfloat16(v - __bfloat162float(h));
}

#define CT0 ((long)MM * KP_T / 4)
#define CT1 ((long)512 * KP_T / 4)
#define CR0 ((long)MM * KP_A)
#define CR1 ((long)256 * KP_A)
#define CR2 ((long)MM * KP_V)
#define CR3 ((long)256 * KP_V)

__global__ void conv_all(const float* __restrict__ text, const float* __restrict__ Wt,
                         const float* __restrict__ audio, const float* __restrict__ Wa,
                         const float* __restrict__ vision, const float* __restrict__ Wv)
{
    const long total = CT0 + CT1 + CR0 + CR1 + CR2 + CR3;
    for (long i = (long)blockIdx.x * blockDim.x + threadIdx.x; i < total;
         i += (long)gridDim.x * blockDim.x) {
        long x = i;
        if (x < CT0) { split4((const float4*)text, (__nv_bfloat162*)g_Athi, (__nv_bfloat162*)g_Atlo, x); continue; }
        x -= CT0;
        if (x < CT1) { split4((const float4*)Wt, (__nv_bfloat162*)g_Wthi, (__nv_bfloat162*)g_Wtlo, x); continue; }
        x -= CT1;
        if (x < CR0) { conv_one(audio,  g_Aahi, g_Aalo, x, 74, KP_A); continue; }
        x -= CR0;
        if (x < CR1) { conv_one(Wa,     g_Wahi, g_Walo, x, 74, KP_A); continue; }
        x -= CR1;
        if (x < CR2) { conv_one(vision, g_Avhi, g_Avlo, x, 35, KP_V); continue; }
        x -= CR2;
        conv_one(Wv, g_Wvhi, g_Wvlo, x, 35, KP_V);
    }
}

// ---------------- tensor-core GEMM (mma.sync): C = A * W^T + bias ----------------
#define GARR 10240
#define GSTG 40960

__device__ __forceinline__ void cp16(unsigned dst, const void* src) {
    asm volatile("cp.async.cg.shared.global [%0], [%1], 16;\n" :: "r"(dst), "l"(src));
}
__device__ __forceinline__ unsigned ld4(const char* base, int r, int e) {
    return *(const unsigned*)(base + r * 80 + e * 2);
}
__device__ __forceinline__ void mma16816(float* d, const unsigned* a, const unsigned* b) {
    asm volatile(
        "mma.sync.aligned.m16n8k16.row.col.f32.bf16.bf16.f32 "
        "{%0,%1,%2,%3}, {%4,%5,%6,%7}, {%8,%9}, {%0,%1,%2,%3};"
        : "+f"(d[0]), "+f"(d[1]), "+f"(d[2]), "+f"(d[3])
        : "r"(a[0]), "r"(a[1]), "r"(a[2]), "r"(a[3]), "r"(b[0]), "r"(b[1]));
}

__global__ __launch_bounds__(256, 2)
void gemm_bf16s(const __nv_bfloat16* __restrict__ Ahi, const __nv_bfloat16* __restrict__ Alo,
                const __nv_bfloat16* __restrict__ Bhi, const __nv_bfloat16* __restrict__ Blo,
                const float* __restrict__ bias, float* __restrict__ C, int N, int Kp)
{
    extern __shared__ char gsm[];
    const int tid = threadIdx.x;
    const size_t n0 = (size_t)blockIdx.x * 128;   // n fastest -> A shared in L2
    const size_t m0 = (size_t)blockIdx.y * 128;
    const unsigned us = (unsigned)__cvta_generic_to_shared(gsm);
    const int NK = Kp >> 5;

    const __nv_bfloat16* gsrc[4] = {Ahi + m0 * Kp, Alo + m0 * Kp,
                                    Bhi + n0 * Kp, Blo + n0 * Kp};

    auto load_chunk = [&](int kc, int stg) {
        unsigned base = us + stg * GSTG;
#pragma unroll
        for (int arr = 0; arr < 4; arr++) {
#pragma unroll
            for (int i = 0; i < 2; i++) {
                int u = tid + 256 * i;
                int row = u >> 2, seg = u & 3;
                unsigned dst = base + arr * GARR + row * 80 + seg * 16;
                cp16(dst, gsrc[arr] + (size_t)row * Kp + kc * 32 + seg * 8);
            }
        }
        asm volatile("cp.async.commit_group;" ::: "memory");
    };

    const int warp = tid >> 5, wm = warp >> 1, wn = warp & 1;
    const int lane = tid & 31, grp = lane >> 2, q = lane & 3;

    float acc[2][8][4];
#pragma unroll
    for (int mt = 0; mt < 2; mt++)
#pragma unroll
        for (int nt = 0; nt < 8; nt++)
#pragma unroll
            for (int i = 0; i < 4; i++) acc[mt][nt][i] = 0.0f;

    load_chunk(0, 0);

    for (int kc = 0; kc < NK; kc++) {
        if (kc + 1 < NK) load_chunk(kc + 1, (kc + 1) & 1);
        else             asm volatile("cp.async.commit_group;" ::: "memory");
        asm volatile("cp.async.wait_group 1;" ::: "memory");
        __syncthreads();

        const char* st  = gsm + (kc & 1) * GSTG;
        const char* sAh = st;
        const char* sAl = st + GARR;
        const char* sBh = st + 2 * GARR;
        const char* sBl = st + 3 * GARR;

#pragma unroll
        for (int kk = 0; kk < 32; kk += 16) {
            unsigned bh[8][2], af[2][4], al[2][4];
#pragma unroll
            for (int nt = 0; nt < 8; nt++) {
                int nr = wn * 64 + nt * 8 + grp;
                bh[nt][0] = ld4(sBh, nr, kk + 2 * q);
                bh[nt][1] = ld4(sBh, nr, kk + 2 * q + 8);
            }
#pragma unroll
            for (int mt = 0; mt < 2; mt++) {
                int r = wm * 32 + mt * 16 + grp;
                af[mt][0] = ld4(sAh, r,     kk + 2 * q);
                af[mt][1] = ld4(sAh, r + 8, kk + 2 * q);
                af[mt][2] = ld4(sAh, r,     kk + 2 * q + 8);
                af[mt][3] = ld4(sAh, r + 8, kk + 2 * q + 8);
                al[mt][0] = ld4(sAl, r,     kk + 2 * q);
                al[mt][1] = ld4(sAl, r + 8, kk + 2 * q);
                al[mt][2] = ld4(sAl, r,     kk + 2 * q + 8);
                al[mt][3] = ld4(sAl, r + 8, kk + 2 * q + 8);
            }
#pragma unroll
            for (int mt = 0; mt < 2; mt++)
#pragma unroll
                for (int nt = 0; nt < 8; nt++) {
                    mma16816(acc[mt][nt], af[mt], bh[nt]);
                    mma16816(acc[mt][nt], al[mt], bh[nt]);
                }
#pragma unroll
            for (int nt = 0; nt < 8; nt++) {
                int nr = wn * 64 + nt * 8 + grp;
                bh[nt][0] = ld4(sBl, nr, kk + 2 * q);
                bh[nt][1] = ld4(sBl, nr, kk + 2 * q + 8);
            }
#pragma unroll
            for (int mt = 0; mt < 2; mt++)
#pragma unroll
                for (int nt = 0; nt < 8; nt++)
                    mma16816(acc[mt][nt], af[mt], bh[nt]);
        }
        __syncthreads();
    }

#pragma unroll
    for (int mt = 0; mt < 2; mt++) {
        size_t r = m0 + wm * 32 + mt * 16 + grp;
#pragma unroll
        for (int nt = 0; nt < 8; nt++) {
            size_t cb = n0 + wn * 64 + nt * 8 + 2 * q;
            float b0v = bias[cb], b1v = bias[cb + 1];
            *(float2*)&C[r * N + cb]       = make_float2(acc[mt][nt][0] + b0v, acc[mt][nt][1] + b1v);
            *(float2*)&C[(r + 8) * N + cb] = make_float2(acc[mt][nt][2] + b0v, acc[mt][nt][3] + b1v);
        }
    }
}

// ---------------- prep recurrent weights (split for profiling slots) ----------------
__global__ void prep_t(const float* __restrict__ Wt)
{
    int i = blockIdx.x * 256 + threadIdx.x;   // 0..65535
    if (i < 512 * 128) {
        int n = i / 128, k = i % 128;
        int j = (n < 256) ? n : (n - 256);
        int s = (n < 256) ? 0 : 1;
        g_WP[((k >> 1) * 256 + j) * 4 + (k & 1) * 2 + s] = Wt[i];
    }
}

__global__ void prep_av(const float* __restrict__ Wa, const float* __restrict__ Wv)
{
    int i = blockIdx.x * 256 + threadIdx.x;
    if (i < 256 * 64) {
        int n = i / 64, k = i % 64;
        g_WTa[k * 256 + n] = Wa[i];
        g_WTv[k * 256 + n] = Wv[i];
    }
}

// ---------------- LSTM text: 128 CTAs, 2 batch rows each ----------------
// Whh: KCS panels in smem as PAIRED ulonglong2 (one LDS.128 = two panels'
// (col j, col j+256) packs); remaining 64 panels in registers.
#define KCS 64
#define TEXT_SMEM ((KCS * 512 + 512 + 512) * 4)

__global__ __launch_bounds__(256, 1)
void lstm_text_kernel()
{
    extern __shared__ float sm[];
    ulonglong2* Wc2  = (ulonglong2*)sm;                  // (KCS/2)*256 entries
    ulonglong2* hdup = (ulonglong2*)(sm + KCS * 512);    // 128: ((h0,h0),(h1,h1))
    float*      exf0 = sm + KCS * 512 + 512;
    float*      exf1 = exf0 + 128;
    float*      exo0 = exf1 + 128;
    float*      exo1 = exo0 + 128;

    const int bx = blockIdx.x, j = threadIdx.x;
    const int b0 = bx * 2, b1 = b0 + 1;
    const ulonglong2* WP2 = (const ulonglong2*)g_WP;
    const ull*        WP1 = (const ull*)g_WP;

    for (int i = j; i < (KCS / 2) * 256; i += 256) Wc2[i] = WP2[i];
    ull wreg[128 - KCS];
#pragma unroll
    for (int kk = 0; kk < 128 - KCS; kk++) {
        int k = KCS + kk;
        wreg[kk] = WP1[((k >> 1) * 256 + j) * 2 + (k & 1)];
    }
    if (j < 128) { hdup[j].x = pack2(0.f, 0.f); hdup[j].y = pack2(0.f, 0.f); }
    __syncthreads();

    float c0 = 0.0f, c1 = 0.0f;

    for (int t = 0; t < TT; t++) {
        const float* Gb0 = g_Gt + ((size_t)(b0 * TT + t)) * 512;
        const float* Gb1 = g_Gt + ((size_t)(b1 * TT + t)) * 512;
        float ga0 = __ldg(&Gb0[j]), ga1 = __ldg(&Gb0[j + 256]);
        float gb0v = __ldg(&Gb1[j]), gb1v = __ldg(&Gb1[j + 256]);

        ull p0 = pack2(0.f, 0.f);
        ull p1 = pack2(0.f, 0.f);

#pragma unroll 4
        for (int p = 0; p < KCS / 2; p++) {
            ulonglong2 w2 = Wc2[p * 256 + j];
            ulonglong2 ha = hdup[2 * p];
            ulonglong2 hb = hdup[2 * p + 1];
            fma2(p0, w2.x, ha.x);
            fma2(p1, w2.x, ha.y);
            fma2(p0, w2.y, hb.x);
            fma2(p1, w2.y, hb.y);
        }
#pragma unroll
        for (int kk = 0; kk < 128 - KCS; kk++) {
            ulonglong2 h = hdup[KCS + kk];
            fma2(p0, wreg[kk], h.x);
            fma2(p1, wreg[kk], h.y);
        }
        float2 A0 = unpack2(p0);
        float2 A1 = unpack2(p1);
        A0.x += ga0;  A0.y += ga1;
        A1.x += gb0v; A1.y += gb1v;

        if (j >= 128) {
            int jj = j - 128;
            exf0[jj] = sigf(A0.x); exf1[jj] = sigf(A1.x);
            exo0[jj] = A0.y;       exo1[jj] = A1.y;
        }
        __syncthreads();
        if (j < 128) {
            c0 = exf0[j] * c0 + sigf(A0.x) * tanhfa(A0.y);
            c1 = exf1[j] * c1 + sigf(A1.x) * tanhfa(A1.y);
            float h0 = sigf(exo0[j]) * tanhfa(c0);
            float h1 = sigf(exo1[j]) * tanhfa(c1);
            hdup[j].x = pack2(h0, h0);
            hdup[j].y = pack2(h1, h1);
            g_z[((size_t)(b0 * TT + t)) * 256 + 128 + j] = h0;
            g_z[((size_t)(b1 * TT + t)) * 256 + 128 + j] = h1;
        }
        __syncthreads();
    }
}

// ---------------- LSTM audio+vision: 128 CTAs, 4 batch rows each ----------------
#define AV_SMEM ((64 * 256 + 256 + 1024) * 4)

__global__ __launch_bounds__(256, 1)
void lstm_av_kernel()
{
    extern __shared__ float sm[];
    float*      Wc   = sm;
    ulonglong2* hb2  = (ulonglong2*)(sm + 16384);
    float*      hbufF = sm + 16384;
    float*      gb   = sm + 16384 + 256;

    const int bx = blockIdx.x, j = threadIdx.x;
    const bool is_audio = (bx < 64);
    const int blk = is_audio ? bx : (bx - 64);
    const float* Gsrc = is_audio ? g_Ga : g_Gv;
    const float* WTs  = is_audio ? g_WTa : g_WTv;
    const int zoff = is_audio ? 0 : 64;
    const int b0 = blk * 4;

    for (int i = j; i < 64 * 256; i += 256) Wc[i] = WTs[i];
    if (j < 64) { hb2[j].x = pack2(0.f, 0.f); hb2[j].y = pack2(0.f, 0.f); }
    __syncthreads();

    const int row = j >> 6, hj = j & 63;
    float c = 0.0f;

    for (int t = 0; t < TT; t++) {
        float a0 = __ldg(&Gsrc[((size_t)((b0 + 0) * TT + t)) * 256 + j]);
        float a1 = __ldg(&Gsrc[((size_t)((b0 + 1) * TT + t)) * 256 + j]);
        float a2 = __ldg(&Gsrc[((size_t)((b0 + 2) * TT + t)) * 256 + j]);
        float a3 = __ldg(&Gsrc[((size_t)((b0 + 3) * TT + t)) * 256 + j]);

        ull q0 = pack2(0.f, 0.f);
        ull q1 = pack2(0.f, 0.f);

#pragma unroll 8
        for (int k = 0; k < 64; k++) {
            float w = Wc[k * 256 + j];
            ull ww = pack2(w, w);
            ulonglong2 h = hb2[k];
            fma2(q0, ww, h.x);
            fma2(q1, ww, h.y);
        }
        float2 Q0 = unpack2(q0), Q1 = unpack2(q1);
        gb[0 * 256 + j] = Q0.x + a0; gb[1 * 256 + j] = Q0.y + a1;
        gb[2 * 256 + j] = Q1.x + a2; gb[3 * 256 + j] = Q1.y + a3;
        __syncthreads();

        const float* g = gb + row * 256;
        float gi = sigf(g[hj]),         gf = sigf(g[64 + hj]);
        float gg = tanhfa(g[128 + hj]), go = sigf(g[192 + hj]);
        c = gf * c + gi * gg;
        float h = go * tanhfa(c);
        hbufF[hj * 4 + row] = h;
        g_z[((size_t)((b0 + row) * TT + t)) * 256 + zoff + hj] = h;
        __syncthreads();
    }
}

// ---------------- fusion ----------------
#define FUSION_SMEM ((6144 + 12312 + 24 + 24 + 192 + 8) * 4)

__global__ __launch_bounds__(256, 1)
void fusion_kernel(const float* __restrict__ W1, const float* __restrict__ b1,
                   const float* __restrict__ W2, const float* __restrict__ b2)
{
    extern __shared__ float sm[];
    float* W1s   = sm;
    float* W2s   = sm + 6144;
    float* b1s   = W2s + 12312;
    float* bcs   = b1s + 24;
    float* Sred  = bcs + 24;
    float* ssred = Sred + 192;

    const int tid = threadIdx.x;
    const int b   = blockIdx.x;

    for (int i = tid; i < 6144;  i += 256) W1s[i] = W1[i];
    for (int i = tid; i < 12312; i += 256) W2s[i] = W2[i];
    if (tid < 24) b1s[tid] = b1[tid];
    __syncthreads();
    if (tid < 24) bcs[tid] = b2[tid] + W2s[tid * 513];
    __syncthreads();

    const int w = tid >> 5, l = tid & 31;
    float S[RANK];
#pragma unroll
    for (int r = 0; r < RANK; r++) S[r] = 0.0f;
    float ss = 0.0f;

    const float* zb = g_z + (size_t)b * TT * 256;

    for (int t0 = w * 32; t0 < w * 32 + 32; t0 += 2) {
        const int t1 = t0 + 1;
        const int t2 = (t0 + 2) & 255;
        float zc0[8], zc1[8], zc2[8];
#pragma unroll
        for (int q = 0; q < 8; q++) {
            zc0[q] = zb[t0 * 256 + l + 32 * q];
            zc1[q] = zb[t1 * 256 + l + 32 * q];
            zc2[q] = zb[t2 * 256 + l + 32 * q];
            ss += zc0[q] * zc0[q] + zc1[q] * zc1[q];
        }
#pragma unroll
        for (int r = 0; r < RANK; r++) {
            float a0 = 0.0f, bb0 = 0.0f, a1 = 0.0f, bb1 = 0.0f;
#pragma unroll
            for (int q = 0; q < 8; q++) {
                float w1v = W1s[r * 256 + l + 32 * q];
                float w2a = W2s[r * 513 + 1   + l + 32 * q];
                float w2b = W2s[r * 513 + 257 + l + 32 * q];
                a0  += w1v * zc0[q];
                bb0 += w2a * zc0[q] + w2b * zc1[q];
                a1  += w1v * zc1[q];
                bb1 += w2a * zc1[q] + w2b * zc2[q];
            }
#pragma unroll
            for (int o = 16; o; o >>= 1) {
                a0  += __shfl_xor_sync(0xffffffffu, a0,  o);
                bb0 += __shfl_xor_sync(0xffffffffu, bb0, o);
                a1  += __shfl_xor_sync(0xffffffffu, a1,  o);
                bb1 += __shfl_xor_sync(0xffffffffu, bb1, o);
            }
            S[r] += (a0 + b1s[r]) * (bb0 + bcs[r])
                  + (a1 + b1s[r]) * (bb1 + bcs[r]);
        }
    }

#pragma unroll
    for (int o = 16; o; o >>= 1) ss += __shfl_xor_sync(0xffffffffu, ss, o);
    if (l == 0) {
#pragma unroll
        for (int r = 0; r < RANK; r++) Sred[w * RANK + r] = S[r];
        ssred[w] = ss;
    }
    __syncthreads();
    if (tid < RANK) {
        float tot = 0.0f;
        for (int ww = 0; ww < 8; ww++) tot += Sred[ww * RANK + tid];
        g_S[b * RANK + tid] = tot;
    }
    if (tid == 32) {
        float tot = 0.0f;
        for (int ww = 0; ww < 8; ww++) tot += ssred[ww];
        g_ss[b] = tot;
    }
}

// ---------------- final ----------------
__global__ void final_kernel(const float* __restrict__ fw, float* __restrict__ out)
{
    const int tid = threadIdx.x;
    float s = 0.0f;
#pragma unroll
    for (int r = 0; r < RANK; r++) s += fw[r] * g_S[tid * RANK + r];
    out[tid] = s * (1.0f / (float)TT);

    __shared__ float red[256];
    red[tid] = sqrtf(g_ss[tid]);
    __syncthreads();
    for (int o = 128; o; o >>= 1) {
        if (tid < o) red[tid] += red[tid + o];
        __syncthreads();
    }
    if (tid == 0) out[256] = red[0] / (float)BB;
}

// ---------------- launch ----------------
extern "C" void kernel_launch(void* const* d_in, const int* in_sizes, int n_in,
                              void* d_out, int out_size)
{
    const float* text  = (const float*)d_in[0];
    const float* audio = (const float*)d_in[1];
    const float* vision= (const float*)d_in[2];
    const float* Wih_t = (const float*)d_in[3];
    const float* Whh_t = (const float*)d_in[4];
    const float* b_t   = (const float*)d_in[5];
    const float* Wih_a = (const float*)d_in[6];
    const float* Whh_a = (const float*)d_in[7];
    const float* b_a   = (const float*)d_in[8];
    const float* Wih_v = (const float*)d_in[9];
    const float* Whh_v = (const float*)d_in[10];
    const float* b_v   = (const float*)d_in[11];
    const float* W1    = (const float*)d_in[12];
    const float* b1    = (const float*)d_in[13];
    const float* W2    = (const float*)d_in[14];
    const float* b2    = (const float*)d_in[15];
    const float* fw    = (const float*)d_in[16];

    float *Gt, *Ga, *Gv;
    cudaGetSymbolAddress((void**)&Gt, g_Gt);
    cudaGetSymbolAddress((void**)&Ga, g_Ga);
    cudaGetSymbolAddress((void**)&Gv, g_Gv);
    __nv_bfloat16 *Athi, *Atlo, *Aahi, *Aalo, *Avhi, *Avlo;
    __nv_bfloat16 *Wthi, *Wtlo, *Wahi, *Walo, *Wvhi, *Wvlo;
    cudaGetSymbolAddress((void**)&Athi, g_Athi);
    cudaGetSymbolAddress((void**)&Atlo, g_Atlo);
    cudaGetSymbolAddress((void**)&Aahi, g_Aahi);
    cudaGetSymbolAddress((void**)&Aalo, g_Aalo);
    cudaGetSymbolAddress((void**)&Avhi, g_Avhi);
    cudaGetSymbolAddress((void**)&Avlo, g_Avlo);
    cudaGetSymbolAddress((void**)&Wthi, g_Wthi);
    cudaGetSymbolAddress((void**)&Wtlo, g_Wtlo);
    cudaGetSymbolAddress((void**)&Wahi, g_Wahi);
    cudaGetSymbolAddress((void**)&Walo, g_Walo);
    cudaGetSymbolAddress((void**)&Wvhi, g_Wvhi);
    cudaGetSymbolAddress((void**)&Wvlo, g_Wvlo);

    cudaFuncSetAttribute(gemm_bf16s,      cudaFuncAttributeMaxDynamicSharedMemorySize, 2 * GSTG);
    cudaFuncSetAttribute(lstm_text_kernel,cudaFuncAttributeMaxDynamicSharedMemorySize, TEXT_SMEM);
    cudaFuncSetAttribute(lstm_av_kernel,  cudaFuncAttributeMaxDynamicSharedMemorySize, AV_SMEM);
    cudaFuncSetAttribute(fusion_kernel,   cudaFuncAttributeMaxDynamicSharedMemorySize, FUSION_SMEM);

    // 1: all conversions fused
    conv_all<<<8192, 256>>>(text, Wih_t, audio, Wih_a, vision, Wih_v);

    // 2-3: recurrent weight prep (split so gemm_text is launch #4)
    prep_t<<<256, 256>>>(Whh_t);
    prep_av<<<64, 256>>>(Whh_a, Whh_v);

    // 4: text GEMM  <-- profiled slot (launch #4)
    gemm_bf16s<<<dim3(4, MM / 128), 256, 2 * GSTG>>>(Athi, Atlo, Wthi, Wtlo, b_t, Gt, 512, KP_T);

    // 5: text recurrence
    lstm_text_kernel<<<128, 256, TEXT_SMEM>>>();

    // 6-7: audio/vision GEMMs
    gemm_bf16s<<<dim3(2, MM / 128), 256, 2 * GSTG>>>(Aahi, Aalo, Wahi, Walo, b_a, Ga, 256, KP_A);
    gemm_bf16s<<<dim3(2, MM / 128), 256, 2 * GSTG>>>(Avhi, Avlo, Wvhi, Wvlo, b_v, Gv, 256, KP_V);

    // 8: audio/vision recurrences
    lstm_av_kernel<<<128, 256, AV_SMEM>>>();

    // 9-10: fusion + final
    fusion_kernel<<<BB, 256, FUSION_SMEM>>>(W1, b1, W2, b2);
    final_kernel<<<1, 256>>>(fw, (float*)d_out);
}

// round 17
// speedup vs baseline: 1.9904x; 1.0109x over previous
#include <cuda_runtime.h>
#include <cuda_bf16.h>
#include <math.h>
#include <stdint.h>

#define BB   256
#define TT   256
#define RANK 24
#define MM   (BB * TT)

#define KP_T 768
#define KP_A 96
#define KP_V 64

typedef unsigned long long ull;

// ---------------- scratch globals ----------------
__device__ float g_Gt[(size_t)MM * 512];
__device__ float g_Ga[(size_t)MM * 256];
__device__ float g_Gv[(size_t)MM * 256];
__device__ float g_z [(size_t)MM * 256];

__device__ __nv_bfloat16 g_Athi[(size_t)MM * KP_T];
__device__ __nv_bfloat16 g_Atlo[(size_t)MM * KP_T];
__device__ __nv_bfloat16 g_Aahi[(size_t)MM * KP_A];
__device__ __nv_bfloat16 g_Aalo[(size_t)MM * KP_A];
__device__ __nv_bfloat16 g_Avhi[(size_t)MM * KP_V];
__device__ __nv_bfloat16 g_Avlo[(size_t)MM * KP_V];
__device__ __nv_bfloat16 g_Wthi[512 * KP_T];
__device__ __nv_bfloat16 g_Wtlo[512 * KP_T];
__device__ __nv_bfloat16 g_Wahi[256 * KP_A];
__device__ __nv_bfloat16 g_Walo[256 * KP_A];
__device__ __nv_bfloat16 g_Wvhi[256 * KP_V];
__device__ __nv_bfloat16 g_Wvlo[256 * KP_V];

// text Whh paired layout: float index ((k>>1)*256 + j)*4 + (k&1)*2 + s
__device__ float g_WP [128 * 512];
__device__ float g_WTa[64 * 256];
__device__ float g_WTv[64 * 256];
__device__ float g_S [BB * RANK];
__device__ float g_ss[BB];

__device__ __forceinline__ float sigf(float x)  { return 1.0f / (1.0f + __expf(-x)); }
__device__ __forceinline__ float tanhfa(float x){ return 1.0f - 2.0f / (__expf(2.0f * x) + 1.0f); }

__device__ __forceinline__ void fma2(ull& d, ull a, ull b) {
    asm("fma.rn.f32x2 %0, %1, %2, %0;" : "+l"(d) : "l"(a), "l"(b));
}
__device__ __forceinline__ ull pack2(float x, float y) {
    ull r; asm("mov.b64 %0, {%1,%2};" : "=l"(r) : "f"(x), "f"(y)); return r;
}
__device__ __forceinline__ float2 unpack2(ull v) {
    float2 r; asm("mov.b64 {%0,%1}, %2;" : "=f"(r.x), "=f"(r.y) : "l"(v)); return r;
}

// ---------------- fused conversion kernel ----------------
__device__ __forceinline__ void split4(const float4* __restrict__ src,
                                       __nv_bfloat162* __restrict__ hi,
                                       __nv_bfloat162* __restrict__ lo, long i)
{
    float4 v = src[i];
    __nv_bfloat16 h0 = __float2bfloat16(v.x), h1 = __float2bfloat16(v.y);
    __nv_bfloat16 h2 = __float2bfloat16(v.z), h3 = __float2bfloat16(v.w);
    hi[2*i]   = __halves2bfloat162(h0, h1);
    hi[2*i+1] = __halves2bfloat162(h2, h3);
    lo[2*i]   = __halves2bfloat162(__float2bfloat16(v.x - __bfloat162float(h0)),
                                   __float2bfloat16(v.y - __bfloat162float(h1)));
    lo[2*i+1] = __halves2bfloat162(__float2bfloat16(v.z - __bfloat162float(h2)),
                                   __float2bfloat16(v.w - __bfloat162float(h3)));
}

__device__ __forceinline__ void conv_one(const float* __restrict__ src,
                                         __nv_bfloat16* __restrict__ hi,
                                         __nv_bfloat16* __restrict__ lo,
                                         long i, int K, int Kp)
{
    int m = (int)(i / Kp), k = (int)(i % Kp);
    float v = (k < K) ? src[(size_t)m * K + k] : 0.0f;
    __nv_bfloat16 h = __float2bfloat16(v);
    hi[i] = h;
    lo[i] = __float2bfloat16(v - __bfloat162float(h));
}

#define CT0 ((long)MM * KP_T / 4)
#define CT1 ((long)512 * KP_T / 4)
#define CR0 ((long)MM * KP_A)
#define CR1 ((long)256 * KP_A)
#define CR2 ((long)MM * KP_V)
#define CR3 ((long)256 * KP_V)

__global__ void conv_all(const float* __restrict__ text, const float* __restrict__ Wt,
                         const float* __restrict__ audio, const float* __restrict__ Wa,
                         const float* __restrict__ vision, const float* __restrict__ Wv)
{
    const long total = CT0 + CT1 + CR0 + CR1 + CR2 + CR3;
    for (long i = (long)blockIdx.x * blockDim.x + threadIdx.x; i < total;
         i += (long)gridDim.x * blockDim.x) {
        long x = i;
        if (x < CT0) { split4((const float4*)text, (__nv_bfloat162*)g_Athi, (__nv_bfloat162*)g_Atlo, x); continue; }
        x -= CT0;
        if (x < CT1) { split4((const float4*)Wt, (__nv_bfloat162*)g_Wthi, (__nv_bfloat162*)g_Wtlo, x); continue; }
        x -= CT1;
        if (x < CR0) { conv_one(audio,  g_Aahi, g_Aalo, x, 74, KP_A); continue; }
        x -= CR0;
        if (x < CR1) { conv_one(Wa,     g_Wahi, g_Walo, x, 74, KP_A); continue; }
        x -= CR1;
        if (x < CR2) { conv_one(vision, g_Avhi, g_Avlo, x, 35, KP_V); continue; }
        x -= CR2;
        conv_one(Wv, g_Wvhi, g_Wvlo, x, 35, KP_V);
    }
}

// ---------------- tensor-core GEMM (mma.sync + ldmatrix): C = A * W^T + bias ----------------
#define GARR 10240
#define GSTG 40960

__device__ __forceinline__ void cp16(unsigned dst, const void* src) {
    asm volatile("cp.async.cg.shared.global [%0], [%1], 16;\n" :: "r"(dst), "l"(src));
}
__device__ __forceinline__ void ldsm4(unsigned& d0, unsigned& d1, unsigned& d2, unsigned& d3,
                                      unsigned addr) {
    asm volatile("ldmatrix.sync.aligned.m8n8.x4.shared.b16 {%0,%1,%2,%3}, [%4];"
                 : "=r"(d0), "=r"(d1), "=r"(d2), "=r"(d3) : "r"(addr));
}
__device__ __forceinline__ void mma16816(float* d, const unsigned* a, const unsigned* b) {
    asm volatile(
        "mma.sync.aligned.m16n8k16.row.col.f32.bf16.bf16.f32 "
        "{%0,%1,%2,%3}, {%4,%5,%6,%7}, {%8,%9}, {%0,%1,%2,%3};"
        : "+f"(d[0]), "+f"(d[1]), "+f"(d[2]), "+f"(d[3])
        : "r"(a[0]), "r"(a[1]), "r"(a[2]), "r"(a[3]), "r"(b[0]), "r"(b[1]));
}

__global__ __launch_bounds__(256, 2)
void gemm_bf16s(const __nv_bfloat16* __restrict__ Ahi, const __nv_bfloat16* __restrict__ Alo,
                const __nv_bfloat16* __restrict__ Bhi, const __nv_bfloat16* __restrict__ Blo,
                const float* __restrict__ bias, float* __restrict__ C, int N, int Kp)
{
    extern __shared__ char gsm[];
    const int tid = threadIdx.x;
    const size_t n0 = (size_t)blockIdx.x * 128;   // n fastest -> A shared in L2
    const size_t m0 = (size_t)blockIdx.y * 128;
    const unsigned us = (unsigned)__cvta_generic_to_shared(gsm);
    const int NK = Kp >> 5;

    const __nv_bfloat16* gsrc[4] = {Ahi + m0 * Kp, Alo + m0 * Kp,
                                    Bhi + n0 * Kp, Blo + n0 * Kp};

    auto load_chunk = [&](int kc, int stg) {
        unsigned base = us + stg * GSTG;
#pragma unroll
        for (int arr = 0; arr < 4; arr++) {
#pragma unroll
            for (int i = 0; i < 2; i++) {
                int u = tid + 256 * i;
                int row = u >> 2, seg = u & 3;
                unsigned dst = base + arr * GARR + row * 80 + seg * 16;
                cp16(dst, gsrc[arr] + (size_t)row * Kp + kc * 32 + seg * 8);
            }
        }
        asm volatile("cp.async.commit_group;" ::: "memory");
    };

    const int warp = tid >> 5, wm = warp >> 1, wn = warp & 1;
    const int lane = tid & 31, grp = lane >> 2, q = lane & 3;
    const int li = lane & 7, sel = lane >> 3;

    // per-lane ldmatrix byte offsets within one array
    unsigned offA[2], offB[4];
#pragma unroll
    for (int mt = 0; mt < 2; mt++)
        offA[mt] = (unsigned)((wm * 32 + mt * 16 + (sel & 1) * 8 + li) * 80 + (sel >> 1) * 16);
#pragma unroll
    for (int p = 0; p < 4; p++)
        offB[p] = (unsigned)((wn * 64 + (2 * p + (sel >> 1)) * 8 + li) * 80 + (sel & 1) * 16);

    float acc[2][8][4];
#pragma unroll
    for (int mt = 0; mt < 2; mt++)
#pragma unroll
        for (int nt = 0; nt < 8; nt++)
#pragma unroll
            for (int i = 0; i < 4; i++) acc[mt][nt][i] = 0.0f;

    load_chunk(0, 0);

    for (int kc = 0; kc < NK; kc++) {
        if (kc + 1 < NK) load_chunk(kc + 1, (kc + 1) & 1);
        else             asm volatile("cp.async.commit_group;" ::: "memory");
        asm volatile("cp.async.wait_group 1;" ::: "memory");
        __syncthreads();

        const unsigned stb = us + (kc & 1) * GSTG;

#pragma unroll
        for (int kk = 0; kk < 32; kk += 16) {
            const unsigned ko = (unsigned)(kk * 2);
            unsigned bh[8][2], af[2][4], al[2][4];
#pragma unroll
            for (int p = 0; p < 4; p++)
                ldsm4(bh[2*p][0], bh[2*p][1], bh[2*p+1][0], bh[2*p+1][1],
                      stb + 2 * GARR + offB[p] + ko);
#pragma unroll
            for (int mt = 0; mt < 2; mt++)
                ldsm4(af[mt][0], af[mt][1], af[mt][2], af[mt][3],
                      stb + offA[mt] + ko);
#pragma unroll
            for (int mt = 0; mt < 2; mt++)
                ldsm4(al[mt][0], al[mt][1], al[mt][2], al[mt][3],
                      stb + GARR + offA[mt] + ko);
#pragma unroll
            for (int mt = 0; mt < 2; mt++)
#pragma unroll
                for (int nt = 0; nt < 8; nt++) {
                    mma16816(acc[mt][nt], af[mt], bh[nt]);
                    mma16816(acc[mt][nt], al[mt], bh[nt]);
                }
#pragma unroll
            for (int p = 0; p < 4; p++)
                ldsm4(bh[2*p][0], bh[2*p][1], bh[2*p+1][0], bh[2*p+1][1],
                      stb + 3 * GARR + offB[p] + ko);
#pragma unroll
            for (int mt = 0; mt < 2; mt++)
#pragma unroll
                for (int nt = 0; nt < 8; nt++)
                    mma16816(acc[mt][nt], af[mt], bh[nt]);
        }
        __syncthreads();
    }

#pragma unroll
    for (int mt = 0; mt < 2; mt++) {
        size_t r = m0 + wm * 32 + mt * 16 + grp;
#pragma unroll
        for (int nt = 0; nt < 8; nt++) {
            size_t cb = n0 + wn * 64 + nt * 8 + 2 * q;
            float b0v = bias[cb], b1v = bias[cb + 1];
            *(float2*)&C[r * N + cb]       = make_float2(acc[mt][nt][0] + b0v, acc[mt][nt][1] + b1v);
            *(float2*)&C[(r + 8) * N + cb] = make_float2(acc[mt][nt][2] + b0v, acc[mt][nt][3] + b1v);
        }
    }
}

// ---------------- prep recurrent weights ----------------
__global__ void prep_t(const float* __restrict__ Wt)
{
    int i = blockIdx.x * 256 + threadIdx.x;
    if (i < 512 * 128) {
        int n = i / 128, k = i % 128;
        int j = (n < 256) ? n : (n - 256);
        int s = (n < 256) ? 0 : 1;
        g_WP[((k >> 1) * 256 + j) * 4 + (k & 1) * 2 + s] = Wt[i];
    }
}

__global__ void prep_av(const float* __restrict__ Wa, const float* __restrict__ Wv)
{
    int i = blockIdx.x * 256 + threadIdx.x;
    if (i < 256 * 64) {
        int n = i / 64, k = i % 64;
        g_WTa[k * 256 + n] = Wa[i];
        g_WTv[k * 256 + n] = Wv[i];
    }
}

// ---------------- LSTM text: 128 CTAs, 2 batch rows each ----------------
// 4 independent fma2 accumulation chains to halve RAW-chain latency.
#define KCS 64
#define TEXT_SMEM ((KCS * 512 + 512 + 512) * 4)

__global__ __launch_bounds__(256, 1)
void lstm_text_kernel()
{
    extern __shared__ float sm[];
    ulonglong2* Wc2  = (ulonglong2*)sm;                  // (KCS/2)*256
    ulonglong2* hdup = (ulonglong2*)(sm + KCS * 512);    // 128
    float*      exf0 = sm + KCS * 512 + 512;
    float*      exf1 = exf0 + 128;
    float*      exo0 = exf1 + 128;
    float*      exo1 = exo0 + 128;

    const int bx = blockIdx.x, j = threadIdx.x;
    const int b0 = bx * 2, b1 = b0 + 1;
    const ulonglong2* WP2 = (const ulonglong2*)g_WP;
    const ull*        WP1 = (const ull*)g_WP;

    for (int i = j; i < (KCS / 2) * 256; i += 256) Wc2[i] = WP2[i];
    ull wreg[128 - KCS];
#pragma unroll
    for (int kk = 0; kk < 128 - KCS; kk++) {
        int k = KCS + kk;
        wreg[kk] = WP1[((k >> 1) * 256 + j) * 2 + (k & 1)];
    }
    if (j < 128) { hdup[j].x = pack2(0.f, 0.f); hdup[j].y = pack2(0.f, 0.f); }
    __syncthreads();

    float c0 = 0.0f, c1 = 0.0f;

    for (int t = 0; t < TT; t++) {
        const float* Gb0 = g_Gt + ((size_t)(b0 * TT + t)) * 512;
        const float* Gb1 = g_Gt + ((size_t)(b1 * TT + t)) * 512;
        float ga0 = __ldg(&Gb0[j]), ga1 = __ldg(&Gb0[j + 256]);
        float gb0v = __ldg(&Gb1[j]), gb1v = __ldg(&Gb1[j + 256]);

        ull p0a = pack2(0.f, 0.f), p0b = pack2(0.f, 0.f);
        ull p1a = pack2(0.f, 0.f), p1b = pack2(0.f, 0.f);

#pragma unroll 4
        for (int p = 0; p < KCS / 2; p++) {
            ulonglong2 w2 = Wc2[p * 256 + j];
            ulonglong2 ha = hdup[2 * p];
            ulonglong2 hb = hdup[2 * p + 1];
            fma2(p0a, w2.x, ha.x);
            fma2(p1a, w2.x, ha.y);
            fma2(p0b, w2.y, hb.x);
            fma2(p1b, w2.y, hb.y);
        }
#pragma unroll
        for (int kk = 0; kk < 128 - KCS; kk += 2) {
            ulonglong2 h0 = hdup[KCS + kk];
            ulonglong2 h1 = hdup[KCS + kk + 1];
            fma2(p0a, wreg[kk],     h0.x);
            fma2(p1a, wreg[kk],     h0.y);
            fma2(p0b, wreg[kk + 1], h1.x);
            fma2(p1b, wreg[kk + 1], h1.y);
        }
        float2 A0a = unpack2(p0a), A0b = unpack2(p0b);
        float2 A1a = unpack2(p1a), A1b = unpack2(p1b);
        float2 A0 = make_float2(A0a.x + A0b.x + ga0,  A0a.y + A0b.y + ga1);
        float2 A1 = make_float2(A1a.x + A1b.x + gb0v, A1a.y + A1b.y + gb1v);

        if (j >= 128) {
            int jj = j - 128;
            exf0[jj] = sigf(A0.x); exf1[jj] = sigf(A1.x);
            exo0[jj] = A0.y;       exo1[jj] = A1.y;
        }
        __syncthreads();
        if (j < 128) {
            c0 = exf0[j] * c0 + sigf(A0.x) * tanhfa(A0.y);
            c1 = exf1[j] * c1 + sigf(A1.x) * tanhfa(A1.y);
            float h0 = sigf(exo0[j]) * tanhfa(c0);
            float h1 = sigf(exo1[j]) * tanhfa(c1);
            hdup[j].x = pack2(h0, h0);
            hdup[j].y = pack2(h1, h1);
            g_z[((size_t)(b0 * TT + t)) * 256 + 128 + j] = h0;
            g_z[((size_t)(b1 * TT + t)) * 256 + 128 + j] = h1;
        }
        __syncthreads();
    }
}

// ---------------- LSTM audio+vision: 128 CTAs, 4 batch rows each ----------------
#define AV_SMEM ((64 * 256 + 256 + 1024) * 4)

__global__ __launch_bounds__(256, 1)
void lstm_av_kernel()
{
    extern __shared__ float sm[];
    float*      Wc   = sm;
    ulonglong2* hb2  = (ulonglong2*)(sm + 16384);
    float*      hbufF = sm + 16384;
    float*      gb   = sm + 16384 + 256;

    const int bx = blockIdx.x, j = threadIdx.x;
    const bool is_audio = (bx < 64);
    const int blk = is_audio ? bx : (bx - 64);
    const float* Gsrc = is_audio ? g_Ga : g_Gv;
    const float* WTs  = is_audio ? g_WTa : g_WTv;
    const int zoff = is_audio ? 0 : 64;
    const int b0 = blk * 4;

    for (int i = j; i < 64 * 256; i += 256) Wc[i] = WTs[i];
    if (j < 64) { hb2[j].x = pack2(0.f, 0.f); hb2[j].y = pack2(0.f, 0.f); }
    __syncthreads();

    const int row = j >> 6, hj = j & 63;
    float c = 0.0f;

    for (int t = 0; t < TT; t++) {
        float a0 = __ldg(&Gsrc[((size_t)((b0 + 0) * TT + t)) * 256 + j]);
        float a1 = __ldg(&Gsrc[((size_t)((b0 + 1) * TT + t)) * 256 + j]);
        float a2 = __ldg(&Gsrc[((size_t)((b0 + 2) * TT + t)) * 256 + j]);
        float a3 = __ldg(&Gsrc[((size_t)((b0 + 3) * TT + t)) * 256 + j]);

        ull q0 = pack2(0.f, 0.f);
        ull q1 = pack2(0.f, 0.f);

#pragma unroll 8
        for (int k = 0; k < 64; k++) {
            float w = Wc[k * 256 + j];
            ull ww = pack2(w, w);
            ulonglong2 h = hb2[k];
            fma2(q0, ww, h.x);
            fma2(q1, ww, h.y);
        }
        float2 Q0 = unpack2(q0), Q1 = unpack2(q1);
        gb[0 * 256 + j] = Q0.x + a0; gb[1 * 256 + j] = Q0.y + a1;
        gb[2 * 256 + j] = Q1.x + a2; gb[3 * 256 + j] = Q1.y + a3;
        __syncthreads();

        const float* g = gb + row * 256;
        float gi = sigf(g[hj]),         gf = sigf(g[64 + hj]);
        float gg = tanhfa(g[128 + hj]), go = sigf(g[192 + hj]);
        c = gf * c + gi * gg;
        float h = go * tanhfa(c);
        hbufF[hj * 4 + row] = h;
        g_z[((size_t)((b0 + row) * TT + t)) * 256 + zoff + hj] = h;
        __syncthreads();
    }
}

// ---------------- fusion ----------------
#define FUSION_SMEM ((6144 + 12312 + 24 + 24 + 192 + 8) * 4)

__global__ __launch_bounds__(256, 1)
void fusion_kernel(const float* __restrict__ W1, const float* __restrict__ b1,
                   const float* __restrict__ W2, const float* __restrict__ b2)
{
    extern __shared__ float sm[];
    float* W1s   = sm;
    float* W2s   = sm + 6144;
    float* b1s   = W2s + 12312;
    float* bcs   = b1s + 24;
    float* Sred  = bcs + 24;
    float* ssred = Sred + 192;

    const int tid = threadIdx.x;
    const int b   = blockIdx.x;

    for (int i = tid; i < 6144;  i += 256) W1s[i] = W1[i];
    for (int i = tid; i < 12312; i += 256) W2s[i] = W2[i];
    if (tid < 24) b1s[tid] = b1[tid];
    __syncthreads();
    if (tid < 24) bcs[tid] = b2[tid] + W2s[tid * 513];
    __syncthreads();

    const int w = tid >> 5, l = tid & 31;
    float S[RANK];
#pragma unroll
    for (int r = 0; r < RANK; r++) S[r] = 0.0f;
    float ss = 0.0f;

    const float* zb = g_z + (size_t)b * TT * 256;

    for (int t0 = w * 32; t0 < w * 32 + 32; t0 += 2) {
        const int t1 = t0 + 1;
        const int t2 = (t0 + 2) & 255;
        float zc0[8], zc1[8], zc2[8];
#pragma unroll
        for (int q = 0; q < 8; q++) {
            zc0[q] = zb[t0 * 256 + l + 32 * q];
            zc1[q] = zb[t1 * 256 + l + 32 * q];
            zc2[q] = zb[t2 * 256 + l + 32 * q];
            ss += zc0[q] * zc0[q] + zc1[q] * zc1[q];
        }
#pragma unroll
        for (int r = 0; r < RANK; r++) {
            float a0 = 0.0f, bb0 = 0.0f, a1 = 0.0f, bb1 = 0.0f;
#pragma unroll
            for (int q = 0; q < 8; q++) {
                float w1v = W1s[r * 256 + l + 32 * q];
                float w2a = W2s[r * 513 + 1   + l + 32 * q];
                float w2b = W2s[r * 513 + 257 + l + 32 * q];
                a0  += w1v * zc0[q];
                bb0 += w2a * zc0[q] + w2b * zc1[q];
                a1  += w1v * zc1[q];
                bb1 += w2a * zc1[q] + w2b * zc2[q];
            }
#pragma unroll
            for (int o = 16; o; o >>= 1) {
                a0  += __shfl_xor_sync(0xffffffffu, a0,  o);
                bb0 += __shfl_xor_sync(0xffffffffu, bb0, o);
                a1  += __shfl_xor_sync(0xffffffffu, a1,  o);
                bb1 += __shfl_xor_sync(0xffffffffu, bb1, o);
            }
            S[r] += (a0 + b1s[r]) * (bb0 + bcs[r])
                  + (a1 + b1s[r]) * (bb1 + bcs[r]);
        }
    }

#pragma unroll
    for (int o = 16; o; o >>= 1) ss += __shfl_xor_sync(0xffffffffu, ss, o);
    if (l == 0) {
#pragma unroll
        for (int r = 0; r < RANK; r++) Sred[w * RANK + r] = S[r];
        ssred[w] = ss;
    }
    __syncthreads();
    if (tid < RANK) {
        float tot = 0.0f;
        for (int ww = 0; ww < 8; ww++) tot += Sred[ww * RANK + tid];
        g_S[b * RANK + tid] = tot;
    }
    if (tid == 32) {
        float tot = 0.0f;
        for (int ww = 0; ww < 8; ww++) tot += ssred[ww];
        g_ss[b] = tot;
    }
}

// ---------------- final ----------------
__global__ void final_kernel(const float* __restrict__ fw, float* __restrict__ out)
{
    const int tid = threadIdx.x;
    float s = 0.0f;
#pragma unroll
    for (int r = 0; r < RANK; r++) s += fw[r] * g_S[tid * RANK + r];
    out[tid] = s * (1.0f / (float)TT);

    __shared__ float red[256];
    red[tid] = sqrtf(g_ss[tid]);
    __syncthreads();
    for (int o = 128; o; o >>= 1) {
        if (tid < o) red[tid] += red[tid + o];
        __syncthreads();
    }
    if (tid == 0) out[256] = red[0] / (float)BB;
}

// ---------------- launch ----------------
extern "C" void kernel_launch(void* const* d_in, const int* in_sizes, int n_in,
                              void* d_out, int out_size)
{
    const float* text  = (const float*)d_in[0];
    const float* audio = (const float*)d_in[1];
    const float* vision= (const float*)d_in[2];
    const float* Wih_t = (const float*)d_in[3];
    const float* Whh_t = (const float*)d_in[4];
    const float* b_t   = (const float*)d_in[5];
    const float* Wih_a = (const float*)d_in[6];
    const float* Whh_a = (const float*)d_in[7];
    const float* b_a   = (const float*)d_in[8];
    const float* Wih_v = (const float*)d_in[9];
    const float* Whh_v = (const float*)d_in[10];
    const float* b_v   = (const float*)d_in[11];
    const float* W1    = (const float*)d_in[12];
    const float* b1    = (const float*)d_in[13];
    const float* W2    = (const float*)d_in[14];
    const float* b2    = (const float*)d_in[15];
    const float* fw    = (const float*)d_in[16];

    float *Gt, *Ga, *Gv;
    cudaGetSymbolAddress((void**)&Gt, g_Gt);
    cudaGetSymbolAddress((void**)&Ga, g_Ga);
    cudaGetSymbolAddress((void**)&Gv, g_Gv);
    __nv_bfloat16 *Athi, *Atlo, *Aahi, *Aalo, *Avhi, *Avlo;
    __nv_bfloat16 *Wthi, *Wtlo, *Wahi, *Walo, *Wvhi, *Wvlo;
    cudaGetSymbolAddress((void**)&Athi, g_Athi);
    cudaGetSymbolAddress((void**)&Atlo, g_Atlo);
    cudaGetSymbolAddress((void**)&Aahi, g_Aahi);
    cudaGetSymbolAddress((void**)&Aalo, g_Aalo);
    cudaGetSymbolAddress((void**)&Avhi, g_Avhi);
    cudaGetSymbolAddress((void**)&Avlo, g_Avlo);
    cudaGetSymbolAddress((void**)&Wthi, g_Wthi);
    cudaGetSymbolAddress((void**)&Wtlo, g_Wtlo);
    cudaGetSymbolAddress((void**)&Wahi, g_Wahi);
    cudaGetSymbolAddress((void**)&Walo, g_Walo);
    cudaGetSymbolAddress((void**)&Wvhi, g_Wvhi);
    cudaGetSymbolAddress((void**)&Wvlo, g_Wvlo);

    cudaFuncSetAttribute(gemm_bf16s,      cudaFuncAttributeMaxDynamicSharedMemorySize, 2 * GSTG);
    cudaFuncSetAttribute(lstm_text_kernel,cudaFuncAttributeMaxDynamicSharedMemorySize, TEXT_SMEM);
    cudaFuncSetAttribute(lstm_av_kernel,  cudaFuncAttributeMaxDynamicSharedMemorySize, AV_SMEM);
    cudaFuncSetAttribute(fusion_kernel,   cudaFuncAttributeMaxDynamicSharedMemorySize, FUSION_SMEM);

    // 1: all conversions fused
    conv_all<<<8192, 256>>>(text, Wih_t, audio, Wih_a, vision, Wih_v);

    // 2-3: recurrent weight prep
    prep_t<<<256, 256>>>(Whh_t);
    prep_av<<<64, 256>>>(Whh_a, Whh_v);

    // 4: text GEMM  <-- profiled slot (launch #4)
    gemm_bf16s<<<dim3(4, MM / 128), 256, 2 * GSTG>>>(Athi, Atlo, Wthi, Wtlo, b_t, Gt, 512, KP_T);

    // 5: text recurrence
    lstm_text_kernel<<<128, 256, TEXT_SMEM>>>();

    // 6-7: audio/vision GEMMs
    gemm_bf16s<<<dim3(2, MM / 128), 256, 2 * GSTG>>>(Aahi, Aalo, Wahi, Walo, b_a, Ga, 256, KP_A);
    gemm_bf16s<<<dim3(2, MM / 128), 256, 2 * GSTG>>>(Avhi, Avlo, Wvhi, Wvlo, b_v, Gv, 256, KP_V);

    // 8: audio/vision recurrences
    lstm_av_kernel<<<128, 256, AV_SMEM>>>();

    // 9-10: fusion + final
    fusion_kernel<<<BB, 256, FUSION_SMEM>>>(W1, b1, W2, b2);
    final_kernel<<<1, 256>>>(fw, (float*)d_out);
}